// round 1
// baseline (speedup 1.0000x reference)
#include <cuda_runtime.h>
#include <math.h>

#define G1 4.0f
#define EPSL 1e-10f

// ---------------- scratch (device globals; no allocations allowed) ----------
__device__ float g_v[40u*2048u*256u];        // [b][r][d]   83.9 MB
__device__ float g_sT[40u*75u*2048u];        // [b][t][r]   24.6 MB
__device__ float g_rowstats[40u*2048u*5u*2u];// [b][r][seg]{max, 1/sumexp}
__device__ float g_cinv_nt[40*75];           // 1/sum_r exp(s_nt)
__device__ float g_sd[40*8*75];              // [b][m][t]
__device__ float g_vtp[4u*40u*75u*256u];     // split-K partials of v_tidal
__device__ float g_vns[40*8*256];            // v_norm_sum
__device__ float g_score1[40*5];
__device__ float g_logit2[40*8*5];
__device__ float g_regval[40];

// ---------------- K0: transpose image [bm][d][p] -> v [b][r=m*256+p][d] -----
__global__ void k_transpose(const float* __restrict__ image) {
    __shared__ float tile[32][33];
    const int bm = blockIdx.z;
    const int p0 = blockIdx.x * 32;
    const int d0 = blockIdx.y * 32;
    const int tx = threadIdx.x, ty = threadIdx.y;
    const float* src = image + (size_t)bm * 256 * 256;
    #pragma unroll
    for (int j = 0; j < 32; j += 8)
        tile[ty + j][tx] = src[(size_t)(d0 + ty + j) * 256 + p0 + tx];
    __syncthreads();
    const int b = bm >> 3, m = bm & 7;
    float* dst = g_v + ((size_t)b * 2048 + m * 256) * 256;
    #pragma unroll
    for (int j = 0; j < 32; j += 8)
        dst[(size_t)(p0 + ty + j) * 256 + d0 + tx] = tile[tx][ty + j];
}

// ---------------- K_vns: v_norm_sum[b][m][d] = sum_hw v/||v_row|| -----------
__global__ void __launch_bounds__(256) k_vns() {
    __shared__ float invn[256];
    const int bm = blockIdx.x;
    const int b = bm >> 3, m = bm & 7;
    const float* vbase = g_v + ((size_t)b * 2048 + m * 256) * 256;
    const int tid = threadIdx.x, lane = tid & 31, w = tid >> 5;
    for (int hw = w; hw < 256; hw += 8) {
        const float* row = vbase + (size_t)hw * 256;
        float ss = 0.f;
        #pragma unroll
        for (int j = 0; j < 8; j++) { float v = row[lane + 32 * j]; ss += v * v; }
        #pragma unroll
        for (int o = 16; o > 0; o >>= 1) ss += __shfl_xor_sync(0xffffffffu, ss, o);
        if (lane == 0) invn[hw] = 1.0f / fmaxf(sqrtf(ss), 1e-12f);
    }
    __syncthreads();
    float acc = 0.f;
    const int d = tid;
    for (int hw = 0; hw < 256; hw++)
        acc = fmaf(vbase[(size_t)hw * 256 + d], invn[hw], acc);
    g_vns[(size_t)bm * 256 + d] = acc;
}

// ---------------- K1: s = v @ e^T ; rowstats ; store s transposed ----------
__global__ void __launch_bounds__(256) k_gemm_s(const float* __restrict__ text) {
    __shared__ float pool[10320];
    float* shA = pool;            // [32 k][132 (128 r pad)]
    float* shB = pool + 32 * 132; // [32 k][84 (80 t pad)]
    const int tid = threadIdx.x;
    const int b = blockIdx.y;
    const int r0 = blockIdx.x * 128;
    const int blk = b / 5;
    const float* ef = text + (size_t)blk * 75 * 256;
    const float* vrow = g_v + (size_t)b * 2048 * 256;
    const int tr = tid & 15, tc = tid >> 4;

    float acc[8][5];
    #pragma unroll
    for (int i = 0; i < 8; i++)
        #pragma unroll
        for (int j = 0; j < 5; j++) acc[i][j] = 0.f;

    for (int kb = 0; kb < 256; kb += 32) {
        #pragma unroll
        for (int it = 0; it < 4; it++) {
            int e = (tid + it * 256) * 4;
            int r = e >> 5, k = e & 31;
            float4 va = *(const float4*)(vrow + (size_t)(r0 + r) * 256 + kb + k);
            shA[(k + 0) * 132 + r] = va.x;
            shA[(k + 1) * 132 + r] = va.y;
            shA[(k + 2) * 132 + r] = va.z;
            shA[(k + 3) * 132 + r] = va.w;
        }
        #pragma unroll
        for (int it = 0; it < 3; it++) {
            int e4 = tid + it * 256;
            if (e4 < 640) {
                int e = e4 * 4;
                int t = e >> 5, k = e & 31;
                float4 vb = make_float4(0.f, 0.f, 0.f, 0.f);
                if (t < 75) vb = *(const float4*)(ef + (size_t)t * 256 + kb + k);
                shB[(k + 0) * 84 + t] = vb.x;
                shB[(k + 1) * 84 + t] = vb.y;
                shB[(k + 2) * 84 + t] = vb.z;
                shB[(k + 3) * 84 + t] = vb.w;
            }
        }
        __syncthreads();
        #pragma unroll
        for (int k = 0; k < 32; k++) {
            float4 a0 = *(const float4*)(shA + k * 132 + tr * 8);
            float4 a1 = *(const float4*)(shA + k * 132 + tr * 8 + 4);
            float av[8] = {a0.x, a0.y, a0.z, a0.w, a1.x, a1.y, a1.z, a1.w};
            float bv[5];
            #pragma unroll
            for (int j = 0; j < 5; j++) bv[j] = shB[k * 84 + tc * 5 + j];
            #pragma unroll
            for (int i = 0; i < 8; i++)
                #pragma unroll
                for (int j = 0; j < 5; j++)
                    acc[i][j] = fmaf(av[i], bv[j], acc[i][j]);
        }
        __syncthreads();
    }
    // stage C into shared as sc[t][r] (stride 129)
    float* sc = pool;
    #pragma unroll
    for (int i = 0; i < 8; i++)
        #pragma unroll
        for (int j = 0; j < 5; j++)
            sc[(tc * 5 + j) * 129 + tr * 8 + i] = acc[i][j];
    __syncthreads();
    // per-row segment softmax stats (max, 1/sumexp) over L=15
    for (int task = tid; task < 640; task += 256) {
        int r = task & 127, seg = task >> 7;
        float mx = -3.4e38f;
        #pragma unroll
        for (int l = 0; l < 15; l++) mx = fmaxf(mx, sc[(seg * 15 + l) * 129 + r]);
        float se = 0.f;
        #pragma unroll
        for (int l = 0; l < 15; l++) se += expf(sc[(seg * 15 + l) * 129 + r] - mx);
        size_t ridx = ((size_t)b * 2048 + r0 + r) * 5 + seg;
        g_rowstats[ridx * 2]     = mx;
        g_rowstats[ridx * 2 + 1] = 1.0f / se;
    }
    // write transposed s: coalesced over r
    for (int i = tid; i < 9600; i += 256) {
        int t = i >> 7, r = i & 127;
        g_sT[((size_t)b * 75 + t) * 2048 + r0 + r] = sc[t * 129 + r];
    }
}

// ---------------- K2: per-(b,t) column stats + sd ---------------------------
__global__ void __launch_bounds__(256) k_colstats() {
    const int t = blockIdx.x, b = blockIdx.y;
    const int tid = threadIdx.x;
    const int seg = t / 15;
    const float* col = g_sT + ((size_t)b * 75 + t) * 2048;
    __shared__ float red[256];
    float vals[8];
    #pragma unroll
    for (int k = 0; k < 8; k++) vals[k] = col[tid + 256 * k];
    float mx = vals[0];
    #pragma unroll
    for (int k = 1; k < 8; k++) mx = fmaxf(mx, vals[k]);
    red[tid] = mx; __syncthreads();
    for (int o = 128; o > 0; o >>= 1) { if (tid < o) red[tid] = fmaxf(red[tid], red[tid + o]); __syncthreads(); }
    const float cmax = red[0];
    __syncthreads();

    float sraw = 0.f, snt = 0.f;
    #pragma unroll
    for (int k = 0; k < 8; k++) {
        int r = tid + 256 * k;
        sraw += expf(vals[k] - cmax);
        float2 rs = *(const float2*)(g_rowstats + (((size_t)b * 2048 + r) * 5 + seg) * 2);
        snt += expf(G1 * expf(vals[k] - rs.x) * rs.y);
    }
    red[tid] = sraw; __syncthreads();
    for (int o = 128; o > 0; o >>= 1) { if (tid < o) red[tid] += red[tid + o]; __syncthreads(); }
    const float cinv = 1.0f / red[0];
    __syncthreads();
    red[tid] = snt; __syncthreads();
    for (int o = 128; o > 0; o >>= 1) { if (tid < o) red[tid] += red[tid + o]; __syncthreads(); }
    if (tid == 0) g_cinv_nt[b * 75 + t] = 1.0f / red[0];
    __syncthreads();

    // sd[b][m][t] = sum_hw exp(softmax_r(s));  r = tid + 256*m  => m fixed per k
    #pragma unroll
    for (int m = 0; m < 8; m++) {
        red[tid] = expf(expf(vals[m] - cmax) * cinv);
        __syncthreads();
        for (int o = 128; o > 0; o >>= 1) { if (tid < o) red[tid] += red[tid + o]; __syncthreads(); }
        if (tid == 0) g_sd[((size_t)b * 8 + m) * 75 + t] = red[0];
        __syncthreads();
    }
}

// ---------------- K3: v_tidal[t][d] = sum_r alpha[r][t] * v[r][d] (split-K) -
__global__ void __launch_bounds__(256) k_vtidal() {
    __shared__ float shA[32 * 84];   // [r][t] = alpha
    __shared__ float shB[32 * 132];  // [r][d] = v
    const int b = blockIdx.y;
    const int d0 = blockIdx.x * 128;
    const int kz = blockIdx.z;
    const int tid = threadIdx.x;
    const int tr = tid & 15, tc = tid >> 4;
    const float* sTb = g_sT + (size_t)b * 75 * 2048;
    const float* vb  = g_v  + (size_t)b * 2048 * 256;
    const float* rsb = g_rowstats + (size_t)b * 2048 * 10;
    const float* civ = g_cinv_nt + b * 75;
    float acc[5][8];
    #pragma unroll
    for (int j = 0; j < 5; j++)
        #pragma unroll
        for (int n = 0; n < 8; n++) acc[j][n] = 0.f;

    const int rbeg = kz * 512;
    for (int r0 = rbeg; r0 < rbeg + 512; r0 += 32) {
        for (int i = tid; i < 640; i += 256) {
            int t = i >> 3;
            int rloc = (i & 7) * 4;
            if (t < 75) {
                float4 s4 = *(const float4*)(sTb + (size_t)t * 2048 + r0 + rloc);
                int seg = t / 15;
                float ci = civ[t];
                float sv[4] = {s4.x, s4.y, s4.z, s4.w};
                #pragma unroll
                for (int j = 0; j < 4; j++) {
                    float2 rs = *(const float2*)(rsb + ((size_t)(r0 + rloc + j) * 5 + seg) * 2);
                    shA[(rloc + j) * 84 + t] = expf(G1 * expf(sv[j] - rs.x) * rs.y) * ci;
                }
            } else {
                #pragma unroll
                for (int j = 0; j < 4; j++) shA[(rloc + j) * 84 + t] = 0.f;
            }
        }
        for (int q = tid; q < 1024; q += 256) {
            int r = q >> 5, d = (q & 31) * 4;
            *(float4*)(shB + r * 132 + d) = *(const float4*)(vb + (size_t)(r0 + r) * 256 + d0 + d);
        }
        __syncthreads();
        #pragma unroll
        for (int r = 0; r < 32; r++) {
            float av[5];
            #pragma unroll
            for (int j = 0; j < 5; j++) av[j] = shA[r * 84 + tr * 5 + j];
            float4 b0 = *(const float4*)(shB + r * 132 + tc * 8);
            float4 b1 = *(const float4*)(shB + r * 132 + tc * 8 + 4);
            float bv[8] = {b0.x, b0.y, b0.z, b0.w, b1.x, b1.y, b1.z, b1.w};
            #pragma unroll
            for (int j = 0; j < 5; j++)
                #pragma unroll
                for (int n = 0; n < 8; n++)
                    acc[j][n] = fmaf(av[j], bv[n], acc[j][n]);
        }
        __syncthreads();
    }
    float* outp = g_vtp + (size_t)kz * 40 * 75 * 256 + (size_t)b * 75 * 256;
    #pragma unroll
    for (int j = 0; j < 5; j++) {
        int t = tr * 5 + j;
        if (t < 75) {
            float* o = outp + (size_t)t * 256 + d0 + tc * 8;
            float4 o0 = {acc[j][0], acc[j][1], acc[j][2], acc[j][3]};
            float4 o1 = {acc[j][4], acc[j][5], acc[j][6], acc[j][7]};
            *(float4*)o = o0; *(float4*)(o + 4) = o1;
        }
    }
}

// ---------------- K4a: logit -> score1 (deterministic) ----------------------
__global__ void __launch_bounds__(256) k_score1(const float* __restrict__ text) {
    __shared__ float el[80];
    const int b = blockIdx.x, blk = b / 5;
    const int tid = threadIdx.x, lane = tid & 31, w = tid >> 5;
    const size_t SL = (size_t)40 * 75 * 256;
    for (int t = w; t < 75; t += 8) {
        const float* e = text + ((size_t)blk * 75 + t) * 256;
        const size_t voff = ((size_t)b * 75 + t) * 256;
        float dot = 0.f, nv = 0.f, ne = 0.f;
        #pragma unroll
        for (int j = 0; j < 8; j++) {
            int d = lane + 32 * j;
            float a = g_vtp[voff + d] + g_vtp[SL + voff + d]
                    + g_vtp[2 * SL + voff + d] + g_vtp[3 * SL + voff + d];
            float c = e[d];
            dot = fmaf(a, c, dot); nv = fmaf(a, a, nv); ne = fmaf(c, c, ne);
        }
        #pragma unroll
        for (int o = 16; o > 0; o >>= 1) {
            dot += __shfl_xor_sync(0xffffffffu, dot, o);
            nv  += __shfl_xor_sync(0xffffffffu, nv,  o);
            ne  += __shfl_xor_sync(0xffffffffu, ne,  o);
        }
        if (lane == 0)
            el[t] = expf(dot / (fmaxf(sqrtf(nv), 1e-12f) * fmaxf(sqrtf(ne), 1e-12f)));
    }
    __syncthreads();
    if (tid < 5) {
        float s = 0.f;
        for (int l = 0; l < 15; l++) s += el[tid * 15 + l];
        g_score1[b * 5 + tid] = s;
    }
}

// ---------------- K4b: em -> logit2 -----------------------------------------
__global__ void __launch_bounds__(256) k_logit2(const float* __restrict__ text) {
    const int b = blockIdx.x, m = blockIdx.y, blk = b / 5;
    const int tid = threadIdx.x;
    __shared__ float shsd[15];
    __shared__ float red[256];
    const float vv = g_vns[((size_t)b * 8 + m) * 256 + tid];
    for (int sb = 0; sb < 5; sb++) {
        if (tid < 15) shsd[tid] = g_sd[((size_t)b * 8 + m) * 75 + sb * 15 + tid];
        __syncthreads();
        float segsum = 0.f;
        #pragma unroll
        for (int l = 0; l < 15; l++) segsum += shsd[l];
        float em = 0.f;
        #pragma unroll
        for (int l = 0; l < 15; l++)
            em = fmaf(shsd[l], text[((size_t)blk * 75 + sb * 15 + l) * 256 + tid], em);
        em /= segsum;
        red[tid] = em * em; __syncthreads();
        for (int o = 128; o > 0; o >>= 1) { if (tid < o) red[tid] += red[tid + o]; __syncthreads(); }
        const float nrm = fmaxf(sqrtf(red[0]), 1e-12f);
        __syncthreads();
        red[tid] = (em / nrm) * vv; __syncthreads();
        for (int o = 128; o > 0; o >>= 1) { if (tid < o) red[tid] += red[tid + o]; __syncthreads(); }
        if (tid == 0) g_logit2[((size_t)b * 8 + m) * 5 + sb] = red[0] / 256.0f;
        __syncthreads();
    }
}

// ---------------- K4c: beta decorrelation regularizer -----------------------
__global__ void __launch_bounds__(256) k_reg() {
    const int b = blockIdx.x, tid = threadIdx.x;
    __shared__ float ssd[600];
    __shared__ float sseg[40];
    __shared__ float sbeta[600];
    __shared__ float red[256];
    for (int i = tid; i < 600; i += 256) ssd[i] = g_sd[(size_t)b * 600 + i];
    __syncthreads();
    if (tid < 40) {
        int m = tid / 5, sb = tid % 5;
        float s = 0.f;
        for (int l = 0; l < 15; l++) s += ssd[m * 75 + sb * 15 + l];
        sseg[tid] = s;
    }
    __syncthreads();
    for (int i = tid; i < 600; i += 256) {
        int m = i / 75, t = i % 75;
        sbeta[i] = ssd[i] / sseg[m * 5 + t / 15];
    }
    __syncthreads();
    float p = 0.f;
    if (tid < 64) {
        int m = tid >> 3, n = tid & 7;
        if (m != n) {
            float a = 0.f;
            for (int t = 0; t < 75; t++) a = fmaf(sbeta[m * 75 + t], sbeta[n * 75 + t], a);
            p = a * a;
        }
    }
    red[tid] = p; __syncthreads();
    for (int o = 128; o > 0; o >>= 1) { if (tid < o) red[tid] += red[tid + o]; __syncthreads(); }
    if (tid == 0) g_regval[b] = sqrtf(red[0]);
}

// ---------------- K5: final scalar -------------------------------------------
__global__ void k_final(float* __restrict__ out) {
    const int tid = threadIdx.x;
    __shared__ float lsm[200];
    __shared__ float bscore[8];
    if (tid < 200) {
        int blk = tid / 25, rem = tid % 25, i = rem / 5, sb = rem % 5;
        int gi = blk * 5 + i;
        float s2 = 0.f;
        #pragma unroll
        for (int m = 0; m < 8; m++) s2 += expf(g_logit2[((size_t)gi * 8 + m) * 5 + sb]);
        float l1 = logf(powf(g_score1[gi * 5 + sb], 0.2f) + EPSL);
        float l2 = logf(powf(s2, 0.2f) + EPSL);
        lsm[tid] = 10.0f * (l1 + l2);
    }
    __syncthreads();
    if (tid < 8) {
        const float* L = lsm + tid * 25;
        float rows[5] = {0, 0, 0, 0, 0}, cols[5] = {0, 0, 0, 0, 0};
        for (int i = 0; i < 5; i++)
            for (int sb = 0; sb < 5; sb++) {
                rows[i] += L[i * 5 + sb];
                cols[sb] += L[i * 5 + sb];
            }
        float acc = 0.f;
        for (int i = 0; i < 5; i++) {
            float dg = L[i * 5 + i];
            acc += -logf(dg / rows[i] + EPSL) - logf(dg / cols[i] + EPSL);
        }
        float reg = 0.f;
        for (int i = 0; i < 5; i++) reg += g_regval[tid * 5 + i];
        bscore[tid] = acc / 5.0f + reg / 5.0f;
    }
    __syncthreads();
    if (tid == 0) {
        float tot = 0.f;
        for (int k = 0; k < 8; k++) tot += bscore[k];
        out[0] = tot / 9.0f;
    }
}

// ---------------- launch -----------------------------------------------------
extern "C" void kernel_launch(void* const* d_in, const int* in_sizes, int n_in,
                              void* d_out, int out_size) {
    (void)in_sizes; (void)n_in; (void)out_size;
    const float* image = (const float*)d_in[0];
    const float* text  = (const float*)d_in[1];
    float* out = (float*)d_out;

    k_transpose<<<dim3(8, 8, 320), dim3(32, 8)>>>(image);
    k_vns<<<320, 256>>>();
    k_gemm_s<<<dim3(16, 40), 256>>>(text);
    k_colstats<<<dim3(75, 40), 256>>>();
    k_vtidal<<<dim3(2, 40, 4), 256>>>();
    k_score1<<<40, 256>>>(text);
    k_logit2<<<dim3(40, 8), 256>>>(text);
    k_reg<<<40, 256>>>();
    k_final<<<1, 256>>>(out);
}

// round 2
// speedup vs baseline: 1.1178x; 1.1178x over previous
#include <cuda_runtime.h>
#include <math.h>

#define G1 4.0f
#define EPSL 1e-10f

// ---------------- scratch (device globals) ----------------------------------
__device__ float g_v[40u*2048u*256u];        // [b][r][d]   83.9 MB (transposed image)
__device__ float g_sT[40u*75u*2048u];        // [b][t][r]: s scores, later overwritten with alpha-numerators
__device__ float g_rowstats[40u*2048u*5u*2u];// [b][r][seg]{max, 1/sumexp}
__device__ float g_cinv_nt[40*75];           // 1/sum_r exp(G1*softmax_seg)
__device__ float g_sd[40*8*75];              // [b][m][t]
__device__ float g_vtp[4u*40u*75u*256u];     // split-K partials of v_tidal
__device__ float g_vns[40*8*256];            // v_norm_sum
__device__ float g_score1[40*5];
__device__ float g_logit2[40*8*5];
__device__ float g_regval[40];

// ============ PHASE 1: gemm_s (640 blks) + transpose (320) + vns (320) ======
__global__ void __launch_bounds__(256) k_phase1(const float* __restrict__ image,
                                                const float* __restrict__ text) {
    __shared__ __align__(16) float pool[10320];
    const int bx = blockIdx.x;
    const int tid = threadIdx.x;

    if (bx < 640) {
        // -------- s = v @ e^T, reading image directly (A is image[b][m][k][p]) ---
        const int b  = bx >> 4;
        const int r0 = (bx & 15) * 128;
        const int m  = r0 >> 8, p0 = r0 & 255;
        const float* srcA = image + (size_t)(b * 8 + m) * 65536;
        const int blk = b / 5;
        const float* ef = text + (size_t)blk * 75 * 256;
        float* shA = pool;            // [32 k][132]
        float* shB = pool + 32 * 132; // [32 k][84]
        const int tr = tid & 15, tc = tid >> 4;

        float acc[8][5];
        #pragma unroll
        for (int i = 0; i < 8; i++)
            #pragma unroll
            for (int j = 0; j < 5; j++) acc[i][j] = 0.f;

        for (int kb = 0; kb < 256; kb += 32) {
            #pragma unroll
            for (int it = 0; it < 4; it++) {
                int lin = tid + it * 256;
                int k = lin >> 5, pq = (lin & 31) * 4;
                float4 va = *(const float4*)(srcA + (size_t)(kb + k) * 256 + p0 + pq);
                *(float4*)(shA + k * 132 + pq) = va;
            }
            #pragma unroll
            for (int it = 0; it < 3; it++) {
                int e4 = tid + it * 256;
                if (e4 < 640) {
                    int e = e4 * 4;
                    int t = e >> 5, k = e & 31;
                    float4 vb = make_float4(0.f, 0.f, 0.f, 0.f);
                    if (t < 75) vb = *(const float4*)(ef + (size_t)t * 256 + kb + k);
                    shB[(k + 0) * 84 + t] = vb.x;
                    shB[(k + 1) * 84 + t] = vb.y;
                    shB[(k + 2) * 84 + t] = vb.z;
                    shB[(k + 3) * 84 + t] = vb.w;
                }
            }
            __syncthreads();
            #pragma unroll
            for (int k = 0; k < 32; k++) {
                float4 a0 = *(const float4*)(shA + k * 132 + tr * 8);
                float4 a1 = *(const float4*)(shA + k * 132 + tr * 8 + 4);
                float av[8] = {a0.x, a0.y, a0.z, a0.w, a1.x, a1.y, a1.z, a1.w};
                float bv[5];
                #pragma unroll
                for (int j = 0; j < 5; j++) bv[j] = shB[k * 84 + tc * 5 + j];
                #pragma unroll
                for (int i = 0; i < 8; i++)
                    #pragma unroll
                    for (int j = 0; j < 5; j++)
                        acc[i][j] = fmaf(av[i], bv[j], acc[i][j]);
            }
            __syncthreads();
        }
        // stage C into shared as sc[t][r] (stride 129)
        float* sc = pool;
        #pragma unroll
        for (int i = 0; i < 8; i++)
            #pragma unroll
            for (int j = 0; j < 5; j++)
                sc[(tc * 5 + j) * 129 + tr * 8 + i] = acc[i][j];
        __syncthreads();
        // per-row segment softmax stats
        for (int task = tid; task < 640; task += 256) {
            int r = task & 127, seg = task >> 7;
            float mx = -3.4e38f;
            #pragma unroll
            for (int l = 0; l < 15; l++) mx = fmaxf(mx, sc[(seg * 15 + l) * 129 + r]);
            float se = 0.f;
            #pragma unroll
            for (int l = 0; l < 15; l++) se += __expf(sc[(seg * 15 + l) * 129 + r] - mx);
            size_t ridx = ((size_t)b * 2048 + r0 + r) * 5 + seg;
            g_rowstats[ridx * 2]     = mx;
            g_rowstats[ridx * 2 + 1] = 1.0f / se;
        }
        // write transposed s
        for (int i = tid; i < 9600; i += 256) {
            int t = i >> 7, r = i & 127;
            g_sT[((size_t)b * 75 + t) * 2048 + r0 + r] = sc[t * 129 + r];
        }
    } else if (bx < 960) {
        // -------- transpose image [bm][d][p] -> g_v [b][r=m*256+p][d] ------------
        const int bm = bx - 640;
        const float* src = image + (size_t)bm * 65536;
        const int b = bm >> 3, mm = bm & 7;
        float* dst = g_v + ((size_t)b * 2048 + mm * 256) * 256;
        float* sm = pool; // [32][257]
        for (int sub = 0; sub < 8; sub++) {
            const int d0 = sub * 32;
            #pragma unroll
            for (int i = 0; i < 32; i++)
                sm[i * 257 + tid] = src[(size_t)(d0 + i) * 256 + tid];
            __syncthreads();
            #pragma unroll
            for (int i = 0; i < 32; i++) {
                int p = (tid >> 5) + i * 8;
                dst[(size_t)p * 256 + d0 + (tid & 31)] = sm[(tid & 31) * 257 + p];
            }
            __syncthreads();
        }
    } else {
        // -------- vns: v_norm_sum[b][m][d] from image directly -------------------
        const int bm = bx - 960;
        const float* src = image + (size_t)bm * 65536;
        float* invn = pool; // 256
        const int lane = tid & 31, w = tid >> 5;
        float s0 = 0.f, s1 = 0.f, s2 = 0.f, s3 = 0.f;
        for (int d = 0; d < 256; d += 4) {
            float x0 = src[(size_t)(d + 0) * 256 + tid];
            float x1 = src[(size_t)(d + 1) * 256 + tid];
            float x2 = src[(size_t)(d + 2) * 256 + tid];
            float x3 = src[(size_t)(d + 3) * 256 + tid];
            s0 = fmaf(x0, x0, s0); s1 = fmaf(x1, x1, s1);
            s2 = fmaf(x2, x2, s2); s3 = fmaf(x3, x3, s3);
        }
        invn[tid] = 1.0f / fmaxf(sqrtf((s0 + s1) + (s2 + s3)), 1e-12f);
        __syncthreads();
        for (int j = 0; j < 32; j++) {
            int d = w * 32 + j;
            const float* row = src + (size_t)d * 256;
            float a = 0.f;
            #pragma unroll
            for (int q = 0; q < 8; q++) {
                int p = lane + 32 * q;
                a = fmaf(row[p], invn[p], a);
            }
            #pragma unroll
            for (int o = 16; o > 0; o >>= 1) a += __shfl_xor_sync(0xffffffffu, a, o);
            if (lane == 0) g_vns[(size_t)bm * 256 + d] = a;
        }
    }
}

// ============ PHASE 2: column stats + sd + alpha-numerator (in-place) =======
__global__ void __launch_bounds__(256) k_colstats() {
    const int t = blockIdx.x, b = blockIdx.y, seg = t / 15;
    const int tid = threadIdx.x, lane = tid & 31, w = tid >> 5;
    float* col = g_sT + ((size_t)b * 75 + t) * 2048;
    __shared__ float smx[8];
    __shared__ float ssm[8];
    __shared__ float sm9[72];

    float vals[8];
    #pragma unroll
    for (int k = 0; k < 8; k++) vals[k] = col[tid + 256 * k];

    float mx = vals[0];
    #pragma unroll
    for (int k = 1; k < 8; k++) mx = fmaxf(mx, vals[k]);
    #pragma unroll
    for (int o = 16; o > 0; o >>= 1) mx = fmaxf(mx, __shfl_xor_sync(0xffffffffu, mx, o));
    if (lane == 0) smx[w] = mx;
    __syncthreads();
    float cmax = smx[0];
    #pragma unroll
    for (int q = 1; q < 8; q++) cmax = fmaxf(cmax, smx[q]);

    float e1[8];
    float sraw = 0.f, snt = 0.f;
    const float* rsb = g_rowstats + (size_t)b * 2048 * 10;
    #pragma unroll
    for (int k = 0; k < 8; k++) {
        int r = tid + 256 * k;
        e1[k] = __expf(vals[k] - cmax);
        sraw += e1[k];
        float2 rs = *(const float2*)(rsb + ((size_t)r * 5 + seg) * 2);
        float al = __expf(G1 * __expf(vals[k] - rs.x) * rs.y);
        snt += al;
        col[r] = al;  // overwrite s with alpha-numerator
    }

    float sr = sraw;
    #pragma unroll
    for (int o = 16; o > 0; o >>= 1) sr += __shfl_xor_sync(0xffffffffu, sr, o);
    if (lane == 0) ssm[w] = sr;
    __syncthreads();
    float tot = 0.f;
    #pragma unroll
    for (int q = 0; q < 8; q++) tot += ssm[q];
    const float cinv = 1.0f / tot;

    float vred[9];
    vred[0] = snt;
    #pragma unroll
    for (int k = 0; k < 8; k++) vred[1 + k] = __expf(e1[k] * cinv);
    #pragma unroll
    for (int j = 0; j < 9; j++) {
        float v = vred[j];
        #pragma unroll
        for (int o = 16; o > 0; o >>= 1) v += __shfl_xor_sync(0xffffffffu, v, o);
        if (lane == 0) sm9[w * 9 + j] = v;
    }
    __syncthreads();
    if (tid < 9) {
        float s = 0.f;
        #pragma unroll
        for (int q = 0; q < 8; q++) s += sm9[q * 9 + tid];
        if (tid == 0) g_cinv_nt[b * 75 + t] = 1.0f / s;
        else g_sd[((size_t)b * 8 + (tid - 1)) * 75 + t] = s;
    }
}

// ============ PHASE 3: vtidal (320) + logit2 (320) + reg (40) ===============
__global__ void __launch_bounds__(256) k_phase3(const float* __restrict__ text) {
    __shared__ __align__(16) float pool[6912];
    __shared__ float scv[80];
    const int bx = blockIdx.x;
    const int tid = threadIdx.x;

    if (bx < 320) {
        // -------- v_tidal[t][d] = sum_r alpha[r][t] * v[r][d] (split-K=4) -------
        const int kz = bx / 80;
        const int rem = bx % 80;
        const int b = rem >> 1;
        const int d0 = (rem & 1) * 128;
        const int tr = tid & 15, tc = tid >> 4;
        float* shA = pool;            // [32 r][84 t]
        float* shB = pool + 32 * 84;  // [32 r][132 d]
        const float* sTb = g_sT + (size_t)b * 75 * 2048;
        const float* vb  = g_v  + (size_t)b * 2048 * 256;
        if (tid < 75) scv[tid] = g_cinv_nt[b * 75 + tid];
        __syncthreads();

        float acc[5][8];
        #pragma unroll
        for (int j = 0; j < 5; j++)
            #pragma unroll
            for (int n = 0; n < 8; n++) acc[j][n] = 0.f;

        const int rbeg = kz * 512;
        for (int r0 = rbeg; r0 < rbeg + 512; r0 += 32) {
            for (int i = tid; i < 640; i += 256) {
                int t = i >> 3;
                int rloc = (i & 7) * 4;
                if (t < 75) {
                    float ci = scv[t];
                    float4 s4 = *(const float4*)(sTb + (size_t)t * 2048 + r0 + rloc);
                    shA[(rloc + 0) * 84 + t] = s4.x * ci;
                    shA[(rloc + 1) * 84 + t] = s4.y * ci;
                    shA[(rloc + 2) * 84 + t] = s4.z * ci;
                    shA[(rloc + 3) * 84 + t] = s4.w * ci;
                } else {
                    #pragma unroll
                    for (int j = 0; j < 4; j++) shA[(rloc + j) * 84 + t] = 0.f;
                }
            }
            for (int q = tid; q < 1024; q += 256) {
                int r = q >> 5, d = (q & 31) * 4;
                *(float4*)(shB + r * 132 + d) =
                    *(const float4*)(vb + (size_t)(r0 + r) * 256 + d0 + d);
            }
            __syncthreads();
            #pragma unroll
            for (int r = 0; r < 32; r++) {
                float av[5];
                #pragma unroll
                for (int j = 0; j < 5; j++) av[j] = shA[r * 84 + tr * 5 + j];
                float4 b0 = *(const float4*)(shB + r * 132 + tc * 8);
                float4 b1 = *(const float4*)(shB + r * 132 + tc * 8 + 4);
                float bv[8] = {b0.x, b0.y, b0.z, b0.w, b1.x, b1.y, b1.z, b1.w};
                #pragma unroll
                for (int j = 0; j < 5; j++)
                    #pragma unroll
                    for (int n = 0; n < 8; n++)
                        acc[j][n] = fmaf(av[j], bv[n], acc[j][n]);
            }
            __syncthreads();
        }
        float* outp = g_vtp + (size_t)kz * 40 * 75 * 256 + (size_t)b * 75 * 256;
        #pragma unroll
        for (int j = 0; j < 5; j++) {
            int t = tr * 5 + j;
            if (t < 75) {
                float* o = outp + (size_t)t * 256 + d0 + tc * 8;
                float4 o0 = {acc[j][0], acc[j][1], acc[j][2], acc[j][3]};
                float4 o1 = {acc[j][4], acc[j][5], acc[j][6], acc[j][7]};
                *(float4*)o = o0; *(float4*)(o + 4) = o1;
            }
        }
    } else if (bx < 640) {
        // -------- logit2 ---------------------------------------------------------
        const int idx = bx - 320;
        const int b = idx >> 3, m = idx & 7, blk = b / 5;
        float* shsd = pool;        // 15
        float* red = pool + 16;    // 256
        const float vv = g_vns[((size_t)b * 8 + m) * 256 + tid];
        for (int sb = 0; sb < 5; sb++) {
            if (tid < 15) shsd[tid] = g_sd[((size_t)b * 8 + m) * 75 + sb * 15 + tid];
            __syncthreads();
            float segsum = 0.f;
            #pragma unroll
            for (int l = 0; l < 15; l++) segsum += shsd[l];
            float em = 0.f;
            #pragma unroll
            for (int l = 0; l < 15; l++)
                em = fmaf(shsd[l], text[((size_t)blk * 75 + sb * 15 + l) * 256 + tid], em);
            em /= segsum;
            red[tid] = em * em; __syncthreads();
            for (int o = 128; o > 0; o >>= 1) { if (tid < o) red[tid] += red[tid + o]; __syncthreads(); }
            const float nrm = fmaxf(sqrtf(red[0]), 1e-12f);
            __syncthreads();
            red[tid] = (em / nrm) * vv; __syncthreads();
            for (int o = 128; o > 0; o >>= 1) { if (tid < o) red[tid] += red[tid + o]; __syncthreads(); }
            if (tid == 0) g_logit2[((size_t)b * 8 + m) * 5 + sb] = red[0] / 256.0f;
            __syncthreads();
        }
    } else {
        // -------- beta decorrelation regularizer --------------------------------
        const int b = bx - 640;
        float* ssd   = pool;        // 600
        float* sseg  = pool + 600;  // 40
        float* sbeta = pool + 640;  // 600
        float* red   = pool + 1240; // 256
        for (int i = tid; i < 600; i += 256) ssd[i] = g_sd[(size_t)b * 600 + i];
        __syncthreads();
        if (tid < 40) {
            int m = tid / 5, sb = tid % 5;
            float s = 0.f;
            for (int l = 0; l < 15; l++) s += ssd[m * 75 + sb * 15 + l];
            sseg[tid] = s;
        }
        __syncthreads();
        for (int i = tid; i < 600; i += 256) {
            int m = i / 75, t = i % 75;
            sbeta[i] = ssd[i] / sseg[m * 5 + t / 15];
        }
        __syncthreads();
        float p = 0.f;
        if (tid < 64) {
            int m = tid >> 3, n = tid & 7;
            if (m != n) {
                float a = 0.f;
                for (int t = 0; t < 75; t++) a = fmaf(sbeta[m * 75 + t], sbeta[n * 75 + t], a);
                p = a * a;
            }
        }
        red[tid] = p; __syncthreads();
        for (int o = 128; o > 0; o >>= 1) { if (tid < o) red[tid] += red[tid + o]; __syncthreads(); }
        if (tid == 0) g_regval[b] = sqrtf(red[0]);
    }
}

// ============ PHASE 4a: score1 ==============================================
__global__ void __launch_bounds__(256) k_score1(const float* __restrict__ text) {
    __shared__ float el[80];
    const int b = blockIdx.x, blk = b / 5;
    const int tid = threadIdx.x, lane = tid & 31, w = tid >> 5;
    const size_t SL = (size_t)40 * 75 * 256;
    for (int t = w; t < 75; t += 8) {
        const float* e = text + ((size_t)blk * 75 + t) * 256;
        const size_t voff = ((size_t)b * 75 + t) * 256;
        float dot = 0.f, nv = 0.f, ne = 0.f;
        #pragma unroll
        for (int j = 0; j < 8; j++) {
            int d = lane + 32 * j;
            float a = g_vtp[voff + d] + g_vtp[SL + voff + d]
                    + g_vtp[2 * SL + voff + d] + g_vtp[3 * SL + voff + d];
            float c = e[d];
            dot = fmaf(a, c, dot); nv = fmaf(a, a, nv); ne = fmaf(c, c, ne);
        }
        #pragma unroll
        for (int o = 16; o > 0; o >>= 1) {
            dot += __shfl_xor_sync(0xffffffffu, dot, o);
            nv  += __shfl_xor_sync(0xffffffffu, nv,  o);
            ne  += __shfl_xor_sync(0xffffffffu, ne,  o);
        }
        if (lane == 0)
            el[t] = __expf(dot / (fmaxf(sqrtf(nv), 1e-12f) * fmaxf(sqrtf(ne), 1e-12f)));
    }
    __syncthreads();
    if (tid < 5) {
        float s = 0.f;
        for (int l = 0; l < 15; l++) s += el[tid * 15 + l];
        g_score1[b * 5 + tid] = s;
    }
}

// ============ PHASE 4b: final scalar ========================================
__global__ void k_final(float* __restrict__ out) {
    const int tid = threadIdx.x;
    __shared__ float lsm[200];
    __shared__ float bscore[8];
    if (tid < 200) {
        int blk = tid / 25, rem = tid % 25, i = rem / 5, sb = rem % 5;
        int gi = blk * 5 + i;
        float s2 = 0.f;
        #pragma unroll
        for (int m = 0; m < 8; m++) s2 += __expf(g_logit2[((size_t)gi * 8 + m) * 5 + sb]);
        float l1 = __logf(__powf(g_score1[gi * 5 + sb], 0.2f) + EPSL);
        float l2 = __logf(__powf(s2, 0.2f) + EPSL);
        lsm[tid] = 10.0f * (l1 + l2);
    }
    __syncthreads();
    if (tid < 8) {
        const float* L = lsm + tid * 25;
        float rows[5] = {0, 0, 0, 0, 0}, cols[5] = {0, 0, 0, 0, 0};
        for (int i = 0; i < 5; i++)
            for (int sb = 0; sb < 5; sb++) {
                rows[i] += L[i * 5 + sb];
                cols[sb] += L[i * 5 + sb];
            }
        float acc = 0.f;
        for (int i = 0; i < 5; i++) {
            float dg = L[i * 5 + i];
            acc += -__logf(dg / rows[i] + EPSL) - __logf(dg / cols[i] + EPSL);
        }
        float reg = 0.f;
        for (int i = 0; i < 5; i++) reg += g_regval[tid * 5 + i];
        bscore[tid] = acc / 5.0f + reg / 5.0f;
    }
    __syncthreads();
    if (tid == 0) {
        float tot = 0.f;
        for (int k = 0; k < 8; k++) tot += bscore[k];
        out[0] = tot / 9.0f;
    }
}

// ---------------- launch -----------------------------------------------------
extern "C" void kernel_launch(void* const* d_in, const int* in_sizes, int n_in,
                              void* d_out, int out_size) {
    (void)in_sizes; (void)n_in; (void)out_size;
    const float* image = (const float*)d_in[0];
    const float* text  = (const float*)d_in[1];
    float* out = (float*)d_out;

    k_phase1<<<1280, 256>>>(image, text);
    k_colstats<<<dim3(75, 40), 256>>>();
    k_phase3<<<680, 256>>>(text);
    k_score1<<<40, 256>>>(text);
    k_final<<<1, 256>>>(out);
}

// round 3
// speedup vs baseline: 1.3295x; 1.1894x over previous
#include <cuda_runtime.h>
#include <math.h>

#define G1 4.0f
#define EPSL 1e-10f

// ---------------- scratch (device globals) ----------------------------------
__device__ float g_sT[40u*75u*2048u];        // [b][t][r]: s scores, later alpha-numerators
__device__ float g_rowstats[40u*2048u*5u*2u];// [b][r][seg]{max, 1/sumexp}
__device__ float g_cinv_nt[40*75];           // 1/sum_r exp(G1*softmax_seg)
__device__ float g_sd[40*8*75];              // [b][m][t]
__device__ float g_vtp[4u*40u*75u*256u];     // split-K partials of v_tidal
__device__ float g_vns[40*8*256];            // v_norm_sum
__device__ float g_el[40*75];                // exp(logit1) per (b,t)
__device__ float g_logit2[40*8*5];
__device__ float g_regval[40];

// ============ PHASE 1: gemm_s (640 blks) + vns (320) ========================
__global__ void __launch_bounds__(256) k_phase1(const float* __restrict__ image,
                                                const float* __restrict__ text) {
    __shared__ __align__(16) float pool[10320];
    const int bx = blockIdx.x;
    const int tid = threadIdx.x;

    if (bx < 640) {
        // -------- s = v @ e^T, reading image directly (A = image[b][m][k][p]) ---
        const int b  = bx >> 4;
        const int r0 = (bx & 15) * 128;
        const int m  = r0 >> 8, p0 = r0 & 255;
        const float* srcA = image + (size_t)(b * 8 + m) * 65536;
        const int blk = b / 5;
        const float* ef = text + (size_t)blk * 75 * 256;
        float* shA = pool;            // [32 k][132]
        float* shB = pool + 32 * 132; // [32 k][84]
        const int tr = tid & 15, tc = tid >> 4;

        float acc[8][5];
        #pragma unroll
        for (int i = 0; i < 8; i++)
            #pragma unroll
            for (int j = 0; j < 5; j++) acc[i][j] = 0.f;

        for (int kb = 0; kb < 256; kb += 32) {
            #pragma unroll
            for (int it = 0; it < 4; it++) {
                int lin = tid + it * 256;
                int k = lin >> 5, pq = (lin & 31) * 4;
                float4 va = *(const float4*)(srcA + (size_t)(kb + k) * 256 + p0 + pq);
                *(float4*)(shA + k * 132 + pq) = va;
            }
            #pragma unroll
            for (int it = 0; it < 3; it++) {
                int e4 = tid + it * 256;
                if (e4 < 640) {
                    int e = e4 * 4;
                    int t = e >> 5, k = e & 31;
                    float4 vb = make_float4(0.f, 0.f, 0.f, 0.f);
                    if (t < 75) vb = *(const float4*)(ef + (size_t)t * 256 + kb + k);
                    shB[(k + 0) * 84 + t] = vb.x;
                    shB[(k + 1) * 84 + t] = vb.y;
                    shB[(k + 2) * 84 + t] = vb.z;
                    shB[(k + 3) * 84 + t] = vb.w;
                }
            }
            __syncthreads();
            #pragma unroll
            for (int k = 0; k < 32; k++) {
                float4 a0 = *(const float4*)(shA + k * 132 + tr * 8);
                float4 a1 = *(const float4*)(shA + k * 132 + tr * 8 + 4);
                float av[8] = {a0.x, a0.y, a0.z, a0.w, a1.x, a1.y, a1.z, a1.w};
                float bv[5];
                #pragma unroll
                for (int j = 0; j < 5; j++) bv[j] = shB[k * 84 + tc * 5 + j];
                #pragma unroll
                for (int i = 0; i < 8; i++)
                    #pragma unroll
                    for (int j = 0; j < 5; j++)
                        acc[i][j] = fmaf(av[i], bv[j], acc[i][j]);
            }
            __syncthreads();
        }
        // stage C into shared as sc[t][r] (stride 129)
        float* sc = pool;
        #pragma unroll
        for (int i = 0; i < 8; i++)
            #pragma unroll
            for (int j = 0; j < 5; j++)
                sc[(tc * 5 + j) * 129 + tr * 8 + i] = acc[i][j];
        __syncthreads();
        // per-row segment softmax stats
        for (int task = tid; task < 640; task += 256) {
            int r = task & 127, seg = task >> 7;
            float mx = -3.4e38f;
            #pragma unroll
            for (int l = 0; l < 15; l++) mx = fmaxf(mx, sc[(seg * 15 + l) * 129 + r]);
            float se = 0.f;
            #pragma unroll
            for (int l = 0; l < 15; l++) se += __expf(sc[(seg * 15 + l) * 129 + r] - mx);
            size_t ridx = ((size_t)b * 2048 + r0 + r) * 5 + seg;
            g_rowstats[ridx * 2]     = mx;
            g_rowstats[ridx * 2 + 1] = 1.0f / se;
        }
        // write transposed s
        for (int i = tid; i < 9600; i += 256) {
            int t = i >> 7, r = i & 127;
            g_sT[((size_t)b * 75 + t) * 2048 + r0 + r] = sc[t * 129 + r];
        }
    } else {
        // -------- vns: v_norm_sum[b][m][d] from image directly -------------------
        const int bm = bx - 640;
        const float* src = image + (size_t)bm * 65536;
        float* invn = pool; // 256
        const int lane = tid & 31, w = tid >> 5;
        float s0 = 0.f, s1 = 0.f, s2 = 0.f, s3 = 0.f;
        for (int d = 0; d < 256; d += 4) {
            float x0 = src[(size_t)(d + 0) * 256 + tid];
            float x1 = src[(size_t)(d + 1) * 256 + tid];
            float x2 = src[(size_t)(d + 2) * 256 + tid];
            float x3 = src[(size_t)(d + 3) * 256 + tid];
            s0 = fmaf(x0, x0, s0); s1 = fmaf(x1, x1, s1);
            s2 = fmaf(x2, x2, s2); s3 = fmaf(x3, x3, s3);
        }
        invn[tid] = 1.0f / fmaxf(sqrtf((s0 + s1) + (s2 + s3)), 1e-12f);
        __syncthreads();
        for (int j = 0; j < 32; j++) {
            int d = w * 32 + j;
            const float* row = src + (size_t)d * 256;
            float a = 0.f;
            #pragma unroll
            for (int q = 0; q < 8; q++) {
                int p = lane + 32 * q;
                a = fmaf(row[p], invn[p], a);
            }
            #pragma unroll
            for (int o = 16; o > 0; o >>= 1) a += __shfl_xor_sync(0xffffffffu, a, o);
            if (lane == 0) g_vns[(size_t)bm * 256 + d] = a;
        }
    }
}

// ============ PHASE 2: column stats + sd + alpha-numerator (in-place) =======
__global__ void __launch_bounds__(256) k_colstats() {
    const int t = blockIdx.x, b = blockIdx.y, seg = t / 15;
    const int tid = threadIdx.x, lane = tid & 31, w = tid >> 5;
    float* col = g_sT + ((size_t)b * 75 + t) * 2048;
    __shared__ float smx[8];
    __shared__ float ssm[8];
    __shared__ float sm9[72];

    float vals[8];
    #pragma unroll
    for (int k = 0; k < 8; k++) vals[k] = col[tid + 256 * k];

    float mx = vals[0];
    #pragma unroll
    for (int k = 1; k < 8; k++) mx = fmaxf(mx, vals[k]);
    #pragma unroll
    for (int o = 16; o > 0; o >>= 1) mx = fmaxf(mx, __shfl_xor_sync(0xffffffffu, mx, o));
    if (lane == 0) smx[w] = mx;
    __syncthreads();
    float cmax = smx[0];
    #pragma unroll
    for (int q = 1; q < 8; q++) cmax = fmaxf(cmax, smx[q]);

    float e1[8];
    float sraw = 0.f, snt = 0.f;
    const float* rsb = g_rowstats + (size_t)b * 2048 * 10;
    #pragma unroll
    for (int k = 0; k < 8; k++) {
        int r = tid + 256 * k;
        e1[k] = __expf(vals[k] - cmax);
        sraw += e1[k];
        float2 rs = *(const float2*)(rsb + ((size_t)r * 5 + seg) * 2);
        float al = __expf(G1 * __expf(vals[k] - rs.x) * rs.y);
        snt += al;
        col[r] = al;  // overwrite s with alpha-numerator
    }

    float sr = sraw;
    #pragma unroll
    for (int o = 16; o > 0; o >>= 1) sr += __shfl_xor_sync(0xffffffffu, sr, o);
    if (lane == 0) ssm[w] = sr;
    __syncthreads();
    float tot = 0.f;
    #pragma unroll
    for (int q = 0; q < 8; q++) tot += ssm[q];
    const float cinv = 1.0f / tot;

    float vred[9];
    vred[0] = snt;
    #pragma unroll
    for (int k = 0; k < 8; k++) vred[1 + k] = __expf(e1[k] * cinv);
    #pragma unroll
    for (int j = 0; j < 9; j++) {
        float v = vred[j];
        #pragma unroll
        for (int o = 16; o > 0; o >>= 1) v += __shfl_xor_sync(0xffffffffu, v, o);
        if (lane == 0) sm9[w * 9 + j] = v;
    }
    __syncthreads();
    if (tid < 9) {
        float s = 0.f;
        #pragma unroll
        for (int q = 0; q < 8; q++) s += sm9[q * 9 + tid];
        if (tid == 0) g_cinv_nt[b * 75 + t] = 1.0f / s;
        else g_sd[((size_t)b * 8 + (tid - 1)) * 75 + t] = s;
    }
}

// ============ PHASE 3: vtidal (320) + logit2 (320) + reg (40) ===============
__global__ void __launch_bounds__(256) k_phase3(const float* __restrict__ image,
                                                const float* __restrict__ text) {
    __shared__ __align__(16) float pool[6912];
    __shared__ float scv[80];
    const int bx = blockIdx.x;
    const int tid = threadIdx.x;

    if (bx < 320) {
        // ---- v_tidal[t][d] = sum_r alpha[r][t] * v[r][d], v read from image ----
        const int kz = bx / 80;
        const int rem = bx % 80;
        const int b = rem >> 1;
        const int d0 = (rem & 1) * 128;
        const int tr = tid & 15, tc = tid >> 4;
        float* shA = pool;            // [32 r][84 t]  alpha
        float* shB = pool + 32 * 84;  // [128 d][33 r pad]  v^T tile
        const float* sTb = g_sT + (size_t)b * 75 * 2048;
        if (tid < 75) scv[tid] = g_cinv_nt[b * 75 + tid];
        __syncthreads();

        float acc[5][8];
        #pragma unroll
        for (int j = 0; j < 5; j++)
            #pragma unroll
            for (int n = 0; n < 8; n++) acc[j][n] = 0.f;

        const int rbeg = kz * 512;
        for (int r0 = rbeg; r0 < rbeg + 512; r0 += 32) {
            // alpha tile
            for (int i = tid; i < 640; i += 256) {
                int t = i >> 3;
                int rloc = (i & 7) * 4;
                if (t < 75) {
                    float ci = scv[t];
                    float4 s4 = *(const float4*)(sTb + (size_t)t * 2048 + r0 + rloc);
                    shA[(rloc + 0) * 84 + t] = s4.x * ci;
                    shA[(rloc + 1) * 84 + t] = s4.y * ci;
                    shA[(rloc + 2) * 84 + t] = s4.z * ci;
                    shA[(rloc + 3) * 84 + t] = s4.w * ci;
                } else {
                    #pragma unroll
                    for (int j = 0; j < 4; j++) shA[(rloc + j) * 84 + t] = 0.f;
                }
            }
            // v tile, direct from image: r = m*256 + p, tile fits one m
            {
                const int m = r0 >> 8, p0 = r0 & 255;
                const float* src = image + (size_t)(b * 8 + m) * 65536
                                 + (size_t)d0 * 256 + p0;
                #pragma unroll
                for (int it = 0; it < 4; it++) {
                    int lin = tid + it * 256;       // [0,1024)
                    int dd = lin >> 3, p4 = (lin & 7) * 4;
                    float4 va = *(const float4*)(src + (size_t)dd * 256 + p4);
                    shB[dd * 33 + p4 + 0] = va.x;
                    shB[dd * 33 + p4 + 1] = va.y;
                    shB[dd * 33 + p4 + 2] = va.z;
                    shB[dd * 33 + p4 + 3] = va.w;
                }
            }
            __syncthreads();
            #pragma unroll
            for (int r = 0; r < 32; r++) {
                float av[5];
                #pragma unroll
                for (int j = 0; j < 5; j++) av[j] = shA[r * 84 + tr * 5 + j];
                float bv[8];
                #pragma unroll
                for (int n = 0; n < 8; n++) bv[n] = shB[(tc * 8 + n) * 33 + r];
                #pragma unroll
                for (int j = 0; j < 5; j++)
                    #pragma unroll
                    for (int n = 0; n < 8; n++)
                        acc[j][n] = fmaf(av[j], bv[n], acc[j][n]);
            }
            __syncthreads();
        }
        float* outp = g_vtp + (size_t)kz * 40 * 75 * 256 + (size_t)b * 75 * 256;
        #pragma unroll
        for (int j = 0; j < 5; j++) {
            int t = tr * 5 + j;
            if (t < 75) {
                float* o = outp + (size_t)t * 256 + d0 + tc * 8;
                float4 o0 = {acc[j][0], acc[j][1], acc[j][2], acc[j][3]};
                float4 o1 = {acc[j][4], acc[j][5], acc[j][6], acc[j][7]};
                *(float4*)o = o0; *(float4*)(o + 4) = o1;
            }
        }
    } else if (bx < 640) {
        // -------- logit2 ---------------------------------------------------------
        const int idx = bx - 320;
        const int b = idx >> 3, m = idx & 7, blk = b / 5;
        float* shsd = pool;        // 15
        float* red = pool + 16;    // 256
        const float vv = g_vns[((size_t)b * 8 + m) * 256 + tid];
        for (int sb = 0; sb < 5; sb++) {
            if (tid < 15) shsd[tid] = g_sd[((size_t)b * 8 + m) * 75 + sb * 15 + tid];
            __syncthreads();
            float segsum = 0.f;
            #pragma unroll
            for (int l = 0; l < 15; l++) segsum += shsd[l];
            float em = 0.f;
            #pragma unroll
            for (int l = 0; l < 15; l++)
                em = fmaf(shsd[l], text[((size_t)blk * 75 + sb * 15 + l) * 256 + tid], em);
            em /= segsum;
            red[tid] = em * em; __syncthreads();
            for (int o = 128; o > 0; o >>= 1) { if (tid < o) red[tid] += red[tid + o]; __syncthreads(); }
            const float nrm = fmaxf(sqrtf(red[0]), 1e-12f);
            __syncthreads();
            red[tid] = (em / nrm) * vv; __syncthreads();
            for (int o = 128; o > 0; o >>= 1) { if (tid < o) red[tid] += red[tid + o]; __syncthreads(); }
            if (tid == 0) g_logit2[((size_t)b * 8 + m) * 5 + sb] = red[0] / 256.0f;
            __syncthreads();
        }
    } else {
        // -------- beta decorrelation regularizer --------------------------------
        const int b = bx - 640;
        float* ssd   = pool;        // 600
        float* sseg  = pool + 600;  // 40
        float* sbeta = pool + 640;  // 600
        float* red   = pool + 1240; // 256
        for (int i = tid; i < 600; i += 256) ssd[i] = g_sd[(size_t)b * 600 + i];
        __syncthreads();
        if (tid < 40) {
            int m = tid / 5, sb = tid % 5;
            float s = 0.f;
            for (int l = 0; l < 15; l++) s += ssd[m * 75 + sb * 15 + l];
            sseg[tid] = s;
        }
        __syncthreads();
        for (int i = tid; i < 600; i += 256) {
            int m = i / 75, t = i % 75;
            sbeta[i] = ssd[i] / sseg[m * 5 + t / 15];
        }
        __syncthreads();
        float p = 0.f;
        if (tid < 64) {
            int m = tid >> 3, n = tid & 7;
            if (m != n) {
                float a = 0.f;
                for (int t = 0; t < 75; t++) a = fmaf(sbeta[m * 75 + t], sbeta[n * 75 + t], a);
                p = a * a;
            }
        }
        red[tid] = p; __syncthreads();
        for (int o = 128; o > 0; o >>= 1) { if (tid < o) red[tid] += red[tid + o]; __syncthreads(); }
        if (tid == 0) g_regval[b] = sqrtf(red[0]);
    }
}

// ============ PHASE 4a: score1 — one warp per (b,t) =========================
__global__ void __launch_bounds__(32) k_score1(const float* __restrict__ text) {
    const int t = blockIdx.x, b = blockIdx.y, blk = b / 5;
    const int lane = threadIdx.x;
    const size_t SL = (size_t)40 * 75 * 256;
    const size_t voff = ((size_t)b * 75 + t) * 256;
    const float* e = text + ((size_t)blk * 75 + t) * 256;
    float dot = 0.f, nv = 0.f, ne = 0.f;
    #pragma unroll
    for (int j = 0; j < 8; j++) {
        int d = lane + 32 * j;
        float a = g_vtp[voff + d] + g_vtp[SL + voff + d]
                + g_vtp[2 * SL + voff + d] + g_vtp[3 * SL + voff + d];
        float c = e[d];
        dot = fmaf(a, c, dot); nv = fmaf(a, a, nv); ne = fmaf(c, c, ne);
    }
    #pragma unroll
    for (int o = 16; o > 0; o >>= 1) {
        dot += __shfl_xor_sync(0xffffffffu, dot, o);
        nv  += __shfl_xor_sync(0xffffffffu, nv,  o);
        ne  += __shfl_xor_sync(0xffffffffu, ne,  o);
    }
    if (lane == 0)
        g_el[b * 75 + t] = __expf(dot / (fmaxf(sqrtf(nv), 1e-12f) * fmaxf(sqrtf(ne), 1e-12f)));
}

// ============ PHASE 4b: final scalar ========================================
__global__ void k_final(float* __restrict__ out) {
    const int tid = threadIdx.x;
    __shared__ float lsm[200];
    __shared__ float bscore[8];
    if (tid < 200) {
        int blk = tid / 25, rem = tid % 25, i = rem / 5, sb = rem % 5;
        int gi = blk * 5 + i;
        float s2 = 0.f;
        #pragma unroll
        for (int m = 0; m < 8; m++) s2 += __expf(g_logit2[((size_t)gi * 8 + m) * 5 + sb]);
        float s1 = 0.f;
        #pragma unroll
        for (int l = 0; l < 15; l++) s1 += g_el[gi * 75 + sb * 15 + l];
        float l1 = __logf(__powf(s1, 0.2f) + EPSL);
        float l2 = __logf(__powf(s2, 0.2f) + EPSL);
        lsm[tid] = 10.0f * (l1 + l2);
    }
    __syncthreads();
    if (tid < 8) {
        const float* L = lsm + tid * 25;
        float rows[5] = {0, 0, 0, 0, 0}, cols[5] = {0, 0, 0, 0, 0};
        for (int i = 0; i < 5; i++)
            for (int sb = 0; sb < 5; sb++) {
                rows[i] += L[i * 5 + sb];
                cols[sb] += L[i * 5 + sb];
            }
        float acc = 0.f;
        for (int i = 0; i < 5; i++) {
            float dg = L[i * 5 + i];
            acc += -__logf(dg / rows[i] + EPSL) - __logf(dg / cols[i] + EPSL);
        }
        float reg = 0.f;
        for (int i = 0; i < 5; i++) reg += g_regval[tid * 5 + i];
        bscore[tid] = acc / 5.0f + reg / 5.0f;
    }
    __syncthreads();
    if (tid == 0) {
        float tot = 0.f;
        for (int k = 0; k < 8; k++) tot += bscore[k];
        out[0] = tot / 9.0f;
    }
}

// ---------------- launch -----------------------------------------------------
extern "C" void kernel_launch(void* const* d_in, const int* in_sizes, int n_in,
                              void* d_out, int out_size) {
    (void)in_sizes; (void)n_in; (void)out_size;
    const float* image = (const float*)d_in[0];
    const float* text  = (const float*)d_in[1];
    float* out = (float*)d_out;

    k_phase1<<<960, 256>>>(image, text);
    k_colstats<<<dim3(75, 40), 256>>>();
    k_phase3<<<680, 256>>>(image, text);
    k_score1<<<dim3(75, 40), 32>>>(text);
    k_final<<<1, 256>>>(out);
}

// round 5
// speedup vs baseline: 1.7700x; 1.3313x over previous
#include <cuda_runtime.h>
#include <cuda_bf16.h>
#include <math.h>
#include <stdint.h>

#define G1 4.0f
#define EPSL 1e-10f

// ---------------- scratch (device globals) ----------------------------------
__device__ float g_sT[40u*75u*2048u];        // [b][t][r]: s scores -> alpha numerators
__device__ float g_rowstats[40u*2048u*5u*2u];// [b][r][seg]{max, 1/sumexp}
__device__ float g_cinv_nt[40*75];
__device__ float g_sd[40*8*75];
__device__ float g_vtp[4u*40u*75u*256u];     // split-K partials of v_tidal
__device__ float g_vns[40*8*256];
__device__ float g_el[40*75];
__device__ float g_logit2[40*8*5];
__device__ float g_regval[40];

// ---------------- helpers ----------------------------------------------------
__device__ __forceinline__ void mma_bf16(float* c, uint32_t a0, uint32_t a1,
                                         uint32_t a2, uint32_t a3,
                                         uint32_t b0, uint32_t b1) {
    asm volatile(
        "mma.sync.aligned.m16n8k16.row.col.f32.bf16.bf16.f32 "
        "{%0,%1,%2,%3}, {%4,%5,%6,%7}, {%8,%9}, {%0,%1,%2,%3};"
        : "+f"(c[0]), "+f"(c[1]), "+f"(c[2]), "+f"(c[3])
        : "r"(a0), "r"(a1), "r"(a2), "r"(a3), "r"(b0), "r"(b1));
}
__device__ __forceinline__ void bsplit2(float x, float y, uint32_t& hi, uint32_t& lo) {
    __nv_bfloat16 hx = __float2bfloat16_rn(x);
    __nv_bfloat16 hy = __float2bfloat16_rn(y);
    __nv_bfloat16 lx = __float2bfloat16_rn(x - __bfloat162float(hx));
    __nv_bfloat16 ly = __float2bfloat16_rn(y - __bfloat162float(hy));
    __nv_bfloat162 h2 = {hx, hy}, l2 = {lx, ly};
    hi = *(uint32_t*)&h2; lo = *(uint32_t*)&l2;
}

// phase1 smem layout (bytes): TR fp32[32][132] | AH u32[128][20] | AL | BH u32[80][20] | BL
#define P1_AH 16896
#define P1_AL 27136
#define P1_BH 37376
#define P1_BL 43776
#define P1_SZ 50176
// vtidal smem layout: AH u32[80][20] | AL | BH u32[256][20] | BL
#define P3_AL 6400
#define P3_BH 12800
#define P3_BL 33280
#define P3_SZ 53760

// ============ PHASE 1: mma gemm_s (640 blks) + vns (320) ====================
__global__ void __launch_bounds__(256) k_phase1(const float* __restrict__ image,
                                                const float* __restrict__ text) {
    extern __shared__ __align__(16) char dsm[];
    const int bx = blockIdx.x;
    const int tid = threadIdx.x;
    const int wid = tid >> 5, lane = tid & 31;

    if (bx < 640) {
        const int b  = bx >> 4;
        const int rb = bx & 15;
        const int r0 = rb * 128;
        const int m  = rb >> 1, p0 = (rb & 1) * 128;
        const float* srcA = image + (size_t)(b * 8 + m) * 65536;
        const float* ef = text + (size_t)(b / 5) * 75 * 256;
        float* TR = (float*)dsm;
        uint32_t* AH = (uint32_t*)(dsm + P1_AH);
        uint32_t* AL = (uint32_t*)(dsm + P1_AL);
        uint32_t* BH = (uint32_t*)(dsm + P1_BH);
        uint32_t* BL = (uint32_t*)(dsm + P1_BL);
        const int gid = lane >> 2, tig = lane & 3;

        // zero B rows 75..79 once
        for (int i = tid; i < 100; i += 256) {
            BH[75 * 20 + i] = 0; BL[75 * 20 + i] = 0;
        }

        float acc[10][4];
        #pragma unroll
        for (int nt = 0; nt < 10; nt++)
            #pragma unroll
            for (int q = 0; q < 4; q++) acc[nt][q] = 0.f;

        for (int c8 = 0; c8 < 8; c8++) {
            const int kb = c8 * 32;
            // ---- stage A fp32 transpose buffer: TR[k][p] -----------------
            #pragma unroll
            for (int it = 0; it < 4; it++) {
                int lin = tid + it * 256;
                int k = lin >> 5, f4 = (lin & 31) * 4;
                float4 v = *(const float4*)(srcA + (size_t)(kb + k) * 256 + p0 + f4);
                *(float4*)(TR + k * 132 + f4) = v;
            }
            // ---- stage B: text rows [t][k], k-contig ---------------------
            for (int idx = tid; idx < 600; idx += 256) {
                int t = idx >> 3, c4 = (idx & 7) * 4;
                float4 v = *(const float4*)(ef + (size_t)t * 256 + kb + c4);
                uint32_t h0, l0, h1, l1;
                bsplit2(v.x, v.y, h0, l0);
                bsplit2(v.z, v.w, h1, l1);
                int w0 = t * 20 + (c4 >> 1);
                BH[w0] = h0; BH[w0 + 1] = h1;
                BL[w0] = l0; BL[w0 + 1] = l1;
            }
            __syncthreads();
            // ---- convert A: [r][k] bf16 hi/lo ----------------------------
            {
                const int r = tid >> 1, kh = (tid & 1) * 16;
                #pragma unroll
                for (int j = 0; j < 16; j += 2) {
                    float x0 = TR[(kh + j) * 132 + r];
                    float x1 = TR[(kh + j + 1) * 132 + r];
                    uint32_t hi, lo;
                    bsplit2(x0, x1, hi, lo);
                    int w0 = r * 20 + ((kh + j) >> 1);
                    AH[w0] = hi; AL[w0] = lo;
                }
            }
            __syncthreads();
            // ---- mma ------------------------------------------------------
            const int rA = wid * 16 + gid;
            #pragma unroll
            for (int ks = 0; ks < 2; ks++) {
                const int ko = ks * 8 + tig;
                uint32_t ah0 = AH[rA * 20 + ko],       ah1 = AH[(rA + 8) * 20 + ko];
                uint32_t ah2 = AH[rA * 20 + ko + 4],   ah3 = AH[(rA + 8) * 20 + ko + 4];
                uint32_t al0 = AL[rA * 20 + ko],       al1 = AL[(rA + 8) * 20 + ko];
                uint32_t al2 = AL[rA * 20 + ko + 4],   al3 = AL[(rA + 8) * 20 + ko + 4];
                #pragma unroll
                for (int nt = 0; nt < 10; nt++) {
                    int nb = (nt * 8 + gid) * 20 + ko;
                    uint32_t bh0 = BH[nb], bh1 = BH[nb + 4];
                    uint32_t bl0 = BL[nb], bl1 = BL[nb + 4];
                    mma_bf16(acc[nt], ah0, ah1, ah2, ah3, bh0, bh1);
                    mma_bf16(acc[nt], ah0, ah1, ah2, ah3, bl0, bl1);
                    mma_bf16(acc[nt], al0, al1, al2, al3, bh0, bh1);
                }
            }
            __syncthreads();
        }
        // ---- epilogue: stage C to sc[t][132 r] --------------------------
        float* sc = (float*)dsm;
        const int rA = wid * 16 + gid;
        #pragma unroll
        for (int nt = 0; nt < 10; nt++) {
            int t0 = nt * 8 + tig * 2;
            sc[t0 * 132 + rA]           = acc[nt][0];
            sc[(t0 + 1) * 132 + rA]     = acc[nt][1];
            sc[t0 * 132 + rA + 8]       = acc[nt][2];
            sc[(t0 + 1) * 132 + rA + 8] = acc[nt][3];
        }
        __syncthreads();
        if (tid < 128) {
            const int r = tid;
            #pragma unroll
            for (int seg = 0; seg < 5; seg++) {
                float mx = -3.4e38f;
                #pragma unroll
                for (int l = 0; l < 15; l++)
                    mx = fmaxf(mx, sc[(seg * 15 + l) * 132 + r]);
                float se = 0.f;
                #pragma unroll
                for (int l = 0; l < 15; l++)
                    se += __expf(sc[(seg * 15 + l) * 132 + r] - mx);
                size_t ridx = ((size_t)b * 2048 + r0 + r) * 5 + seg;
                g_rowstats[ridx * 2]     = mx;
                g_rowstats[ridx * 2 + 1] = 1.0f / se;
            }
        }
        for (int i = tid; i < 9600; i += 256) {
            int t = i >> 7, r = i & 127;
            g_sT[((size_t)b * 75 + t) * 2048 + r0 + r] = sc[t * 132 + r];
        }
    } else {
        // -------- vns from image directly ------------------------------------
        const int bm = bx - 640;
        const float* src = image + (size_t)bm * 65536;
        float* invn = (float*)dsm;
        float s0 = 0.f, s1 = 0.f, s2 = 0.f, s3 = 0.f;
        for (int d = 0; d < 256; d += 4) {
            float x0 = src[(size_t)(d + 0) * 256 + tid];
            float x1 = src[(size_t)(d + 1) * 256 + tid];
            float x2 = src[(size_t)(d + 2) * 256 + tid];
            float x3 = src[(size_t)(d + 3) * 256 + tid];
            s0 = fmaf(x0, x0, s0); s1 = fmaf(x1, x1, s1);
            s2 = fmaf(x2, x2, s2); s3 = fmaf(x3, x3, s3);
        }
        invn[tid] = 1.0f / fmaxf(sqrtf((s0 + s1) + (s2 + s3)), 1e-12f);
        __syncthreads();
        for (int j = 0; j < 32; j++) {
            int d = wid * 32 + j;
            const float* row = src + (size_t)d * 256;
            float a = 0.f;
            #pragma unroll
            for (int q = 0; q < 8; q++) {
                int p = lane + 32 * q;
                a = fmaf(row[p], invn[p], a);
            }
            #pragma unroll
            for (int o = 16; o > 0; o >>= 1) a += __shfl_xor_sync(0xffffffffu, a, o);
            if (lane == 0) g_vns[(size_t)bm * 256 + d] = a;
        }
    }
}

// ============ PHASE 2: column stats + sd + alpha-numerator ===================
__global__ void __launch_bounds__(256) k_colstats() {
    const int t = blockIdx.x, b = blockIdx.y, seg = t / 15;
    const int tid = threadIdx.x, lane = tid & 31, w = tid >> 5;
    float* col = g_sT + ((size_t)b * 75 + t) * 2048;
    __shared__ float smx[8];
    __shared__ float ssm[8];
    __shared__ float sm9[72];

    float vals[8];
    #pragma unroll
    for (int k = 0; k < 8; k++) vals[k] = col[tid + 256 * k];

    float mx = vals[0];
    #pragma unroll
    for (int k = 1; k < 8; k++) mx = fmaxf(mx, vals[k]);
    #pragma unroll
    for (int o = 16; o > 0; o >>= 1) mx = fmaxf(mx, __shfl_xor_sync(0xffffffffu, mx, o));
    if (lane == 0) smx[w] = mx;
    __syncthreads();
    float cmax = smx[0];
    #pragma unroll
    for (int q = 1; q < 8; q++) cmax = fmaxf(cmax, smx[q]);

    float e1[8];
    float sraw = 0.f, snt = 0.f;
    const float* rsb = g_rowstats + (size_t)b * 2048 * 10;
    #pragma unroll
    for (int k = 0; k < 8; k++) {
        int r = tid + 256 * k;
        e1[k] = __expf(vals[k] - cmax);
        sraw += e1[k];
        float2 rs = *(const float2*)(rsb + ((size_t)r * 5 + seg) * 2);
        float al = __expf(G1 * __expf(vals[k] - rs.x) * rs.y);
        snt += al;
        col[r] = al;
    }

    float sr = sraw;
    #pragma unroll
    for (int o = 16; o > 0; o >>= 1) sr += __shfl_xor_sync(0xffffffffu, sr, o);
    if (lane == 0) ssm[w] = sr;
    __syncthreads();
    float tot = 0.f;
    #pragma unroll
    for (int q = 0; q < 8; q++) tot += ssm[q];
    const float cinv = 1.0f / tot;

    float vred[9];
    vred[0] = snt;
    #pragma unroll
    for (int k = 0; k < 8; k++) vred[1 + k] = __expf(e1[k] * cinv);
    #pragma unroll
    for (int j = 0; j < 9; j++) {
        float v = vred[j];
        #pragma unroll
        for (int o = 16; o > 0; o >>= 1) v += __shfl_xor_sync(0xffffffffu, v, o);
        if (lane == 0) sm9[w * 9 + j] = v;
    }
    __syncthreads();
    if (tid < 9) {
        float s = 0.f;
        #pragma unroll
        for (int q = 0; q < 8; q++) s += sm9[q * 9 + tid];
        if (tid == 0) g_cinv_nt[b * 75 + t] = 1.0f / s;
        else g_sd[((size_t)b * 8 + (tid - 1)) * 75 + t] = s;
    }
}

// ============ PHASE 3: mma v_tidal (160 blocks, split-K=4) ===================
__global__ void __launch_bounds__(256) k_vtidal(const float* __restrict__ image) {
    extern __shared__ __align__(16) char dsm[];
    __shared__ float scv[80];
    const int tid = threadIdx.x;
    const int wid = tid >> 5, lane = tid & 31;
    const int b = blockIdx.x >> 2;
    const int kz = blockIdx.x & 3;
    const int gid = lane >> 2, tig = lane & 3;
    uint32_t* AH = (uint32_t*)dsm;
    uint32_t* AL = (uint32_t*)(dsm + P3_AL);
    uint32_t* BH = (uint32_t*)(dsm + P3_BH);
    uint32_t* BL = (uint32_t*)(dsm + P3_BL);
    const float* sTb = g_sT + (size_t)b * 75 * 2048;

    if (tid < 75) scv[tid] = g_cinv_nt[b * 75 + tid];
    for (int i = tid; i < 100; i += 256) {
        AH[75 * 20 + i] = 0; AL[75 * 20 + i] = 0;
    }
    __syncthreads();

    float acc[5][4][4];
    #pragma unroll
    for (int mt = 0; mt < 5; mt++)
        #pragma unroll
        for (int nt = 0; nt < 4; nt++)
            #pragma unroll
            for (int q = 0; q < 4; q++) acc[mt][nt][q] = 0.f;

    const int n0 = wid * 32;

    for (int c16 = 0; c16 < 16; c16++) {
        const int rg = kz * 512 + c16 * 32;
        const int m = rg >> 8, p0 = rg & 255;
        // ---- A: alpha rows [t][r-chunk] -------------------------------
        for (int idx = tid; idx < 600; idx += 256) {
            int t = idx >> 3, c4 = (idx & 7) * 4;
            float ci = scv[t];
            float4 v = *(const float4*)(sTb + (size_t)t * 2048 + rg + c4);
            uint32_t h0, l0, h1, l1;
            bsplit2(v.x * ci, v.y * ci, h0, l0);
            bsplit2(v.z * ci, v.w * ci, h1, l1);
            int w0 = t * 20 + (c4 >> 1);
            AH[w0] = h0; AH[w0 + 1] = h1;
            AL[w0] = l0; AL[w0 + 1] = l1;
        }
        // ---- B: image d-rows [d][r-chunk], natively k-contig -----------
        {
            const float* src = image + (size_t)(b * 8 + m) * 65536 + p0;
            #pragma unroll
            for (int it = 0; it < 8; it++) {
                int idx = tid + it * 256;
                int d = idx >> 3, c4 = (idx & 7) * 4;
                float4 v = *(const float4*)(src + (size_t)d * 256 + c4);
                uint32_t h0, l0, h1, l1;
                bsplit2(v.x, v.y, h0, l0);
                bsplit2(v.z, v.w, h1, l1);
                int w0 = d * 20 + (c4 >> 1);
                BH[w0] = h0; BH[w0 + 1] = h1;
                BL[w0] = l0; BL[w0 + 1] = l1;
            }
        }
        __syncthreads();
        #pragma unroll
        for (int ks = 0; ks < 2; ks++) {
            const int ko = ks * 8 + tig;
            uint32_t bh[4][2], bl[4][2];
            #pragma unroll
            for (int nt = 0; nt < 4; nt++) {
                int nb = (n0 + nt * 8 + gid) * 20 + ko;
                bh[nt][0] = BH[nb]; bh[nt][1] = BH[nb + 4];
                bl[nt][0] = BL[nb]; bl[nt][1] = BL[nb + 4];
            }
            #pragma unroll
            for (int mt = 0; mt < 5; mt++) {
                int ra = mt * 16 + gid;
                uint32_t ah0 = AH[ra * 20 + ko],     ah1 = AH[(ra + 8) * 20 + ko];
                uint32_t ah2 = AH[ra * 20 + ko + 4], ah3 = AH[(ra + 8) * 20 + ko + 4];
                uint32_t al0 = AL[ra * 20 + ko],     al1 = AL[(ra + 8) * 20 + ko];
                uint32_t al2 = AL[ra * 20 + ko + 4], al3 = AL[(ra + 8) * 20 + ko + 4];
                #pragma unroll
                for (int nt = 0; nt < 4; nt++) {
                    mma_bf16(acc[mt][nt], ah0, ah1, ah2, ah3, bh[nt][0], bh[nt][1]);
                    mma_bf16(acc[mt][nt], ah0, ah1, ah2, ah3, bl[nt][0], bl[nt][1]);
                    mma_bf16(acc[mt][nt], al0, al1, al2, al3, bh[nt][0], bh[nt][1]);
                }
            }
        }
        __syncthreads();
    }
    // ---- epilogue: write split-K partials ---------------------------------
    float* outp = g_vtp + (size_t)kz * 40 * 75 * 256 + (size_t)b * 75 * 256;
    #pragma unroll
    for (int mt = 0; mt < 5; mt++) {
        int t = mt * 16 + gid;
        #pragma unroll
        for (int nt = 0; nt < 4; nt++) {
            int d = n0 + nt * 8 + tig * 2;
            if (t < 75) {
                float2 v0 = {acc[mt][nt][0], acc[mt][nt][1]};
                *(float2*)(outp + (size_t)t * 256 + d) = v0;
            }
            if (t + 8 < 75) {
                float2 v1 = {acc[mt][nt][2], acc[mt][nt][3]};
                *(float2*)(outp + (size_t)(t + 8) * 256 + d) = v1;
            }
        }
    }
}

// ============ PHASE 4: tail = logit2 (320) + reg (40) + score1 (375) ========
__global__ void __launch_bounds__(256) k_tail(const float* __restrict__ text) {
    __shared__ __align__(16) float pool[1500];
    const int bx = blockIdx.x;
    const int tid = threadIdx.x;

    if (bx < 320) {
        const int b = bx >> 3, m = bx & 7, blk = b / 5;
        float* shsd = pool;
        float* red = pool + 16;
        const float vv = g_vns[((size_t)b * 8 + m) * 256 + tid];
        for (int sb = 0; sb < 5; sb++) {
            if (tid < 15) shsd[tid] = g_sd[((size_t)b * 8 + m) * 75 + sb * 15 + tid];
            __syncthreads();
            float segsum = 0.f;
            #pragma unroll
            for (int l = 0; l < 15; l++) segsum += shsd[l];
            float em = 0.f;
            #pragma unroll
            for (int l = 0; l < 15; l++)
                em = fmaf(shsd[l], text[((size_t)blk * 75 + sb * 15 + l) * 256 + tid], em);
            em /= segsum;
            red[tid] = em * em; __syncthreads();
            for (int o = 128; o > 0; o >>= 1) { if (tid < o) red[tid] += red[tid + o]; __syncthreads(); }
            const float nrm = fmaxf(sqrtf(red[0]), 1e-12f);
            __syncthreads();
            red[tid] = (em / nrm) * vv; __syncthreads();
            for (int o = 128; o > 0; o >>= 1) { if (tid < o) red[tid] += red[tid + o]; __syncthreads(); }
            if (tid == 0) g_logit2[((size_t)b * 8 + m) * 5 + sb] = red[0] / 256.0f;
            __syncthreads();
        }
    } else if (bx < 360) {
        const int b = bx - 320;
        float* ssd   = pool;
        float* sseg  = pool + 600;
        float* sbeta = pool + 640;
        float* red   = pool + 1240;
        for (int i = tid; i < 600; i += 256) ssd[i] = g_sd[(size_t)b * 600 + i];
        __syncthreads();
        if (tid < 40) {
            int m = tid / 5, sb2 = tid % 5;
            float s = 0.f;
            for (int l = 0; l < 15; l++) s += ssd[m * 75 + sb2 * 15 + l];
            sseg[tid] = s;
        }
        __syncthreads();
        for (int i = tid; i < 600; i += 256) {
            int m = i / 75, t = i % 75;
            sbeta[i] = ssd[i] / sseg[m * 5 + t / 15];
        }
        __syncthreads();
        float p = 0.f;
        if (tid < 64) {
            int m = tid >> 3, n = tid & 7;
            if (m != n) {
                float a = 0.f;
                for (int t = 0; t < 75; t++) a = fmaf(sbeta[m * 75 + t], sbeta[n * 75 + t], a);
                p = a * a;
            }
        }
        red[tid] = p; __syncthreads();
        for (int o = 128; o > 0; o >>= 1) { if (tid < o) red[tid] += red[tid + o]; __syncthreads(); }
        if (tid == 0) g_regval[b] = sqrtf(red[0]);
    } else {
        // score1: one warp per (b,t)
        const int gt = (bx - 360) * 8 + (tid >> 5);
        if (gt < 3000) {
            const int b = gt / 75, t = gt % 75, blk = b / 5;
            const int lane = tid & 31;
            const size_t SL = (size_t)40 * 75 * 256;
            const size_t voff = ((size_t)b * 75 + t) * 256;
            const float* e = text + ((size_t)blk * 75 + t) * 256;
            float dot = 0.f, nv = 0.f, ne = 0.f;
            #pragma unroll
            for (int j = 0; j < 8; j++) {
                int d = lane + 32 * j;
                float a = g_vtp[voff + d] + g_vtp[SL + voff + d]
                        + g_vtp[2 * SL + voff + d] + g_vtp[3 * SL + voff + d];
                float cc = e[d];
                dot = fmaf(a, cc, dot); nv = fmaf(a, a, nv); ne = fmaf(cc, cc, ne);
            }
            #pragma unroll
            for (int o = 16; o > 0; o >>= 1) {
                dot += __shfl_xor_sync(0xffffffffu, dot, o);
                nv  += __shfl_xor_sync(0xffffffffu, nv,  o);
                ne  += __shfl_xor_sync(0xffffffffu, ne,  o);
            }
            if (lane == 0)
                g_el[b * 75 + t] = __expf(dot / (fmaxf(sqrtf(nv), 1e-12f) * fmaxf(sqrtf(ne), 1e-12f)));
        }
    }
}

// ============ PHASE 5: final scalar =========================================
__global__ void k_final(float* __restrict__ out) {
    const int tid = threadIdx.x;
    __shared__ float lsm[200];
    __shared__ float bscore[8];
    if (tid < 200) {
        int blk = tid / 25, rem = tid % 25, i = rem / 5, sb = rem % 5;
        int gi = blk * 5 + i;
        float s2 = 0.f;
        #pragma unroll
        for (int m = 0; m < 8; m++) s2 += __expf(g_logit2[((size_t)gi * 8 + m) * 5 + sb]);
        float s1 = 0.f;
        #pragma unroll
        for (int l = 0; l < 15; l++) s1 += g_el[gi * 75 + sb * 15 + l];
        float l1 = __logf(__powf(s1, 0.2f) + EPSL);
        float l2 = __logf(__powf(s2, 0.2f) + EPSL);
        lsm[tid] = 10.0f * (l1 + l2);
    }
    __syncthreads();
    if (tid < 8) {
        const float* L = lsm + tid * 25;
        float rows[5] = {0, 0, 0, 0, 0}, cols[5] = {0, 0, 0, 0, 0};
        for (int i = 0; i < 5; i++)
            for (int sb = 0; sb < 5; sb++) {
                rows[i] += L[i * 5 + sb];
                cols[sb] += L[i * 5 + sb];
            }
        float acc = 0.f;
        for (int i = 0; i < 5; i++) {
            float dg = L[i * 5 + i];
            acc += -__logf(dg / rows[i] + EPSL) - __logf(dg / cols[i] + EPSL);
        }
        float reg = 0.f;
        for (int i = 0; i < 5; i++) reg += g_regval[tid * 5 + i];
        bscore[tid] = acc / 5.0f + reg / 5.0f;
    }
    __syncthreads();
    if (tid == 0) {
        float tot = 0.f;
        for (int k = 0; k < 8; k++) tot += bscore[k];
        out[0] = tot / 9.0f;
    }
}

// ---------------- launch -----------------------------------------------------
extern "C" void kernel_launch(void* const* d_in, const int* in_sizes, int n_in,
                              void* d_out, int out_size) {
    (void)in_sizes; (void)n_in; (void)out_size;
    const float* image = (const float*)d_in[0];
    const float* text  = (const float*)d_in[1];
    float* out = (float*)d_out;

    cudaFuncSetAttribute(k_phase1, cudaFuncAttributeMaxDynamicSharedMemorySize, P1_SZ);
    cudaFuncSetAttribute(k_vtidal, cudaFuncAttributeMaxDynamicSharedMemorySize, P3_SZ);

    k_phase1<<<960, 256, P1_SZ>>>(image, text);
    k_colstats<<<dim3(75, 40), 256>>>();
    k_vtidal<<<160, 256, P3_SZ>>>(image);
    k_tail<<<735, 256>>>(text);
    k_final<<<1, 256>>>(out);
}

// round 6
// speedup vs baseline: 1.8165x; 1.0263x over previous
#include <cuda_runtime.h>
#include <cuda_bf16.h>
#include <math.h>
#include <stdint.h>

#define G1 4.0f
#define EPSL 1e-10f

// ---------------- scratch (device globals) ----------------------------------
__device__ float    g_sT[40u*75u*2048u];      // [b][t][r]: s scores
__device__ float    g_rowstats[40u*2048u*5u*2u];
__device__ float    g_cinv_nt[40*75];
__device__ float    g_sd[40*8*75];
__device__ uint32_t g_aH[40u*75u*1024u];      // alpha numerators, bf16-hi pairs
__device__ uint32_t g_aL[40u*75u*1024u];      // alpha numerators, bf16-lo pairs
__device__ uint32_t g_eh[8*75*128];           // text bf16-hi pairs
__device__ uint32_t g_el2[8*75*128];          // text bf16-lo pairs
__device__ float    g_vtp[8u*40u*75u*256u];   // split-K partials of v_tidal
__device__ float    g_vns[40*8*256];
__device__ float    g_el[40*75];
__device__ float    g_logit2[40*8*5];
__device__ float    g_regval[40];

// ---------------- helpers ----------------------------------------------------
__device__ __forceinline__ void mma_bf16(float* c, uint32_t a0, uint32_t a1,
                                         uint32_t a2, uint32_t a3,
                                         uint32_t b0, uint32_t b1) {
    asm volatile(
        "mma.sync.aligned.m16n8k16.row.col.f32.bf16.bf16.f32 "
        "{%0,%1,%2,%3}, {%4,%5,%6,%7}, {%8,%9}, {%0,%1,%2,%3};"
        : "+f"(c[0]), "+f"(c[1]), "+f"(c[2]), "+f"(c[3])
        : "r"(a0), "r"(a1), "r"(a2), "r"(a3), "r"(b0), "r"(b1));
}
// fast split: x,y -> packed bf16 hi (x low half) + packed bf16 lo residual
__device__ __forceinline__ void bsplit2(float x, float y, uint32_t& hi, uint32_t& lo) {
    uint32_t h;
    asm("cvt.rn.bf16x2.f32 %0, %1, %2;" : "=r"(h) : "f"(y), "f"(x));
    float hx = __uint_as_float(h << 16);
    float hy = __uint_as_float(h & 0xFFFF0000u);
    float lx = x - hx, ly = y - hy;
    asm("cvt.rn.bf16x2.f32 %0, %1, %2;" : "=r"(lo) : "f"(ly), "f"(lx));
    hi = h;
}

// phase1 smem layout (bytes): TR fp32[32][132] | AH u32[128][20] | AL | BH u32[80][20] | BL
#define P1_AH 16896
#define P1_AL 27136
#define P1_BH 37376
#define P1_BL 43776
#define P1_SZ 50176
// vtidal smem layout: AH u32[80][20] | AL | BH u32[256][20] | BL
#define P3_AL 6400
#define P3_BH 12800
#define P3_BL 33280
#define P3_SZ 53760

// ============ PHASE 0: convert text to bf16 hi/lo pairs =====================
__global__ void __launch_bounds__(256) k_prep(const float* __restrict__ text) {
    int i = blockIdx.x * 256 + threadIdx.x;   // 76800 pairs
    float2 v = *(const float2*)(text + 2 * i);
    uint32_t h, l;
    bsplit2(v.x, v.y, h, l);
    g_eh[i] = h; g_el2[i] = l;
}

// ============ PHASE 1: mma gemm_s (640 blks) + vns (320) ====================
__global__ void __launch_bounds__(256) k_phase1(const float* __restrict__ image,
                                                const float* __restrict__ text) {
    extern __shared__ __align__(16) char dsm[];
    const int bx = blockIdx.x;
    const int tid = threadIdx.x;
    const int wid = tid >> 5, lane = tid & 31;

    if (bx < 640) {
        const int b  = bx >> 4;
        const int rb = bx & 15;
        const int r0 = rb * 128;
        const int m  = rb >> 1, p0 = (rb & 1) * 128;
        const float* srcA = image + (size_t)(b * 8 + m) * 65536;
        const uint32_t* eH = g_eh  + (size_t)(b / 5) * 9600;
        const uint32_t* eL = g_el2 + (size_t)(b / 5) * 9600;
        float* TR = (float*)dsm;
        uint32_t* AH = (uint32_t*)(dsm + P1_AH);
        uint32_t* AL = (uint32_t*)(dsm + P1_AL);
        uint32_t* BH = (uint32_t*)(dsm + P1_BH);
        uint32_t* BL = (uint32_t*)(dsm + P1_BL);
        const int gid = lane >> 2, tig = lane & 3;

        // zero B rows 75..79 once
        for (int i = tid; i < 100; i += 256) {
            BH[75 * 20 + i] = 0; BL[75 * 20 + i] = 0;
        }

        float acc[10][4];
        #pragma unroll
        for (int nt = 0; nt < 10; nt++)
            #pragma unroll
            for (int q = 0; q < 4; q++) acc[nt][q] = 0.f;

        for (int c8 = 0; c8 < 8; c8++) {
            const int kb = c8 * 32;
            // ---- stage A fp32 transpose buffer: TR[k][p] -----------------
            #pragma unroll
            for (int it = 0; it < 4; it++) {
                int lin = tid + it * 256;
                int k = lin >> 5, f4 = (lin & 31) * 4;
                float4 v = *(const float4*)(srcA + (size_t)(kb + k) * 256 + p0 + f4);
                *(float4*)(TR + k * 132 + f4) = v;
            }
            // ---- stage B: direct copy of prepped bf16 text ----------------
            for (int idx = tid; idx < 1200; idx += 256) {
                int t = idx >> 4, c = idx & 15;
                int gi = t * 128 + (kb >> 1) + c;
                BH[t * 20 + c] = eH[gi];
                BL[t * 20 + c] = eL[gi];
            }
            __syncthreads();
            // ---- convert A: [r][k] bf16 hi/lo ----------------------------
            {
                const int r = tid >> 1, kh = (tid & 1) * 16;
                #pragma unroll
                for (int j = 0; j < 16; j += 2) {
                    float x0 = TR[(kh + j) * 132 + r];
                    float x1 = TR[(kh + j + 1) * 132 + r];
                    uint32_t hi, lo;
                    bsplit2(x0, x1, hi, lo);
                    int w0 = r * 20 + ((kh + j) >> 1);
                    AH[w0] = hi; AL[w0] = lo;
                }
            }
            __syncthreads();
            // ---- mma ------------------------------------------------------
            const int rA = wid * 16 + gid;
            #pragma unroll
            for (int ks = 0; ks < 2; ks++) {
                const int ko = ks * 8 + tig;
                uint32_t ah0 = AH[rA * 20 + ko],       ah1 = AH[(rA + 8) * 20 + ko];
                uint32_t ah2 = AH[rA * 20 + ko + 4],   ah3 = AH[(rA + 8) * 20 + ko + 4];
                uint32_t al0 = AL[rA * 20 + ko],       al1 = AL[(rA + 8) * 20 + ko];
                uint32_t al2 = AL[rA * 20 + ko + 4],   al3 = AL[(rA + 8) * 20 + ko + 4];
                #pragma unroll
                for (int nt = 0; nt < 10; nt++) {
                    int nb = (nt * 8 + gid) * 20 + ko;
                    uint32_t bh0 = BH[nb], bh1 = BH[nb + 4];
                    uint32_t bl0 = BL[nb], bl1 = BL[nb + 4];
                    mma_bf16(acc[nt], ah0, ah1, ah2, ah3, bh0, bh1);
                    mma_bf16(acc[nt], ah0, ah1, ah2, ah3, bl0, bl1);
                    mma_bf16(acc[nt], al0, al1, al2, al3, bh0, bh1);
                }
            }
            __syncthreads();
        }
        // ---- epilogue: stage C to sc[t][132 r] --------------------------
        float* sc = (float*)dsm;
        const int rA = wid * 16 + gid;
        #pragma unroll
        for (int nt = 0; nt < 10; nt++) {
            int t0 = nt * 8 + tig * 2;
            sc[t0 * 132 + rA]           = acc[nt][0];
            sc[(t0 + 1) * 132 + rA]     = acc[nt][1];
            sc[t0 * 132 + rA + 8]       = acc[nt][2];
            sc[(t0 + 1) * 132 + rA + 8] = acc[nt][3];
        }
        __syncthreads();
        if (tid < 128) {
            const int r = tid;
            #pragma unroll
            for (int seg = 0; seg < 5; seg++) {
                float mx = -3.4e38f;
                #pragma unroll
                for (int l = 0; l < 15; l++)
                    mx = fmaxf(mx, sc[(seg * 15 + l) * 132 + r]);
                float se = 0.f;
                #pragma unroll
                for (int l = 0; l < 15; l++)
                    se += __expf(sc[(seg * 15 + l) * 132 + r] - mx);
                size_t ridx = ((size_t)b * 2048 + r0 + r) * 5 + seg;
                g_rowstats[ridx * 2]     = mx;
                g_rowstats[ridx * 2 + 1] = 1.0f / se;
            }
        }
        for (int i = tid; i < 9600; i += 256) {
            int t = i >> 7, r = i & 127;
            g_sT[((size_t)b * 75 + t) * 2048 + r0 + r] = sc[t * 132 + r];
        }
    } else {
        // -------- vns from image directly ------------------------------------
        const int bm = bx - 640;
        const float* src = image + (size_t)bm * 65536;
        float* invn = (float*)dsm;
        float s0 = 0.f, s1 = 0.f, s2 = 0.f, s3 = 0.f;
        for (int d = 0; d < 256; d += 4) {
            float x0 = src[(size_t)(d + 0) * 256 + tid];
            float x1 = src[(size_t)(d + 1) * 256 + tid];
            float x2 = src[(size_t)(d + 2) * 256 + tid];
            float x3 = src[(size_t)(d + 3) * 256 + tid];
            s0 = fmaf(x0, x0, s0); s1 = fmaf(x1, x1, s1);
            s2 = fmaf(x2, x2, s2); s3 = fmaf(x3, x3, s3);
        }
        invn[tid] = 1.0f / fmaxf(sqrtf((s0 + s1) + (s2 + s3)), 1e-12f);
        __syncthreads();
        for (int j = 0; j < 32; j++) {
            int d = wid * 32 + j;
            const float* row = src + (size_t)d * 256;
            float a = 0.f;
            #pragma unroll
            for (int q = 0; q < 8; q++) {
                int p = lane + 32 * q;
                a = fmaf(row[p], invn[p], a);
            }
            #pragma unroll
            for (int o = 16; o > 0; o >>= 1) a += __shfl_xor_sync(0xffffffffu, a, o);
            if (lane == 0) g_vns[(size_t)bm * 256 + d] = a;
        }
    }
}

// ============ PHASE 2: column stats + sd + packed bf16 alpha =================
__global__ void __launch_bounds__(256) k_colstats() {
    const int t = blockIdx.x, b = blockIdx.y, seg = t / 15;
    const int tid = threadIdx.x, lane = tid & 31, w = tid >> 5;
    const float* col = g_sT + ((size_t)b * 75 + t) * 2048;
    __shared__ float sred[24];   // [0,8): max, [8,16): sraw, [16,24): snt

    float vals[8];
    *(float4*)vals       = *(const float4*)(col + tid * 8);
    *(float4*)(vals + 4) = *(const float4*)(col + tid * 8 + 4);

    float mx = vals[0];
    #pragma unroll
    for (int k = 1; k < 8; k++) mx = fmaxf(mx, vals[k]);
    #pragma unroll
    for (int o = 16; o > 0; o >>= 1) mx = fmaxf(mx, __shfl_xor_sync(0xffffffffu, mx, o));
    if (lane == 0) sred[w] = mx;
    __syncthreads();
    float cmax = sred[0];
    #pragma unroll
    for (int q = 1; q < 8; q++) cmax = fmaxf(cmax, sred[q]);

    float e1[8], al[8];
    float sraw = 0.f, snt = 0.f;
    const float* rsb = g_rowstats + (((size_t)b * 2048 + tid * 8) * 5 + seg) * 2;
    #pragma unroll
    for (int k = 0; k < 8; k++) {
        e1[k] = __expf(vals[k] - cmax);
        sraw += e1[k];
        float2 rs = *(const float2*)(rsb + k * 10);
        al[k] = __expf(G1 * __expf(vals[k] - rs.x) * rs.y);
        snt += al[k];
    }
    // write packed bf16 hi/lo alpha-numerators
    {
        uint32_t* aH = g_aH + (size_t)b * 76800 + t * 1024 + tid * 4;
        uint32_t* aL = g_aL + (size_t)b * 76800 + t * 1024 + tid * 4;
        #pragma unroll
        for (int j = 0; j < 4; j++) {
            uint32_t h, l;
            bsplit2(al[2 * j], al[2 * j + 1], h, l);
            aH[j] = h; aL[j] = l;
        }
    }
    float sr = sraw, sn = snt;
    #pragma unroll
    for (int o = 16; o > 0; o >>= 1) {
        sr += __shfl_xor_sync(0xffffffffu, sr, o);
        sn += __shfl_xor_sync(0xffffffffu, sn, o);
    }
    if (lane == 0) { sred[8 + w] = sr; sred[16 + w] = sn; }
    __syncthreads();
    float tot = 0.f;
    #pragma unroll
    for (int q = 0; q < 8; q++) tot += sred[8 + q];
    const float cinv = 1.0f / tot;
    if (tid == 0) {
        float s = 0.f;
        #pragma unroll
        for (int q = 0; q < 8; q++) s += sred[16 + q];
        g_cinv_nt[b * 75 + t] = 1.0f / s;
    }
    // sd: warp w owns m = w (r = tid*8+k in [256w, 256w+256))
    float e2 = 0.f;
    #pragma unroll
    for (int k = 0; k < 8; k++) e2 += __expf(e1[k] * cinv);
    #pragma unroll
    for (int o = 16; o > 0; o >>= 1) e2 += __shfl_xor_sync(0xffffffffu, e2, o);
    if (lane == 0) g_sd[((size_t)b * 8 + w) * 75 + t] = e2;
}

// ============ PHASE 3: mma v_tidal (320 blocks, split-K=8) ===================
__global__ void __launch_bounds__(256) k_vtidal(const float* __restrict__ image) {
    extern __shared__ __align__(16) char dsm[];
    __shared__ float scv[80];
    const int tid = threadIdx.x;
    const int wid = tid >> 5, lane = tid & 31;
    const int b = blockIdx.x >> 3;
    const int kz = blockIdx.x & 7;
    const int gid = lane >> 2, tig = lane & 3;
    uint32_t* AH = (uint32_t*)dsm;
    uint32_t* AL = (uint32_t*)(dsm + P3_AL);
    uint32_t* BH = (uint32_t*)(dsm + P3_BH);
    uint32_t* BL = (uint32_t*)(dsm + P3_BL);
    const uint32_t* aHg = g_aH + (size_t)b * 76800;
    const uint32_t* aLg = g_aL + (size_t)b * 76800;

    if (tid < 75) scv[tid] = g_cinv_nt[b * 75 + tid];
    for (int i = tid; i < 100; i += 256) {
        AH[75 * 20 + i] = 0; AL[75 * 20 + i] = 0;
    }
    __syncthreads();

    float acc[5][4][4];
    #pragma unroll
    for (int mt = 0; mt < 5; mt++)
        #pragma unroll
        for (int nt = 0; nt < 4; nt++)
            #pragma unroll
            for (int q = 0; q < 4; q++) acc[mt][nt][q] = 0.f;

    const int n0 = wid * 32;
    const float* srcB = image + (size_t)(b * 8 + kz) * 65536;

    for (int c8 = 0; c8 < 8; c8++) {
        const int rg = kz * 256 + c8 * 32;
        const int p0 = c8 * 32;
        // ---- A: direct copy of prepped bf16 alpha-numerators --------------
        for (int idx = tid; idx < 1200; idx += 256) {
            int t = idx >> 4, c = idx & 15;
            int gi = t * 1024 + (rg >> 1) + c;
            AH[t * 20 + c] = aHg[gi];
            AL[t * 20 + c] = aLg[gi];
        }
        // ---- B: image d-rows [d][p-chunk], natively k-contig ---------------
        #pragma unroll
        for (int it = 0; it < 8; it++) {
            int idx = tid + it * 256;
            int d = idx >> 3, c4 = (idx & 7) * 4;
            float4 v = *(const float4*)(srcB + (size_t)d * 256 + p0 + c4);
            uint32_t h0, l0, h1, l1;
            bsplit2(v.x, v.y, h0, l0);
            bsplit2(v.z, v.w, h1, l1);
            int w0 = d * 20 + (c4 >> 1);
            BH[w0] = h0; BH[w0 + 1] = h1;
            BL[w0] = l0; BL[w0 + 1] = l1;
        }
        __syncthreads();
        #pragma unroll
        for (int ks = 0; ks < 2; ks++) {
            const int ko = ks * 8 + tig;
            uint32_t bh[4][2], bl[4][2];
            #pragma unroll
            for (int nt = 0; nt < 4; nt++) {
                int nb = (n0 + nt * 8 + gid) * 20 + ko;
                bh[nt][0] = BH[nb]; bh[nt][1] = BH[nb + 4];
                bl[nt][0] = BL[nb]; bl[nt][1] = BL[nb + 4];
            }
            #pragma unroll
            for (int mt = 0; mt < 5; mt++) {
                int ra = mt * 16 + gid;
                uint32_t ah0 = AH[ra * 20 + ko],     ah1 = AH[(ra + 8) * 20 + ko];
                uint32_t ah2 = AH[ra * 20 + ko + 4], ah3 = AH[(ra + 8) * 20 + ko + 4];
                uint32_t al0 = AL[ra * 20 + ko],     al1 = AL[(ra + 8) * 20 + ko];
                uint32_t al2 = AL[ra * 20 + ko + 4], al3 = AL[(ra + 8) * 20 + ko + 4];
                #pragma unroll
                for (int nt = 0; nt < 4; nt++) {
                    mma_bf16(acc[mt][nt], ah0, ah1, ah2, ah3, bh[nt][0], bh[nt][1]);
                    mma_bf16(acc[mt][nt], ah0, ah1, ah2, ah3, bl[nt][0], bl[nt][1]);
                    mma_bf16(acc[mt][nt], al0, al1, al2, al3, bh[nt][0], bh[nt][1]);
                }
            }
        }
        __syncthreads();
    }
    // ---- epilogue: scale by cinv[t], write split-K partials -----------------
    float* outp = g_vtp + (size_t)kz * 40 * 75 * 256 + (size_t)b * 75 * 256;
    #pragma unroll
    for (int mt = 0; mt < 5; mt++) {
        int t = mt * 16 + gid;
        #pragma unroll
        for (int nt = 0; nt < 4; nt++) {
            int d = n0 + nt * 8 + tig * 2;
            if (t < 75) {
                float ci = scv[t];
                float2 v0 = {acc[mt][nt][0] * ci, acc[mt][nt][1] * ci};
                *(float2*)(outp + (size_t)t * 256 + d) = v0;
            }
            if (t + 8 < 75) {
                float ci = scv[t + 8];
                float2 v1 = {acc[mt][nt][2] * ci, acc[mt][nt][3] * ci};
                *(float2*)(outp + (size_t)(t + 8) * 256 + d) = v1;
            }
        }
    }
}

// ============ PHASE 4: tail = logit2 (320) + reg (40) + score1 (375) ========
__global__ void __launch_bounds__(256) k_tail(const float* __restrict__ text) {
    __shared__ __align__(16) float pool[1500];
    const int bx = blockIdx.x;
    const int tid = threadIdx.x;
    const int lane = tid & 31, w = tid >> 5;

    if (bx < 320) {
        const int b = bx >> 3, m = bx & 7, blk = b / 5;
        float* shsd = pool;        // 16
        float* wred = pool + 16;   // 16
        const float vv = g_vns[((size_t)b * 8 + m) * 256 + tid];
        for (int sb = 0; sb < 5; sb++) {
            if (tid < 15) shsd[tid] = g_sd[((size_t)b * 8 + m) * 75 + sb * 15 + tid];
            __syncthreads();
            float segsum = 0.f;
            #pragma unroll
            for (int l = 0; l < 15; l++) segsum += shsd[l];
            float em = 0.f;
            #pragma unroll
            for (int l = 0; l < 15; l++)
                em = fmaf(shsd[l], text[((size_t)blk * 75 + sb * 15 + l) * 256 + tid], em);
            em /= segsum;
            float p = em * em, q = em * vv;
            #pragma unroll
            for (int o = 16; o > 0; o >>= 1) {
                p += __shfl_xor_sync(0xffffffffu, p, o);
                q += __shfl_xor_sync(0xffffffffu, q, o);
            }
            if (lane == 0) { wred[w] = p; wred[8 + w] = q; }
            __syncthreads();
            if (tid == 0) {
                float s1 = 0.f, s2 = 0.f;
                #pragma unroll
                for (int j = 0; j < 8; j++) { s1 += wred[j]; s2 += wred[8 + j]; }
                g_logit2[((size_t)b * 8 + m) * 5 + sb] =
                    s2 / (fmaxf(sqrtf(s1), 1e-12f) * 256.0f);
            }
            __syncthreads();
        }
    } else if (bx < 360) {
        const int b = bx - 320;
        float* ssd   = pool;
        float* sseg  = pool + 600;
        float* sbeta = pool + 640;
        float* red   = pool + 1240;
        for (int i = tid; i < 600; i += 256) ssd[i] = g_sd[(size_t)b * 600 + i];
        __syncthreads();
        if (tid < 40) {
            int m = tid / 5, sb2 = tid % 5;
            float s = 0.f;
            for (int l = 0; l < 15; l++) s += ssd[m * 75 + sb2 * 15 + l];
            sseg[tid] = s;
        }
        __syncthreads();
        for (int i = tid; i < 600; i += 256) {
            int m = i / 75, t = i % 75;
            sbeta[i] = ssd[i] / sseg[m * 5 + t / 15];
        }
        __syncthreads();
        float p = 0.f;
        if (tid < 64) {
            int m = tid >> 3, n = tid & 7;
            if (m != n) {
                float a = 0.f;
                for (int t = 0; t < 75; t++) a = fmaf(sbeta[m * 75 + t], sbeta[n * 75 + t], a);
                p = a * a;
            }
        }
        red[tid] = p; __syncthreads();
        for (int o = 128; o > 0; o >>= 1) { if (tid < o) red[tid] += red[tid + o]; __syncthreads(); }
        if (tid == 0) g_regval[b] = sqrtf(red[0]);
    } else {
        // score1: one warp per (b,t); sum 8 split-K partials
        const int gt = (bx - 360) * 8 + w;
        if (gt < 3000) {
            const int b = gt / 75, t = gt % 75, blk = b / 5;
            const size_t SL = (size_t)40 * 75 * 256;
            const size_t voff = ((size_t)b * 75 + t) * 256;
            const float* e = text + ((size_t)blk * 75 + t) * 256;
            float dot = 0.f, nv = 0.f, ne = 0.f;
            #pragma unroll
            for (int j = 0; j < 8; j++) {
                int d = lane + 32 * j;
                float a = 0.f;
                #pragma unroll
                for (int s8 = 0; s8 < 8; s8++) a += g_vtp[s8 * SL + voff + d];
                float cc = e[d];
                dot = fmaf(a, cc, dot); nv = fmaf(a, a, nv); ne = fmaf(cc, cc, ne);
            }
            #pragma unroll
            for (int o = 16; o > 0; o >>= 1) {
                dot += __shfl_xor_sync(0xffffffffu, dot, o);
                nv  += __shfl_xor_sync(0xffffffffu, nv,  o);
                ne  += __shfl_xor_sync(0xffffffffu, ne,  o);
            }
            if (lane == 0)
                g_el[b * 75 + t] = __expf(dot / (fmaxf(sqrtf(nv), 1e-12f) * fmaxf(sqrtf(ne), 1e-12f)));
        }
    }
}

// ============ PHASE 5: final scalar =========================================
__global__ void k_final(float* __restrict__ out) {
    const int tid = threadIdx.x;
    __shared__ float lsm[200];
    __shared__ float bscore[8];
    if (tid < 200) {
        int blk = tid / 25, rem = tid % 25, i = rem / 5, sb = rem % 5;
        int gi = blk * 5 + i;
        float s2 = 0.f;
        #pragma unroll
        for (int m = 0; m < 8; m++) s2 += __expf(g_logit2[((size_t)gi * 8 + m) * 5 + sb]);
        float s1 = 0.f;
        #pragma unroll
        for (int l = 0; l < 15; l++) s1 += g_el[gi * 75 + sb * 15 + l];
        float l1 = __logf(__powf(s1, 0.2f) + EPSL);
        float l2 = __logf(__powf(s2, 0.2f) + EPSL);
        lsm[tid] = 10.0f * (l1 + l2);
    }
    __syncthreads();
    if (tid < 8) {
        const float* L = lsm + tid * 25;
        float rows[5] = {0, 0, 0, 0, 0}, cols[5] = {0, 0, 0, 0, 0};
        for (int i = 0; i < 5; i++)
            for (int sb = 0; sb < 5; sb++) {
                rows[i] += L[i * 5 + sb];
                cols[sb] += L[i * 5 + sb];
            }
        float acc = 0.f;
        for (int i = 0; i < 5; i++) {
            float dg = L[i * 5 + i];
            acc += -__logf(dg / rows[i] + EPSL) - __logf(dg / cols[i] + EPSL);
        }
        float reg = 0.f;
        for (int i = 0; i < 5; i++) reg += g_regval[tid * 5 + i];
        bscore[tid] = acc / 5.0f + reg / 5.0f;
    }
    __syncthreads();
    if (tid == 0) {
        float tot = 0.f;
        for (int k = 0; k < 8; k++) tot += bscore[k];
        out[0] = tot / 9.0f;
    }
}

// ---------------- launch -----------------------------------------------------
extern "C" void kernel_launch(void* const* d_in, const int* in_sizes, int n_in,
                              void* d_out, int out_size) {
    (void)in_sizes; (void)n_in; (void)out_size;
    const float* image = (const float*)d_in[0];
    const float* text  = (const float*)d_in[1];
    float* out = (float*)d_out;

    cudaFuncSetAttribute(k_phase1, cudaFuncAttributeMaxDynamicSharedMemorySize, P1_SZ);
    cudaFuncSetAttribute(k_vtidal, cudaFuncAttributeMaxDynamicSharedMemorySize, P3_SZ);

    k_prep<<<300, 256>>>(text);
    k_phase1<<<960, 256, P1_SZ>>>(image, text);
    k_colstats<<<dim3(75, 40), 256>>>();
    k_vtidal<<<320, 256, P3_SZ>>>(image);
    k_tail<<<735, 256>>>(text);
    k_final<<<1, 256>>>(out);
}

// round 7
// speedup vs baseline: 2.1340x; 1.1748x over previous
#include <cuda_runtime.h>
#include <cuda_bf16.h>
#include <math.h>
#include <stdint.h>

#define G1 4.0f
#define EPSL 1e-10f

// ---------------- scratch (device globals) ----------------------------------
__device__ float    g_sT[40u*75u*2048u];      // [b][t][r]: s scores
__device__ float    g_rowstats[40u*2048u*5u*2u];
__device__ float    g_cinv_nt[40*75];
__device__ float    g_sd[40*8*75];
__device__ uint32_t g_aH[40u*75u*1024u];      // alpha numerators, bf16-hi pairs
__device__ uint32_t g_aL[40u*75u*1024u];      // alpha numerators, bf16-lo pairs
__device__ uint32_t g_eh[8*75*128];           // text bf16-hi pairs
__device__ uint32_t g_el2[8*75*128];          // text bf16-lo pairs
__device__ float    g_vtp[8u*40u*75u*256u];   // split-K partials of v_tidal
__device__ float    g_vns[40*8*256];
__device__ float    g_el[40*75];
__device__ float    g_logit2[40*8*5];
__device__ float    g_regval[40];

// ---------------- helpers ----------------------------------------------------
__device__ __forceinline__ void mma_bf16(float* c, uint32_t a0, uint32_t a1,
                                         uint32_t a2, uint32_t a3,
                                         uint32_t b0, uint32_t b1) {
    asm volatile(
        "mma.sync.aligned.m16n8k16.row.col.f32.bf16.bf16.f32 "
        "{%0,%1,%2,%3}, {%4,%5,%6,%7}, {%8,%9}, {%0,%1,%2,%3};"
        : "+f"(c[0]), "+f"(c[1]), "+f"(c[2]), "+f"(c[3])
        : "r"(a0), "r"(a1), "r"(a2), "r"(a3), "r"(b0), "r"(b1));
}
// fast split: x,y -> packed bf16 hi + packed bf16 lo residual
__device__ __forceinline__ void bsplit2(float x, float y, uint32_t& hi, uint32_t& lo) {
    uint32_t h;
    asm("cvt.rn.bf16x2.f32 %0, %1, %2;" : "=r"(h) : "f"(y), "f"(x));
    float hx = __uint_as_float(h << 16);
    float hy = __uint_as_float(h & 0xFFFF0000u);
    float lx = x - hx, ly = y - hy;
    asm("cvt.rn.bf16x2.f32 %0, %1, %2;" : "=r"(lo) : "f"(ly), "f"(lx));
    hi = h;
}

// phase1 smem layout (bytes): TR fp32[32][132] | AH u32[128][20] | AL | BH u32[80][20] | BL
#define P1_AH 16896
#define P1_AL 27136
#define P1_BH 37376
#define P1_BL 43776
#define P1_SZ 50176
// vtidal smem layout (N=128 split): AH u32[80][20] | AL | BH u32[128][20] | BL
#define P3_AL 6400
#define P3_BH 12800
#define P3_BL 23040
#define P3_SZ 33280

// ============ PHASE 0: convert text to bf16 hi/lo pairs =====================
__global__ void __launch_bounds__(256) k_prep(const float* __restrict__ text) {
    int i = blockIdx.x * 256 + threadIdx.x;   // 76800 pairs
    float2 v = *(const float2*)(text + 2 * i);
    uint32_t h, l;
    bsplit2(v.x, v.y, h, l);
    g_eh[i] = h; g_el2[i] = l;
}

// ============ PHASE 1: mma gemm_s (640 blks) + vns (320) ====================
__global__ void __launch_bounds__(256) k_phase1(const float* __restrict__ image,
                                                const float* __restrict__ text) {
    extern __shared__ __align__(16) char dsm[];
    const int bx = blockIdx.x;
    const int tid = threadIdx.x;
    const int wid = tid >> 5, lane = tid & 31;

    if (bx < 640) {
        const int b  = bx >> 4;
        const int rb = bx & 15;
        const int r0 = rb * 128;
        const int m  = rb >> 1, p0 = (rb & 1) * 128;
        const float* srcA = image + (size_t)(b * 8 + m) * 65536;
        const uint32_t* eH = g_eh  + (size_t)(b / 5) * 9600;
        const uint32_t* eL = g_el2 + (size_t)(b / 5) * 9600;
        float* TR = (float*)dsm;
        uint32_t* AH = (uint32_t*)(dsm + P1_AH);
        uint32_t* AL = (uint32_t*)(dsm + P1_AL);
        uint32_t* BH = (uint32_t*)(dsm + P1_BH);
        uint32_t* BL = (uint32_t*)(dsm + P1_BL);
        const int gid = lane >> 2, tig = lane & 3;

        // zero B rows 75..79 once
        for (int i = tid; i < 100; i += 256) {
            BH[75 * 20 + i] = 0; BL[75 * 20 + i] = 0;
        }

        float acc[10][4];
        #pragma unroll
        for (int nt = 0; nt < 10; nt++)
            #pragma unroll
            for (int q = 0; q < 4; q++) acc[nt][q] = 0.f;

        for (int c8 = 0; c8 < 8; c8++) {
            const int kb = c8 * 32;
            // ---- stage A fp32 transpose buffer: TR[k][p] -----------------
            #pragma unroll
            for (int it = 0; it < 4; it++) {
                int lin = tid + it * 256;
                int k = lin >> 5, f4 = (lin & 31) * 4;
                float4 v = *(const float4*)(srcA + (size_t)(kb + k) * 256 + p0 + f4);
                *(float4*)(TR + k * 132 + f4) = v;
            }
            // ---- stage B: direct copy of prepped bf16 text ----------------
            for (int idx = tid; idx < 1200; idx += 256) {
                int t = idx >> 4, c = idx & 15;
                int gi = t * 128 + (kb >> 1) + c;
                BH[t * 20 + c] = eH[gi];
                BL[t * 20 + c] = eL[gi];
            }
            __syncthreads();
            // ---- convert A: [r][k] bf16 hi/lo ----------------------------
            {
                const int r = tid >> 1, kh = (tid & 1) * 16;
                #pragma unroll
                for (int j = 0; j < 16; j += 2) {
                    float x0 = TR[(kh + j) * 132 + r];
                    float x1 = TR[(kh + j + 1) * 132 + r];
                    uint32_t hi, lo;
                    bsplit2(x0, x1, hi, lo);
                    int w0 = r * 20 + ((kh + j) >> 1);
                    AH[w0] = hi; AL[w0] = lo;
                }
            }
            __syncthreads();
            // ---- mma ------------------------------------------------------
            const int rA = wid * 16 + gid;
            #pragma unroll
            for (int ks = 0; ks < 2; ks++) {
                const int ko = ks * 8 + tig;
                uint32_t ah0 = AH[rA * 20 + ko],       ah1 = AH[(rA + 8) * 20 + ko];
                uint32_t ah2 = AH[rA * 20 + ko + 4],   ah3 = AH[(rA + 8) * 20 + ko + 4];
                uint32_t al0 = AL[rA * 20 + ko],       al1 = AL[(rA + 8) * 20 + ko];
                uint32_t al2 = AL[rA * 20 + ko + 4],   al3 = AL[(rA + 8) * 20 + ko + 4];
                #pragma unroll
                for (int nt = 0; nt < 10; nt++) {
                    int nb = (nt * 8 + gid) * 20 + ko;
                    uint32_t bh0 = BH[nb], bh1 = BH[nb + 4];
                    uint32_t bl0 = BL[nb], bl1 = BL[nb + 4];
                    mma_bf16(acc[nt], ah0, ah1, ah2, ah3, bh0, bh1);
                    mma_bf16(acc[nt], ah0, ah1, ah2, ah3, bl0, bl1);
                    mma_bf16(acc[nt], al0, al1, al2, al3, bh0, bh1);
                }
            }
            __syncthreads();
        }
        // ---- epilogue: stage C to sc[t][132 r] --------------------------
        float* sc = (float*)dsm;
        const int rA = wid * 16 + gid;
        #pragma unroll
        for (int nt = 0; nt < 10; nt++) {
            int t0 = nt * 8 + tig * 2;
            sc[t0 * 132 + rA]           = acc[nt][0];
            sc[(t0 + 1) * 132 + rA]     = acc[nt][1];
            sc[t0 * 132 + rA + 8]       = acc[nt][2];
            sc[(t0 + 1) * 132 + rA + 8] = acc[nt][3];
        }
        __syncthreads();
        if (tid < 128) {
            const int r = tid;
            #pragma unroll
            for (int seg = 0; seg < 5; seg++) {
                float mx = -3.4e38f;
                #pragma unroll
                for (int l = 0; l < 15; l++)
                    mx = fmaxf(mx, sc[(seg * 15 + l) * 132 + r]);
                float se = 0.f;
                #pragma unroll
                for (int l = 0; l < 15; l++)
                    se += __expf(sc[(seg * 15 + l) * 132 + r] - mx);
                size_t ridx = ((size_t)b * 2048 + r0 + r) * 5 + seg;
                g_rowstats[ridx * 2]     = mx;
                g_rowstats[ridx * 2 + 1] = 1.0f / se;
            }
        }
        for (int i = tid; i < 9600; i += 256) {
            int t = i >> 7, r = i & 127;
            g_sT[((size_t)b * 75 + t) * 2048 + r0 + r] = sc[t * 132 + r];
        }
    } else {
        // -------- vns from image directly ------------------------------------
        const int bm = bx - 640;
        const float* src = image + (size_t)bm * 65536;
        float* invn = (float*)dsm;
        float s0 = 0.f, s1 = 0.f, s2 = 0.f, s3 = 0.f;
        for (int d = 0; d < 256; d += 4) {
            float x0 = src[(size_t)(d + 0) * 256 + tid];
            float x1 = src[(size_t)(d + 1) * 256 + tid];
            float x2 = src[(size_t)(d + 2) * 256 + tid];
            float x3 = src[(size_t)(d + 3) * 256 + tid];
            s0 = fmaf(x0, x0, s0); s1 = fmaf(x1, x1, s1);
            s2 = fmaf(x2, x2, s2); s3 = fmaf(x3, x3, s3);
        }
        invn[tid] = 1.0f / fmaxf(sqrtf((s0 + s1) + (s2 + s3)), 1e-12f);
        __syncthreads();
        for (int j = 0; j < 32; j++) {
            int d = wid * 32 + j;
            const float* row = src + (size_t)d * 256;
            float a = 0.f;
            #pragma unroll
            for (int q = 0; q < 8; q++) {
                int p = lane + 32 * q;
                a = fmaf(row[p], invn[p], a);
            }
            #pragma unroll
            for (int o = 16; o > 0; o >>= 1) a += __shfl_xor_sync(0xffffffffu, a, o);
            if (lane == 0) g_vns[(size_t)bm * 256 + d] = a;
        }
    }
}

// ============ PHASE 2: column stats + sd + packed bf16 alpha =================
__global__ void __launch_bounds__(256) k_colstats() {
    const int t = blockIdx.x, b = blockIdx.y, seg = t / 15;
    const int tid = threadIdx.x, lane = tid & 31, w = tid >> 5;
    const float* col = g_sT + ((size_t)b * 75 + t) * 2048;
    __shared__ float sred[24];

    float vals[8];
    *(float4*)vals       = *(const float4*)(col + tid * 8);
    *(float4*)(vals + 4) = *(const float4*)(col + tid * 8 + 4);

    float mx = vals[0];
    #pragma unroll
    for (int k = 1; k < 8; k++) mx = fmaxf(mx, vals[k]);
    #pragma unroll
    for (int o = 16; o > 0; o >>= 1) mx = fmaxf(mx, __shfl_xor_sync(0xffffffffu, mx, o));
    if (lane == 0) sred[w] = mx;
    __syncthreads();
    float cmax = sred[0];
    #pragma unroll
    for (int q = 1; q < 8; q++) cmax = fmaxf(cmax, sred[q]);

    float e1[8], al[8];
    float sraw = 0.f, snt = 0.f;
    const float* rsb = g_rowstats + (((size_t)b * 2048 + tid * 8) * 5 + seg) * 2;
    #pragma unroll
    for (int k = 0; k < 8; k++) {
        e1[k] = __expf(vals[k] - cmax);
        sraw += e1[k];
        float2 rs = *(const float2*)(rsb + k * 10);
        al[k] = __expf(G1 * __expf(vals[k] - rs.x) * rs.y);
        snt += al[k];
    }
    {
        uint32_t* aH = g_aH + (size_t)b * 76800 + t * 1024 + tid * 4;
        uint32_t* aL = g_aL + (size_t)b * 76800 + t * 1024 + tid * 4;
        #pragma unroll
        for (int j = 0; j < 4; j++) {
            uint32_t h, l;
            bsplit2(al[2 * j], al[2 * j + 1], h, l);
            aH[j] = h; aL[j] = l;
        }
    }
    float sr = sraw, sn = snt;
    #pragma unroll
    for (int o = 16; o > 0; o >>= 1) {
        sr += __shfl_xor_sync(0xffffffffu, sr, o);
        sn += __shfl_xor_sync(0xffffffffu, sn, o);
    }
    if (lane == 0) { sred[8 + w] = sr; sred[16 + w] = sn; }
    __syncthreads();
    float tot = 0.f;
    #pragma unroll
    for (int q = 0; q < 8; q++) tot += sred[8 + q];
    const float cinv = 1.0f / tot;
    if (tid == 0) {
        float s = 0.f;
        #pragma unroll
        for (int q = 0; q < 8; q++) s += sred[16 + q];
        g_cinv_nt[b * 75 + t] = 1.0f / s;
    }
    float e2 = 0.f;
    #pragma unroll
    for (int k = 0; k < 8; k++) e2 += __expf(e1[k] * cinv);
    #pragma unroll
    for (int o = 16; o > 0; o >>= 1) e2 += __shfl_xor_sync(0xffffffffu, e2, o);
    if (lane == 0) g_sd[((size_t)b * 8 + w) * 75 + t] = e2;
}

// ============ PHASE 3: mma v_tidal (640 blocks, split-K=8, N-split=2) ========
__global__ void __launch_bounds__(256) k_vtidal(const float* __restrict__ image) {
    extern __shared__ __align__(16) char dsm[];
    __shared__ float scv[80];
    const int tid = threadIdx.x;
    const int wid = tid >> 5, lane = tid & 31;
    const int b  = blockIdx.x >> 4;
    const int kz = (blockIdx.x >> 1) & 7;
    const int nh = blockIdx.x & 1;
    const int gid = lane >> 2, tig = lane & 3;
    uint32_t* AH = (uint32_t*)dsm;
    uint32_t* AL = (uint32_t*)(dsm + P3_AL);
    uint32_t* BH = (uint32_t*)(dsm + P3_BH);
    uint32_t* BL = (uint32_t*)(dsm + P3_BL);
    const uint32_t* aHg = g_aH + (size_t)b * 76800;
    const uint32_t* aLg = g_aL + (size_t)b * 76800;

    if (tid < 75) scv[tid] = g_cinv_nt[b * 75 + tid];
    for (int i = tid; i < 100; i += 256) {
        AH[75 * 20 + i] = 0; AL[75 * 20 + i] = 0;
    }
    __syncthreads();

    float acc[5][2][4];
    #pragma unroll
    for (int mt = 0; mt < 5; mt++)
        #pragma unroll
        for (int nt = 0; nt < 2; nt++)
            #pragma unroll
            for (int q = 0; q < 4; q++) acc[mt][nt][q] = 0.f;

    const int n0 = wid * 16;
    const float* srcB = image + (size_t)(b * 8 + kz) * 65536 + (size_t)(nh * 128) * 256;

    for (int c8 = 0; c8 < 8; c8++) {
        const int rg = kz * 256 + c8 * 32;
        const int p0 = c8 * 32;
        // ---- A: direct copy of prepped bf16 alpha-numerators --------------
        for (int idx = tid; idx < 1200; idx += 256) {
            int t = idx >> 4, c = idx & 15;
            int gi = t * 1024 + (rg >> 1) + c;
            AH[t * 20 + c] = aHg[gi];
            AL[t * 20 + c] = aLg[gi];
        }
        // ---- B: 128 image d-rows (this N-half), natively k-contig ----------
        #pragma unroll
        for (int it = 0; it < 4; it++) {
            int idx = tid + it * 256;
            int d = idx >> 3, c4 = (idx & 7) * 4;
            float4 v = *(const float4*)(srcB + (size_t)d * 256 + p0 + c4);
            uint32_t h0, l0, h1, l1;
            bsplit2(v.x, v.y, h0, l0);
            bsplit2(v.z, v.w, h1, l1);
            int w0 = d * 20 + (c4 >> 1);
            BH[w0] = h0; BH[w0 + 1] = h1;
            BL[w0] = l0; BL[w0 + 1] = l1;
        }
        __syncthreads();
        #pragma unroll
        for (int ks = 0; ks < 2; ks++) {
            const int ko = ks * 8 + tig;
            uint32_t bh[2][2], bl[2][2];
            #pragma unroll
            for (int nt = 0; nt < 2; nt++) {
                int nb = (n0 + nt * 8 + gid) * 20 + ko;
                bh[nt][0] = BH[nb]; bh[nt][1] = BH[nb + 4];
                bl[nt][0] = BL[nb]; bl[nt][1] = BL[nb + 4];
            }
            #pragma unroll
            for (int mt = 0; mt < 5; mt++) {
                int ra = mt * 16 + gid;
                uint32_t ah0 = AH[ra * 20 + ko],     ah1 = AH[(ra + 8) * 20 + ko];
                uint32_t ah2 = AH[ra * 20 + ko + 4], ah3 = AH[(ra + 8) * 20 + ko + 4];
                uint32_t al0 = AL[ra * 20 + ko],     al1 = AL[(ra + 8) * 20 + ko];
                uint32_t al2 = AL[ra * 20 + ko + 4], al3 = AL[(ra + 8) * 20 + ko + 4];
                #pragma unroll
                for (int nt = 0; nt < 2; nt++) {
                    mma_bf16(acc[mt][nt], ah0, ah1, ah2, ah3, bh[nt][0], bh[nt][1]);
                    mma_bf16(acc[mt][nt], ah0, ah1, ah2, ah3, bl[nt][0], bl[nt][1]);
                    mma_bf16(acc[mt][nt], al0, al1, al2, al3, bh[nt][0], bh[nt][1]);
                }
            }
        }
        __syncthreads();
    }
    // ---- epilogue: scale by cinv[t], write split-K partials -----------------
    float* outp = g_vtp + (size_t)kz * 40 * 75 * 256 + (size_t)b * 75 * 256 + nh * 128;
    #pragma unroll
    for (int mt = 0; mt < 5; mt++) {
        int t = mt * 16 + gid;
        #pragma unroll
        for (int nt = 0; nt < 2; nt++) {
            int d = n0 + nt * 8 + tig * 2;
            if (t < 75) {
                float ci = scv[t];
                float2 v0 = {acc[mt][nt][0] * ci, acc[mt][nt][1] * ci};
                *(float2*)(outp + (size_t)t * 256 + d) = v0;
            }
            if (t + 8 < 75) {
                float ci = scv[t + 8];
                float2 v1 = {acc[mt][nt][2] * ci, acc[mt][nt][3] * ci};
                *(float2*)(outp + (size_t)(t + 8) * 256 + d) = v1;
            }
        }
    }
}

// ============ PHASE 4: tail = logit2 (320) + reg (40) + score1 (375) ========
__global__ void __launch_bounds__(256) k_tail(const float* __restrict__ text) {
    __shared__ __align__(16) float pool[1500];
    const int bx = blockIdx.x;
    const int tid = threadIdx.x;
    const int lane = tid & 31, w = tid >> 5;

    if (bx < 320) {
        const int b = bx >> 3, m = bx & 7, blk = b / 5;
        float* shsd = pool;
        float* wred = pool + 16;
        const float vv = g_vns[((size_t)b * 8 + m) * 256 + tid];
        for (int sb = 0; sb < 5; sb++) {
            if (tid < 15) shsd[tid] = g_sd[((size_t)b * 8 + m) * 75 + sb * 15 + tid];
            __syncthreads();
            float segsum = 0.f;
            #pragma unroll
            for (int l = 0; l < 15; l++) segsum += shsd[l];
            float em = 0.f;
            #pragma unroll
            for (int l = 0; l < 15; l++)
                em = fmaf(shsd[l], text[((size_t)blk * 75 + sb * 15 + l) * 256 + tid], em);
            em /= segsum;
            float p = em * em, q = em * vv;
            #pragma unroll
            for (int o = 16; o > 0; o >>= 1) {
                p += __shfl_xor_sync(0xffffffffu, p, o);
                q += __shfl_xor_sync(0xffffffffu, q, o);
            }
            if (lane == 0) { wred[w] = p; wred[8 + w] = q; }
            __syncthreads();
            if (tid == 0) {
                float s1 = 0.f, s2 = 0.f;
                #pragma unroll
                for (int j = 0; j < 8; j++) { s1 += wred[j]; s2 += wred[8 + j]; }
                g_logit2[((size_t)b * 8 + m) * 5 + sb] =
                    s2 / (fmaxf(sqrtf(s1), 1e-12f) * 256.0f);
            }
            __syncthreads();
        }
    } else if (bx < 360) {
        const int b = bx - 320;
        float* ssd   = pool;
        float* sseg  = pool + 600;
        float* sbeta = pool + 640;
        float* red   = pool + 1240;
        for (int i = tid; i < 600; i += 256) ssd[i] = g_sd[(size_t)b * 600 + i];
        __syncthreads();
        if (tid < 40) {
            int m = tid / 5, sb2 = tid % 5;
            float s = 0.f;
            for (int l = 0; l < 15; l++) s += ssd[m * 75 + sb2 * 15 + l];
            sseg[tid] = s;
        }
        __syncthreads();
        for (int i = tid; i < 600; i += 256) {
            int m = i / 75, t = i % 75;
            sbeta[i] = ssd[i] / sseg[m * 5 + t / 15];
        }
        __syncthreads();
        float p = 0.f;
        if (tid < 64) {
            int m = tid >> 3, n = tid & 7;
            if (m != n) {
                float a = 0.f;
                for (int t = 0; t < 75; t++) a = fmaf(sbeta[m * 75 + t], sbeta[n * 75 + t], a);
                p = a * a;
            }
        }
        red[tid] = p; __syncthreads();
        for (int o = 128; o > 0; o >>= 1) { if (tid < o) red[tid] += red[tid + o]; __syncthreads(); }
        if (tid == 0) g_regval[b] = sqrtf(red[0]);
    } else {
        const int gt = (bx - 360) * 8 + w;
        if (gt < 3000) {
            const int b = gt / 75, t = gt % 75, blk = b / 5;
            const size_t SL = (size_t)40 * 75 * 256;
            const size_t voff = ((size_t)b * 75 + t) * 256;
            const float* e = text + ((size_t)blk * 75 + t) * 256;
            float dot = 0.f, nv = 0.f, ne = 0.f;
            #pragma unroll
            for (int j = 0; j < 8; j++) {
                int d = lane + 32 * j;
                float a = 0.f;
                #pragma unroll
                for (int s8 = 0; s8 < 8; s8++) a += g_vtp[s8 * SL + voff + d];
                float cc = e[d];
                dot = fmaf(a, cc, dot); nv = fmaf(a, a, nv); ne = fmaf(cc, cc, ne);
            }
            #pragma unroll
            for (int o = 16; o > 0; o >>= 1) {
                dot += __shfl_xor_sync(0xffffffffu, dot, o);
                nv  += __shfl_xor_sync(0xffffffffu, nv,  o);
                ne  += __shfl_xor_sync(0xffffffffu, ne,  o);
            }
            if (lane == 0)
                g_el[b * 75 + t] = __expf(dot / (fmaxf(sqrtf(nv), 1e-12f) * fmaxf(sqrtf(ne), 1e-12f)));
        }
    }
}

// ============ PHASE 5: final scalar =========================================
__global__ void k_final(float* __restrict__ out) {
    const int tid = threadIdx.x;
    __shared__ float lsm[200];
    __shared__ float bscore[8];
    if (tid < 200) {
        int blk = tid / 25, rem = tid % 25, i = rem / 5, sb = rem % 5;
        int gi = blk * 5 + i;
        float s2 = 0.f;
        #pragma unroll
        for (int m = 0; m < 8; m++) s2 += __expf(g_logit2[((size_t)gi * 8 + m) * 5 + sb]);
        float s1 = 0.f;
        #pragma unroll
        for (int l = 0; l < 15; l++) s1 += g_el[gi * 75 + sb * 15 + l];
        float l1 = __logf(__powf(s1, 0.2f) + EPSL);
        float l2 = __logf(__powf(s2, 0.2f) + EPSL);
        lsm[tid] = 10.0f * (l1 + l2);
    }
    __syncthreads();
    if (tid < 8) {
        const float* L = lsm + tid * 25;
        float rows[5] = {0, 0, 0, 0, 0}, cols[5] = {0, 0, 0, 0, 0};
        for (int i = 0; i < 5; i++)
            for (int sb = 0; sb < 5; sb++) {
                rows[i] += L[i * 5 + sb];
                cols[sb] += L[i * 5 + sb];
            }
        float acc = 0.f;
        for (int i = 0; i < 5; i++) {
            float dg = L[i * 5 + i];
            acc += -__logf(dg / rows[i] + EPSL) - __logf(dg / cols[i] + EPSL);
        }
        float reg = 0.f;
        for (int i = 0; i < 5; i++) reg += g_regval[tid * 5 + i];
        bscore[tid] = acc / 5.0f + reg / 5.0f;
    }
    __syncthreads();
    if (tid == 0) {
        float tot = 0.f;
        for (int k = 0; k < 8; k++) tot += bscore[k];
        out[0] = tot / 9.0f;
    }
}

// ---------------- launch -----------------------------------------------------
extern "C" void kernel_launch(void* const* d_in, const int* in_sizes, int n_in,
                              void* d_out, int out_size) {
    (void)in_sizes; (void)n_in; (void)out_size;
    const float* image = (const float*)d_in[0];
    const float* text  = (const float*)d_in[1];
    float* out = (float*)d_out;

    cudaFuncSetAttribute(k_phase1, cudaFuncAttributeMaxDynamicSharedMemorySize, P1_SZ);
    cudaFuncSetAttribute(k_vtidal, cudaFuncAttributeMaxDynamicSharedMemorySize, P3_SZ);

    k_prep<<<300, 256>>>(text);
    k_phase1<<<960, 256, P1_SZ>>>(image, text);
    k_colstats<<<dim3(75, 40), 256>>>();
    k_vtidal<<<640, 256, P3_SZ>>>(image);
    k_tail<<<735, 256>>>(text);
    k_final<<<1, 256>>>(out);
}

// round 8
// speedup vs baseline: 2.5596x; 1.1995x over previous
#include <cuda_runtime.h>
#include <cuda_bf16.h>
#include <math.h>
#include <stdint.h>

#define G1 4.0f
#define EPSL 1e-10f

// ---------------- scratch (device globals) ----------------------------------
__device__ float    g_sT[40u*75u*2048u];      // [b][t][r]: s scores
__device__ float    g_rowstats[40u*2048u*5u*2u];
__device__ float    g_cinv_nt[40*75];
__device__ float    g_sd[40*8*75];
__device__ uint32_t g_aH[40u*75u*1024u];      // alpha numerators, bf16-hi pairs
__device__ uint32_t g_aL[40u*75u*1024u];      // alpha numerators, bf16-lo pairs
__device__ uint32_t g_eh[8*75*128];           // text bf16-hi pairs
__device__ uint32_t g_el2[8*75*128];          // text bf16-lo pairs
__device__ float    g_vtp[8u*40u*75u*256u];   // split-K partials of v_tidal
__device__ float    g_vns[40*8*256];
__device__ float    g_el[40*75];
__device__ float    g_logit2[40*8*5];
__device__ float    g_regval[40];

// ---------------- helpers ----------------------------------------------------
__device__ __forceinline__ uint32_t s2u(const void* p) {
    uint32_t a;
    asm("{ .reg .u64 t; cvta.to.shared.u64 t, %1; cvt.u32.u64 %0, t; }" : "=r"(a) : "l"(p));
    return a;
}
__device__ __forceinline__ void cp16(uint32_t dst, const void* src) {
    asm volatile("cp.async.cg.shared.global [%0], [%1], 16;" :: "r"(dst), "l"(src));
}
__device__ __forceinline__ void cp_commit() { asm volatile("cp.async.commit_group;" ::: "memory"); }
__device__ __forceinline__ void cp_wait0()  { asm volatile("cp.async.wait_group 0;" ::: "memory"); }

__device__ __forceinline__ void mma_bf16(float* c, uint32_t a0, uint32_t a1,
                                         uint32_t a2, uint32_t a3,
                                         uint32_t b0, uint32_t b1) {
    asm volatile(
        "mma.sync.aligned.m16n8k16.row.col.f32.bf16.bf16.f32 "
        "{%0,%1,%2,%3}, {%4,%5,%6,%7}, {%8,%9}, {%0,%1,%2,%3};"
        : "+f"(c[0]), "+f"(c[1]), "+f"(c[2]), "+f"(c[3])
        : "r"(a0), "r"(a1), "r"(a2), "r"(a3), "r"(b0), "r"(b1));
}
// fast split: x,y -> packed bf16 hi + packed bf16 lo residual
__device__ __forceinline__ void bsplit2(float x, float y, uint32_t& hi, uint32_t& lo) {
    uint32_t h;
    asm("cvt.rn.bf16x2.f32 %0, %1, %2;" : "=r"(h) : "f"(y), "f"(x));
    float hx = __uint_as_float(h << 16);
    float hy = __uint_as_float(h & 0xFFFF0000u);
    float lx = x - hx, ly = y - hy;
    asm("cvt.rn.bf16x2.f32 %0, %1, %2;" : "=r"(lo) : "f"(ly), "f"(lx));
    hi = h;
}

// phase1: per-stage 33280 B: AH[128][20] @0 | AL @10240 | BH[80][20] @20480 | BL @26880
// TR fp32[32][132] @66560 ; total 83456
#define P1_ST  33280
#define P1_TR  66560
#define P1_SZ  83456
// vtidal: per-stage 33280 B: AH[80][20] @0 | AL @6400 | BH[128][20] @12800 | BL @23040
#define P3_ST  33280
#define P3_SZ  66560

// ============ PHASE 0: convert text to bf16 hi/lo pairs =====================
__global__ void __launch_bounds__(256) k_prep(const float* __restrict__ text) {
    int i = blockIdx.x * 256 + threadIdx.x;   // 76800 pairs
    float2 v = *(const float2*)(text + 2 * i);
    uint32_t h, l;
    bsplit2(v.x, v.y, h, l);
    g_eh[i] = h; g_el2[i] = l;
}

// ============ PHASE 1: pipelined mma gemm_s (640 blks) + vns (320) ==========
__global__ void __launch_bounds__(256) k_phase1(const float* __restrict__ image,
                                                const float* __restrict__ text) {
    extern __shared__ __align__(16) char dsm[];
    const int bx = blockIdx.x;
    const int tid = threadIdx.x;
    const int wid = tid >> 5, lane = tid & 31;

    if (bx < 640) {
        const int b  = bx >> 4;
        const int rb = bx & 15;
        const int r0 = rb * 128;
        const int m  = rb >> 1, p0 = (rb & 1) * 128;
        const float* srcA = image + (size_t)(b * 8 + m) * 65536;
        const uint32_t* eH = g_eh  + (size_t)(b / 5) * 9600;
        const uint32_t* eL = g_el2 + (size_t)(b / 5) * 9600;
        const uint32_t sbase = s2u(dsm);
        float* TR = (float*)(dsm + P1_TR);
        const int gid = lane >> 2, tig = lane & 3;

        // zero B pad rows 75..79 in both stages
        for (int i = tid; i < 100; i += 256) {
            #pragma unroll
            for (int s = 0; s < 2; s++) {
                *(uint32_t*)(dsm + s * P1_ST + 20480 + (1500 + i) * 4) = 0;
                *(uint32_t*)(dsm + s * P1_ST + 26880 + (1500 + i) * 4) = 0;
            }
        }

        float4 iv[4];
        // load image chunk kb into regs
        auto load_a = [&](int c) {
            const int kb = c * 32;
            #pragma unroll
            for (int it = 0; it < 4; it++) {
                int lin = tid + it * 256;
                int k = lin >> 5, f4 = (lin & 31) * 4;
                iv[it] = *(const float4*)(srcA + (size_t)(kb + k) * 256 + p0 + f4);
            }
        };
        auto store_tr = [&]() {
            #pragma unroll
            for (int it = 0; it < 4; it++) {
                int lin = tid + it * 256;
                int k = lin >> 5, f4 = (lin & 31) * 4;
                *(float4*)(TR + k * 132 + f4) = iv[it];
            }
        };
        auto conv_a = [&](int s) {
            uint32_t* AH = (uint32_t*)(dsm + s * P1_ST);
            uint32_t* AL = (uint32_t*)(dsm + s * P1_ST + 10240);
            const int r = tid >> 1, kh = (tid & 1) * 16;
            #pragma unroll
            for (int j = 0; j < 16; j += 2) {
                float x0 = TR[(kh + j) * 132 + r];
                float x1 = TR[(kh + j + 1) * 132 + r];
                uint32_t hi, lo;
                bsplit2(x0, x1, hi, lo);
                int w0 = r * 20 + ((kh + j) >> 1);
                AH[w0] = hi; AL[w0] = lo;
            }
        };
        auto stage_b = [&](int c, int s) {
            const int kw = c * 16;    // u32 offset within text row
            #pragma unroll
            for (int i = 0; i < 3; i++) {
                int idx = tid + i * 256;
                if (idx < 600) {
                    int half = (idx >= 300) ? 1 : 0;
                    int j = idx - half * 300;
                    int t = j >> 2, c4 = (j & 3) * 4;
                    const uint32_t* src = (half ? eL : eH) + t * 128 + kw + c4;
                    cp16(sbase + s * P1_ST + 20480 + half * 6400 + (t * 20 + c4) * 4, src);
                }
            }
            cp_commit();
        };

        float acc[10][4];
        #pragma unroll
        for (int nt = 0; nt < 10; nt++)
            #pragma unroll
            for (int q = 0; q < 4; q++) acc[nt][q] = 0.f;

        // prologue: chunk 0
        load_a(0);
        stage_b(0, 0);
        store_tr();
        __syncthreads();
        conv_a(0);
        cp_wait0();
        __syncthreads();

        for (int c = 0; c < 8; c++) {
            const int s = c & 1;
            if (c < 7) { load_a(c + 1); stage_b(c + 1, s ^ 1); }
            // ---- mma on stage s -----------------------------------------
            {
                uint32_t* AH = (uint32_t*)(dsm + s * P1_ST);
                uint32_t* AL = (uint32_t*)(dsm + s * P1_ST + 10240);
                uint32_t* BH = (uint32_t*)(dsm + s * P1_ST + 20480);
                uint32_t* BL = (uint32_t*)(dsm + s * P1_ST + 26880);
                const int rA = wid * 16 + gid;
                #pragma unroll
                for (int ks = 0; ks < 2; ks++) {
                    const int ko = ks * 8 + tig;
                    uint32_t ah0 = AH[rA * 20 + ko],       ah1 = AH[(rA + 8) * 20 + ko];
                    uint32_t ah2 = AH[rA * 20 + ko + 4],   ah3 = AH[(rA + 8) * 20 + ko + 4];
                    uint32_t al0 = AL[rA * 20 + ko],       al1 = AL[(rA + 8) * 20 + ko];
                    uint32_t al2 = AL[rA * 20 + ko + 4],   al3 = AL[(rA + 8) * 20 + ko + 4];
                    #pragma unroll
                    for (int nt = 0; nt < 10; nt++) {
                        int nb = (nt * 8 + gid) * 20 + ko;
                        uint32_t bh0 = BH[nb], bh1 = BH[nb + 4];
                        uint32_t bl0 = BL[nb], bl1 = BL[nb + 4];
                        mma_bf16(acc[nt], ah0, ah1, ah2, ah3, bh0, bh1);
                        mma_bf16(acc[nt], ah0, ah1, ah2, ah3, bl0, bl1);
                        mma_bf16(acc[nt], al0, al1, al2, al3, bh0, bh1);
                    }
                }
            }
            if (c < 7) {
                store_tr();
                __syncthreads();
                conv_a(s ^ 1);
                cp_wait0();
            }
            __syncthreads();
        }
        // ---- epilogue: stage C to sc[t][132 r] --------------------------
        float* sc = (float*)dsm;
        const int rA = wid * 16 + gid;
        #pragma unroll
        for (int nt = 0; nt < 10; nt++) {
            int t0 = nt * 8 + tig * 2;
            sc[t0 * 132 + rA]           = acc[nt][0];
            sc[(t0 + 1) * 132 + rA]     = acc[nt][1];
            sc[t0 * 132 + rA + 8]       = acc[nt][2];
            sc[(t0 + 1) * 132 + rA + 8] = acc[nt][3];
        }
        __syncthreads();
        if (tid < 128) {
            const int r = tid;
            #pragma unroll
            for (int seg = 0; seg < 5; seg++) {
                float mx = -3.4e38f;
                #pragma unroll
                for (int l = 0; l < 15; l++)
                    mx = fmaxf(mx, sc[(seg * 15 + l) * 132 + r]);
                float se = 0.f;
                #pragma unroll
                for (int l = 0; l < 15; l++)
                    se += __expf(sc[(seg * 15 + l) * 132 + r] - mx);
                size_t ridx = ((size_t)b * 2048 + r0 + r) * 5 + seg;
                g_rowstats[ridx * 2]     = mx;
                g_rowstats[ridx * 2 + 1] = 1.0f / se;
            }
        }
        for (int i = tid; i < 9600; i += 256) {
            int t = i >> 7, r = i & 127;
            g_sT[((size_t)b * 75 + t) * 2048 + r0 + r] = sc[t * 132 + r];
        }
    } else {
        // -------- vns from image directly ------------------------------------
        const int bm = bx - 640;
        const float* src = image + (size_t)bm * 65536;
        float* invn = (float*)dsm;
        float s0 = 0.f, s1 = 0.f, s2 = 0.f, s3 = 0.f;
        for (int d = 0; d < 256; d += 4) {
            float x0 = src[(size_t)(d + 0) * 256 + tid];
            float x1 = src[(size_t)(d + 1) * 256 + tid];
            float x2 = src[(size_t)(d + 2) * 256 + tid];
            float x3 = src[(size_t)(d + 3) * 256 + tid];
            s0 = fmaf(x0, x0, s0); s1 = fmaf(x1, x1, s1);
            s2 = fmaf(x2, x2, s2); s3 = fmaf(x3, x3, s3);
        }
        invn[tid] = 1.0f / fmaxf(sqrtf((s0 + s1) + (s2 + s3)), 1e-12f);
        __syncthreads();
        for (int j = 0; j < 32; j++) {
            int d = wid * 32 + j;
            const float* row = src + (size_t)d * 256;
            float a = 0.f;
            #pragma unroll
            for (int q = 0; q < 8; q++) {
                int p = lane + 32 * q;
                a = fmaf(row[p], invn[p], a);
            }
            #pragma unroll
            for (int o = 16; o > 0; o >>= 1) a += __shfl_xor_sync(0xffffffffu, a, o);
            if (lane == 0) g_vns[(size_t)bm * 256 + d] = a;
        }
    }
}

// ============ PHASE 2: column stats + sd + packed bf16 alpha =================
__global__ void __launch_bounds__(256) k_colstats() {
    const int t = blockIdx.x, b = blockIdx.y, seg = t / 15;
    const int tid = threadIdx.x, lane = tid & 31, w = tid >> 5;
    const float* col = g_sT + ((size_t)b * 75 + t) * 2048;
    __shared__ float sred[24];

    float vals[8];
    *(float4*)vals       = *(const float4*)(col + tid * 8);
    *(float4*)(vals + 4) = *(const float4*)(col + tid * 8 + 4);

    float mx = vals[0];
    #pragma unroll
    for (int k = 1; k < 8; k++) mx = fmaxf(mx, vals[k]);
    #pragma unroll
    for (int o = 16; o > 0; o >>= 1) mx = fmaxf(mx, __shfl_xor_sync(0xffffffffu, mx, o));
    if (lane == 0) sred[w] = mx;
    __syncthreads();
    float cmax = sred[0];
    #pragma unroll
    for (int q = 1; q < 8; q++) cmax = fmaxf(cmax, sred[q]);

    float e1[8], al[8];
    float sraw = 0.f, snt = 0.f;
    const float* rsb = g_rowstats + (((size_t)b * 2048 + tid * 8) * 5 + seg) * 2;
    #pragma unroll
    for (int k = 0; k < 8; k++) {
        e1[k] = __expf(vals[k] - cmax);
        sraw += e1[k];
        float2 rs = *(const float2*)(rsb + k * 10);
        al[k] = __expf(G1 * __expf(vals[k] - rs.x) * rs.y);
        snt += al[k];
    }
    {
        uint32_t* aH = g_aH + (size_t)b * 76800 + t * 1024 + tid * 4;
        uint32_t* aL = g_aL + (size_t)b * 76800 + t * 1024 + tid * 4;
        #pragma unroll
        for (int j = 0; j < 4; j++) {
            uint32_t h, l;
            bsplit2(al[2 * j], al[2 * j + 1], h, l);
            aH[j] = h; aL[j] = l;
        }
    }
    float sr = sraw, sn = snt;
    #pragma unroll
    for (int o = 16; o > 0; o >>= 1) {
        sr += __shfl_xor_sync(0xffffffffu, sr, o);
        sn += __shfl_xor_sync(0xffffffffu, sn, o);
    }
    if (lane == 0) { sred[8 + w] = sr; sred[16 + w] = sn; }
    __syncthreads();
    float tot = 0.f;
    #pragma unroll
    for (int q = 0; q < 8; q++) tot += sred[8 + q];
    const float cinv = 1.0f / tot;
    if (tid == 0) {
        float s = 0.f;
        #pragma unroll
        for (int q = 0; q < 8; q++) s += sred[16 + q];
        g_cinv_nt[b * 75 + t] = 1.0f / s;
    }
    float e2 = 0.f;
    #pragma unroll
    for (int k = 0; k < 8; k++) e2 += __expf(e1[k] * cinv);
    #pragma unroll
    for (int o = 16; o > 0; o >>= 1) e2 += __shfl_xor_sync(0xffffffffu, e2, o);
    if (lane == 0) g_sd[((size_t)b * 8 + w) * 75 + t] = e2;
}

// ============ PHASE 3: pipelined mma v_tidal (640 blocks) ====================
__global__ void __launch_bounds__(256) k_vtidal(const float* __restrict__ image) {
    extern __shared__ __align__(16) char dsm[];
    __shared__ float scv[80];
    const int tid = threadIdx.x;
    const int wid = tid >> 5, lane = tid & 31;
    const int b  = blockIdx.x >> 4;
    const int kz = (blockIdx.x >> 1) & 7;
    const int nh = blockIdx.x & 1;
    const int gid = lane >> 2, tig = lane & 3;
    const uint32_t sbase = s2u(dsm);
    const uint32_t* aHg = g_aH + (size_t)b * 76800;
    const uint32_t* aLg = g_aL + (size_t)b * 76800;
    const float* srcB = image + (size_t)(b * 8 + kz) * 65536 + (size_t)(nh * 128) * 256;

    if (tid < 75) scv[tid] = g_cinv_nt[b * 75 + tid];
    // zero A pad rows 75..79 in both stages
    for (int i = tid; i < 100; i += 256) {
        #pragma unroll
        for (int s = 0; s < 2; s++) {
            *(uint32_t*)(dsm + s * P3_ST +        (1500 + i) * 4) = 0;
            *(uint32_t*)(dsm + s * P3_ST + 6400 + (1500 + i) * 4) = 0;
        }
    }

    auto stage_a = [&](int c, int s) {
        const int rgw = (kz * 256 + c * 32) >> 1;
        #pragma unroll
        for (int i = 0; i < 3; i++) {
            int idx = tid + i * 256;
            if (idx < 600) {
                int half = (idx >= 300) ? 1 : 0;
                int j = idx - half * 300;
                int t = j >> 2, c4 = (j & 3) * 4;
                const uint32_t* src = (half ? aLg : aHg) + t * 1024 + rgw + c4;
                cp16(sbase + s * P3_ST + half * 6400 + (t * 20 + c4) * 4, src);
            }
        }
        cp_commit();
    };

    float4 vb[4];
    auto load_b = [&](int c) {
        const int p0 = c * 32;
        #pragma unroll
        for (int it = 0; it < 4; it++) {
            int idx = tid + it * 256;
            int d = idx >> 3, c4 = (idx & 7) * 4;
            vb[it] = *(const float4*)(srcB + (size_t)d * 256 + p0 + c4);
        }
    };
    auto store_b = [&](int s) {
        uint32_t* BH = (uint32_t*)(dsm + s * P3_ST + 12800);
        uint32_t* BL = (uint32_t*)(dsm + s * P3_ST + 23040);
        #pragma unroll
        for (int it = 0; it < 4; it++) {
            int idx = tid + it * 256;
            int d = idx >> 3, c4 = (idx & 7) * 4;
            uint32_t h0, l0, h1, l1;
            bsplit2(vb[it].x, vb[it].y, h0, l0);
            bsplit2(vb[it].z, vb[it].w, h1, l1);
            int w0 = d * 20 + (c4 >> 1);
            BH[w0] = h0; BH[w0 + 1] = h1;
            BL[w0] = l0; BL[w0 + 1] = l1;
        }
    };

    float acc[5][2][4];
    #pragma unroll
    for (int mt = 0; mt < 5; mt++)
        #pragma unroll
        for (int nt = 0; nt < 2; nt++)
            #pragma unroll
            for (int q = 0; q < 4; q++) acc[mt][nt][q] = 0.f;

    // prologue: chunk 0
    stage_a(0, 0);
    load_b(0);
    store_b(0);
    cp_wait0();
    __syncthreads();

    const int n0 = wid * 16;
    for (int c = 0; c < 8; c++) {
        const int s = c & 1;
        if (c < 7) { stage_a(c + 1, s ^ 1); load_b(c + 1); }
        // ---- mma on stage s ---------------------------------------------
        {
            uint32_t* AH = (uint32_t*)(dsm + s * P3_ST);
            uint32_t* AL = (uint32_t*)(dsm + s * P3_ST + 6400);
            uint32_t* BH = (uint32_t*)(dsm + s * P3_ST + 12800);
            uint32_t* BL = (uint32_t*)(dsm + s * P3_ST + 23040);
            #pragma unroll
            for (int ks = 0; ks < 2; ks++) {
                const int ko = ks * 8 + tig;
                uint32_t bh[2][2], bl[2][2];
                #pragma unroll
                for (int nt = 0; nt < 2; nt++) {
                    int nb = (n0 + nt * 8 + gid) * 20 + ko;
                    bh[nt][0] = BH[nb]; bh[nt][1] = BH[nb + 4];
                    bl[nt][0] = BL[nb]; bl[nt][1] = BL[nb + 4];
                }
                #pragma unroll
                for (int mt = 0; mt < 5; mt++) {
                    int ra = mt * 16 + gid;
                    uint32_t ah0 = AH[ra * 20 + ko],     ah1 = AH[(ra + 8) * 20 + ko];
                    uint32_t ah2 = AH[ra * 20 + ko + 4], ah3 = AH[(ra + 8) * 20 + ko + 4];
                    uint32_t al0 = AL[ra * 20 + ko],     al1 = AL[(ra + 8) * 20 + ko];
                    uint32_t al2 = AL[ra * 20 + ko + 4], al3 = AL[(ra + 8) * 20 + ko + 4];
                    #pragma unroll
                    for (int nt = 0; nt < 2; nt++) {
                        mma_bf16(acc[mt][nt], ah0, ah1, ah2, ah3, bh[nt][0], bh[nt][1]);
                        mma_bf16(acc[mt][nt], ah0, ah1, ah2, ah3, bl[nt][0], bl[nt][1]);
                        mma_bf16(acc[mt][nt], al0, al1, al2, al3, bh[nt][0], bh[nt][1]);
                    }
                }
            }
        }
        if (c < 7) { store_b(s ^ 1); cp_wait0(); }
        __syncthreads();
    }
    // ---- epilogue: scale by cinv[t], write split-K partials -----------------
    float* outp = g_vtp + (size_t)kz * 40 * 75 * 256 + (size_t)b * 75 * 256 + nh * 128;
    #pragma unroll
    for (int mt = 0; mt < 5; mt++) {
        int t = mt * 16 + gid;
        #pragma unroll
        for (int nt = 0; nt < 2; nt++) {
            int d = n0 + nt * 8 + tig * 2;
            if (t < 75) {
                float ci = scv[t];
                float2 v0 = {acc[mt][nt][0] * ci, acc[mt][nt][1] * ci};
                *(float2*)(outp + (size_t)t * 256 + d) = v0;
            }
            if (t + 8 < 75) {
                float ci = scv[t + 8];
                float2 v1 = {acc[mt][nt][2] * ci, acc[mt][nt][3] * ci};
                *(float2*)(outp + (size_t)(t + 8) * 256 + d) = v1;
            }
        }
    }
}

// ============ PHASE 4: tail = logit2 (320) + reg (40) + score1 (375) ========
__global__ void __launch_bounds__(256) k_tail(const float* __restrict__ text) {
    __shared__ __align__(16) float pool[1500];
    const int bx = blockIdx.x;
    const int tid = threadIdx.x;
    const int lane = tid & 31, w = tid >> 5;

    if (bx < 320) {
        const int b = bx >> 3, m = bx & 7, blk = b / 5;
        float* shsd = pool;
        float* wred = pool + 16;
        const float vv = g_vns[((size_t)b * 8 + m) * 256 + tid];
        for (int sb = 0; sb < 5; sb++) {
            if (tid < 15) shsd[tid] = g_sd[((size_t)b * 8 + m) * 75 + sb * 15 + tid];
            __syncthreads();
            float segsum = 0.f;
            #pragma unroll
            for (int l = 0; l < 15; l++) segsum += shsd[l];
            float em = 0.f;
            #pragma unroll
            for (int l = 0; l < 15; l++)
                em = fmaf(shsd[l], text[((size_t)blk * 75 + sb * 15 + l) * 256 + tid], em);
            em /= segsum;
            float p = em * em, q = em * vv;
            #pragma unroll
            for (int o = 16; o > 0; o >>= 1) {
                p += __shfl_xor_sync(0xffffffffu, p, o);
                q += __shfl_xor_sync(0xffffffffu, q, o);
            }
            if (lane == 0) { wred[w] = p; wred[8 + w] = q; }
            __syncthreads();
            if (tid == 0) {
                float s1 = 0.f, s2 = 0.f;
                #pragma unroll
                for (int j = 0; j < 8; j++) { s1 += wred[j]; s2 += wred[8 + j]; }
                g_logit2[((size_t)b * 8 + m) * 5 + sb] =
                    s2 / (fmaxf(sqrtf(s1), 1e-12f) * 256.0f);
            }
            __syncthreads();
        }
    } else if (bx < 360) {
        const int b = bx - 320;
        float* ssd   = pool;
        float* sseg  = pool + 600;
        float* sbeta = pool + 640;
        float* red   = pool + 1240;
        for (int i = tid; i < 600; i += 256) ssd[i] = g_sd[(size_t)b * 600 + i];
        __syncthreads();
        if (tid < 40) {
            int m = tid / 5, sb2 = tid % 5;
            float s = 0.f;
            for (int l = 0; l < 15; l++) s += ssd[m * 75 + sb2 * 15 + l];
            sseg[tid] = s;
        }
        __syncthreads();
        for (int i = tid; i < 600; i += 256) {
            int m = i / 75, t = i % 75;
            sbeta[i] = ssd[i] / sseg[m * 5 + t / 15];
        }
        __syncthreads();
        float p = 0.f;
        if (tid < 64) {
            int m = tid >> 3, n = tid & 7;
            if (m != n) {
                float a = 0.f;
                for (int t = 0; t < 75; t++) a = fmaf(sbeta[m * 75 + t], sbeta[n * 75 + t], a);
                p = a * a;
            }
        }
        red[tid] = p; __syncthreads();
        for (int o = 128; o > 0; o >>= 1) { if (tid < o) red[tid] += red[tid + o]; __syncthreads(); }
        if (tid == 0) g_regval[b] = sqrtf(red[0]);
    } else {
        const int gt = (bx - 360) * 8 + w;
        if (gt < 3000) {
            const int b = gt / 75, t = gt % 75, blk = b / 5;
            const size_t SL = (size_t)40 * 75 * 256;
            const size_t voff = ((size_t)b * 75 + t) * 256;
            const float* e = text + ((size_t)blk * 75 + t) * 256;
            float dot = 0.f, nv = 0.f, ne = 0.f;
            #pragma unroll
            for (int j = 0; j < 8; j++) {
                int d = lane + 32 * j;
                float a = 0.f;
                #pragma unroll
                for (int s8 = 0; s8 < 8; s8++) a += g_vtp[s8 * SL + voff + d];
                float cc = e[d];
                dot = fmaf(a, cc, dot); nv = fmaf(a, a, nv); ne = fmaf(cc, cc, ne);
            }
            #pragma unroll
            for (int o = 16; o > 0; o >>= 1) {
                dot += __shfl_xor_sync(0xffffffffu, dot, o);
                nv  += __shfl_xor_sync(0xffffffffu, nv,  o);
                ne  += __shfl_xor_sync(0xffffffffu, ne,  o);
            }
            if (lane == 0)
                g_el[b * 75 + t] = __expf(dot / (fmaxf(sqrtf(nv), 1e-12f) * fmaxf(sqrtf(ne), 1e-12f)));
        }
    }
}

// ============ PHASE 5: final scalar =========================================
__global__ void k_final(float* __restrict__ out) {
    const int tid = threadIdx.x;
    __shared__ float lsm[200];
    __shared__ float bscore[8];
    if (tid < 200) {
        int blk = tid / 25, rem = tid % 25, i = rem / 5, sb = rem % 5;
        int gi = blk * 5 + i;
        float s2 = 0.f;
        #pragma unroll
        for (int m = 0; m < 8; m++) s2 += __expf(g_logit2[((size_t)gi * 8 + m) * 5 + sb]);
        float s1 = 0.f;
        #pragma unroll
        for (int l = 0; l < 15; l++) s1 += g_el[gi * 75 + sb * 15 + l];
        float l1 = __logf(__powf(s1, 0.2f) + EPSL);
        float l2 = __logf(__powf(s2, 0.2f) + EPSL);
        lsm[tid] = 10.0f * (l1 + l2);
    }
    __syncthreads();
    if (tid < 8) {
        const float* L = lsm + tid * 25;
        float rows[5] = {0, 0, 0, 0, 0}, cols[5] = {0, 0, 0, 0, 0};
        for (int i = 0; i < 5; i++)
            for (int sb = 0; sb < 5; sb++) {
                rows[i] += L[i * 5 + sb];
                cols[sb] += L[i * 5 + sb];
            }
        float acc = 0.f;
        for (int i = 0; i < 5; i++) {
            float dg = L[i * 5 + i];
            acc += -__logf(dg / rows[i] + EPSL) - __logf(dg / cols[i] + EPSL);
        }
        float reg = 0.f;
        for (int i = 0; i < 5; i++) reg += g_regval[tid * 5 + i];
        bscore[tid] = acc / 5.0f + reg / 5.0f;
    }
    __syncthreads();
    if (tid == 0) {
        float tot = 0.f;
        for (int k = 0; k < 8; k++) tot += bscore[k];
        out[0] = tot / 9.0f;
    }
}

// ---------------- launch -----------------------------------------------------
extern "C" void kernel_launch(void* const* d_in, const int* in_sizes, int n_in,
                              void* d_out, int out_size) {
    (void)in_sizes; (void)n_in; (void)out_size;
    const float* image = (const float*)d_in[0];
    const float* text  = (const float*)d_in[1];
    float* out = (float*)d_out;

    cudaFuncSetAttribute(k_phase1, cudaFuncAttributeMaxDynamicSharedMemorySize, P1_SZ);
    cudaFuncSetAttribute(k_vtidal, cudaFuncAttributeMaxDynamicSharedMemorySize, P3_SZ);

    k_prep<<<300, 256>>>(text);
    k_phase1<<<960, 256, P1_SZ>>>(image, text);
    k_colstats<<<dim3(75, 40), 256>>>();
    k_vtidal<<<640, 256, P3_SZ>>>(image);
    k_tail<<<735, 256>>>(text);
    k_final<<<1, 256>>>(out);
}

// round 9
// speedup vs baseline: 2.6527x; 1.0363x over previous
#include <cuda_runtime.h>
#include <cuda_bf16.h>
#include <math.h>
#include <stdint.h>

#define G1 4.0f
#define EPSL 1e-10f

// ---------------- scratch (device globals) ----------------------------------
__device__ float    g_sT[40u*75u*2048u];      // [b][t][r]: s scores
__device__ float    g_rowstats[40u*2048u*5u*2u];
__device__ float    g_cinv_nt[40*75];
__device__ float    g_sd[40*8*75];
__device__ uint32_t g_aH[40u*75u*1024u];      // alpha numerators, bf16-hi pairs
__device__ uint32_t g_aL[40u*75u*1024u];      // alpha numerators, bf16-lo pairs
__device__ uint32_t g_eh[8*75*128];           // text bf16-hi pairs
__device__ uint32_t g_el2[8*75*128];          // text bf16-lo pairs
__device__ float    g_vtp[8u*40u*75u*256u];   // split-K partials of v_tidal
__device__ float    g_vns[40*8*256];
__device__ float    g_el[40*75];
__device__ float    g_logit2[40*8*5];
__device__ float    g_regval[40];

// ---------------- helpers ----------------------------------------------------
__device__ __forceinline__ uint32_t s2u(const void* p) {
    uint32_t a;
    asm("{ .reg .u64 t; cvta.to.shared.u64 t, %1; cvt.u32.u64 %0, t; }" : "=r"(a) : "l"(p));
    return a;
}
__device__ __forceinline__ void cp16(uint32_t dst, const void* src) {
    asm volatile("cp.async.cg.shared.global [%0], [%1], 16;" :: "r"(dst), "l"(src));
}
__device__ __forceinline__ void cp_commit() { asm volatile("cp.async.commit_group;" ::: "memory"); }
__device__ __forceinline__ void cp_wait0()  { asm volatile("cp.async.wait_group 0;" ::: "memory"); }

__device__ __forceinline__ void ldm_x4(uint32_t& r0, uint32_t& r1, uint32_t& r2,
                                       uint32_t& r3, uint32_t addr) {
    asm volatile("ldmatrix.sync.aligned.m8n8.x4.shared.b16 {%0,%1,%2,%3}, [%4];"
                 : "=r"(r0), "=r"(r1), "=r"(r2), "=r"(r3) : "r"(addr));
}
__device__ __forceinline__ void mma_bf16(float* c, uint32_t a0, uint32_t a1,
                                         uint32_t a2, uint32_t a3,
                                         uint32_t b0, uint32_t b1) {
    asm volatile(
        "mma.sync.aligned.m16n8k16.row.col.f32.bf16.bf16.f32 "
        "{%0,%1,%2,%3}, {%4,%5,%6,%7}, {%8,%9}, {%0,%1,%2,%3};"
        : "+f"(c[0]), "+f"(c[1]), "+f"(c[2]), "+f"(c[3])
        : "r"(a0), "r"(a1), "r"(a2), "r"(a3), "r"(b0), "r"(b1));
}
// fast split: x,y -> packed bf16 hi + packed bf16 lo residual
__device__ __forceinline__ void bsplit2(float x, float y, uint32_t& hi, uint32_t& lo) {
    uint32_t h;
    asm("cvt.rn.bf16x2.f32 %0, %1, %2;" : "=r"(h) : "f"(y), "f"(x));
    float hx = __uint_as_float(h << 16);
    float hy = __uint_as_float(h & 0xFFFF0000u);
    float lx = x - hx, ly = y - hy;
    asm("cvt.rn.bf16x2.f32 %0, %1, %2;" : "=r"(lo) : "f"(ly), "f"(lx));
    hi = h;
}

// phase1: per-stage 33280 B: AH[128][20] @0 | AL @10240 | BH[80][20] @20480 | BL @26880
// TR fp32[32][132] @66560 ; total 83456
#define P1_ST  33280
#define P1_TR  66560
#define P1_SZ  83456
// vtidal: per-stage 33280 B: AH[80][20] @0 | AL @6400 | BH[128][20] @12800 | BL @23040
#define P3_ST  33280
#define P3_SZ  66560

// ============ PHASE 0: convert text to bf16 hi/lo pairs =====================
__global__ void __launch_bounds__(256) k_prep(const float* __restrict__ text) {
    int i = blockIdx.x * 256 + threadIdx.x;   // 76800 pairs
    float2 v = *(const float2*)(text + 2 * i);
    uint32_t h, l;
    bsplit2(v.x, v.y, h, l);
    g_eh[i] = h; g_el2[i] = l;
}

// ============ PHASE 1: pipelined mma gemm_s (640 blks) + vns (320) ==========
__global__ void __launch_bounds__(256) k_phase1(const float* __restrict__ image,
                                                const float* __restrict__ text) {
    extern __shared__ __align__(16) char dsm[];
    const int bx = blockIdx.x;
    const int tid = threadIdx.x;
    const int wid = tid >> 5, lane = tid & 31;

    if (bx < 640) {
        const int b  = bx >> 4;
        const int rb = bx & 15;
        const int r0 = rb * 128;
        const int m  = rb >> 1, p0 = (rb & 1) * 128;
        const float* srcA = image + (size_t)(b * 8 + m) * 65536;
        const uint32_t* eH = g_eh  + (size_t)(b / 5) * 9600;
        const uint32_t* eL = g_el2 + (size_t)(b / 5) * 9600;
        const uint32_t sbase = s2u(dsm);
        float* TR = (float*)(dsm + P1_TR);
        const int gid = lane >> 2, tig = lane & 3;

        // zero B pad rows 75..79 in both stages
        for (int i = tid; i < 100; i += 256) {
            #pragma unroll
            for (int s = 0; s < 2; s++) {
                *(uint32_t*)(dsm + s * P1_ST + 20480 + (1500 + i) * 4) = 0;
                *(uint32_t*)(dsm + s * P1_ST + 26880 + (1500 + i) * 4) = 0;
            }
        }

        float4 iv[4];
        auto load_a = [&](int c) {
            const int kb = c * 32;
            #pragma unroll
            for (int it = 0; it < 4; it++) {
                int lin = tid + it * 256;
                int k = lin >> 5, f4 = (lin & 31) * 4;
                iv[it] = *(const float4*)(srcA + (size_t)(kb + k) * 256 + p0 + f4);
            }
        };
        auto store_tr = [&]() {
            #pragma unroll
            for (int it = 0; it < 4; it++) {
                int lin = tid + it * 256;
                int k = lin >> 5, f4 = (lin & 31) * 4;
                *(float4*)(TR + k * 132 + f4) = iv[it];
            }
        };
        auto conv_a = [&](int s) {
            uint32_t* AH = (uint32_t*)(dsm + s * P1_ST);
            uint32_t* AL = (uint32_t*)(dsm + s * P1_ST + 10240);
            const int r = tid >> 1, kh = (tid & 1) * 16;
            #pragma unroll
            for (int j = 0; j < 16; j += 2) {
                float x0 = TR[(kh + j) * 132 + r];
                float x1 = TR[(kh + j + 1) * 132 + r];
                uint32_t hi, lo;
                bsplit2(x0, x1, hi, lo);
                int w0 = r * 20 + ((kh + j) >> 1);
                AH[w0] = hi; AL[w0] = lo;
            }
        };
        auto stage_b = [&](int c, int s) {
            const int kw = c * 16;
            #pragma unroll
            for (int i = 0; i < 3; i++) {
                int idx = tid + i * 256;
                if (idx < 600) {
                    int half = (idx >= 300) ? 1 : 0;
                    int j = idx - half * 300;
                    int t = j >> 2, c4 = (j & 3) * 4;
                    const uint32_t* src = (half ? eL : eH) + t * 128 + kw + c4;
                    cp16(sbase + s * P1_ST + 20480 + half * 6400 + (t * 20 + c4) * 4, src);
                }
            }
            cp_commit();
        };

        float acc[10][4];
        #pragma unroll
        for (int nt = 0; nt < 10; nt++)
            #pragma unroll
            for (int q = 0; q < 4; q++) acc[nt][q] = 0.f;

        // ldmatrix address bases
        const uint32_t aoff0 = (uint32_t)((wid * 16 + (lane & 15)) * 80 + (lane >> 4) * 16);
        const uint32_t boff0 = (uint32_t)((((lane >> 4) & 1) * 8 + (lane & 7)) * 80
                                          + ((lane >> 3) & 1) * 16);

        // prologue: chunk 0
        load_a(0);
        stage_b(0, 0);
        store_tr();
        __syncthreads();
        conv_a(0);
        cp_wait0();
        __syncthreads();

        for (int c = 0; c < 8; c++) {
            const int s = c & 1;
            if (c < 7) { load_a(c + 1); stage_b(c + 1, s ^ 1); }
            // ---- mma on stage s (ldmatrix fragments) ---------------------
            {
                const uint32_t pAH = sbase + s * P1_ST;
                const uint32_t pAL = pAH + 10240;
                const uint32_t pBH = pAH + 20480;
                const uint32_t pBL = pAH + 26880;
                #pragma unroll
                for (int ks = 0; ks < 2; ks++) {
                    uint32_t ah0, ah1, ah2, ah3, al0, al1, al2, al3;
                    ldm_x4(ah0, ah1, ah2, ah3, pAH + aoff0 + ks * 32);
                    ldm_x4(al0, al1, al2, al3, pAL + aoff0 + ks * 32);
                    #pragma unroll
                    for (int j = 0; j < 5; j++) {
                        uint32_t bh0, bh1, bh2, bh3, bl0, bl1, bl2, bl3;
                        uint32_t bo = boff0 + (uint32_t)(j * 16 * 80 + ks * 32);
                        ldm_x4(bh0, bh1, bh2, bh3, pBH + bo);
                        ldm_x4(bl0, bl1, bl2, bl3, pBL + bo);
                        mma_bf16(acc[2 * j],     ah0, ah1, ah2, ah3, bh0, bh1);
                        mma_bf16(acc[2 * j],     ah0, ah1, ah2, ah3, bl0, bl1);
                        mma_bf16(acc[2 * j],     al0, al1, al2, al3, bh0, bh1);
                        mma_bf16(acc[2 * j + 1], ah0, ah1, ah2, ah3, bh2, bh3);
                        mma_bf16(acc[2 * j + 1], ah0, ah1, ah2, ah3, bl2, bl3);
                        mma_bf16(acc[2 * j + 1], al0, al1, al2, al3, bh2, bh3);
                    }
                }
            }
            if (c < 7) {
                store_tr();
                __syncthreads();
                conv_a(s ^ 1);
                cp_wait0();
            }
            __syncthreads();
        }
        // ---- epilogue: stage C to sc[t][132 r] --------------------------
        float* sc = (float*)dsm;
        const int rA = wid * 16 + gid;
        #pragma unroll
        for (int nt = 0; nt < 10; nt++) {
            int t0 = nt * 8 + tig * 2;
            sc[t0 * 132 + rA]           = acc[nt][0];
            sc[(t0 + 1) * 132 + rA]     = acc[nt][1];
            sc[t0 * 132 + rA + 8]       = acc[nt][2];
            sc[(t0 + 1) * 132 + rA + 8] = acc[nt][3];
        }
        __syncthreads();
        if (tid < 128) {
            const int r = tid;
            #pragma unroll
            for (int seg = 0; seg < 5; seg++) {
                float mx = -3.4e38f;
                #pragma unroll
                for (int l = 0; l < 15; l++)
                    mx = fmaxf(mx, sc[(seg * 15 + l) * 132 + r]);
                float se = 0.f;
                #pragma unroll
                for (int l = 0; l < 15; l++)
                    se += __expf(sc[(seg * 15 + l) * 132 + r] - mx);
                size_t ridx = ((size_t)b * 2048 + r0 + r) * 5 + seg;
                g_rowstats[ridx * 2]     = mx;
                g_rowstats[ridx * 2 + 1] = 1.0f / se;
            }
        }
        for (int i = tid; i < 9600; i += 256) {
            int t = i >> 7, r = i & 127;
            g_sT[((size_t)b * 75 + t) * 2048 + r0 + r] = sc[t * 132 + r];
        }
    } else {
        // -------- vns from image directly ------------------------------------
        const int bm = bx - 640;
        const float* src = image + (size_t)bm * 65536;
        float* invn = (float*)dsm;
        float s0 = 0.f, s1 = 0.f, s2 = 0.f, s3 = 0.f;
        for (int d = 0; d < 256; d += 4) {
            float x0 = src[(size_t)(d + 0) * 256 + tid];
            float x1 = src[(size_t)(d + 1) * 256 + tid];
            float x2 = src[(size_t)(d + 2) * 256 + tid];
            float x3 = src[(size_t)(d + 3) * 256 + tid];
            s0 = fmaf(x0, x0, s0); s1 = fmaf(x1, x1, s1);
            s2 = fmaf(x2, x2, s2); s3 = fmaf(x3, x3, s3);
        }
        invn[tid] = 1.0f / fmaxf(sqrtf((s0 + s1) + (s2 + s3)), 1e-12f);
        __syncthreads();
        for (int j = 0; j < 32; j++) {
            int d = wid * 32 + j;
            const float* row = src + (size_t)d * 256;
            float a = 0.f;
            #pragma unroll
            for (int q = 0; q < 8; q++) {
                int p = lane + 32 * q;
                a = fmaf(row[p], invn[p], a);
            }
            #pragma unroll
            for (int o = 16; o > 0; o >>= 1) a += __shfl_xor_sync(0xffffffffu, a, o);
            if (lane == 0) g_vns[(size_t)bm * 256 + d] = a;
        }
    }
}

// ============ PHASE 2: column stats + sd + packed bf16 alpha =================
__global__ void __launch_bounds__(256) k_colstats() {
    const int t = blockIdx.x, b = blockIdx.y, seg = t / 15;
    const int tid = threadIdx.x, lane = tid & 31, w = tid >> 5;
    const float* col = g_sT + ((size_t)b * 75 + t) * 2048;
    __shared__ float sred[24];

    float vals[8];
    *(float4*)vals       = *(const float4*)(col + tid * 8);
    *(float4*)(vals + 4) = *(const float4*)(col + tid * 8 + 4);

    float mx = vals[0];
    #pragma unroll
    for (int k = 1; k < 8; k++) mx = fmaxf(mx, vals[k]);
    #pragma unroll
    for (int o = 16; o > 0; o >>= 1) mx = fmaxf(mx, __shfl_xor_sync(0xffffffffu, mx, o));
    if (lane == 0) sred[w] = mx;
    __syncthreads();
    float cmax = sred[0];
    #pragma unroll
    for (int q = 1; q < 8; q++) cmax = fmaxf(cmax, sred[q]);

    float e1[8], al[8];
    float sraw = 0.f, snt = 0.f;
    const float* rsb = g_rowstats + (((size_t)b * 2048 + tid * 8) * 5 + seg) * 2;
    #pragma unroll
    for (int k = 0; k < 8; k++) {
        e1[k] = __expf(vals[k] - cmax);
        sraw += e1[k];
        float2 rs = *(const float2*)(rsb + k * 10);
        al[k] = __expf(G1 * __expf(vals[k] - rs.x) * rs.y);
        snt += al[k];
    }
    {
        uint32_t* aH = g_aH + (size_t)b * 76800 + t * 1024 + tid * 4;
        uint32_t* aL = g_aL + (size_t)b * 76800 + t * 1024 + tid * 4;
        #pragma unroll
        for (int j = 0; j < 4; j++) {
            uint32_t h, l;
            bsplit2(al[2 * j], al[2 * j + 1], h, l);
            aH[j] = h; aL[j] = l;
        }
    }
    float sr = sraw, sn = snt;
    #pragma unroll
    for (int o = 16; o > 0; o >>= 1) {
        sr += __shfl_xor_sync(0xffffffffu, sr, o);
        sn += __shfl_xor_sync(0xffffffffu, sn, o);
    }
    if (lane == 0) { sred[8 + w] = sr; sred[16 + w] = sn; }
    __syncthreads();
    float tot = 0.f;
    #pragma unroll
    for (int q = 0; q < 8; q++) tot += sred[8 + q];
    const float cinv = 1.0f / tot;
    if (tid == 0) {
        float s = 0.f;
        #pragma unroll
        for (int q = 0; q < 8; q++) s += sred[16 + q];
        g_cinv_nt[b * 75 + t] = 1.0f / s;
    }
    float e2 = 0.f;
    #pragma unroll
    for (int k = 0; k < 8; k++) e2 += __expf(e1[k] * cinv);
    #pragma unroll
    for (int o = 16; o > 0; o >>= 1) e2 += __shfl_xor_sync(0xffffffffu, e2, o);
    if (lane == 0) g_sd[((size_t)b * 8 + w) * 75 + t] = e2;
}

// ============ PHASE 3: pipelined mma v_tidal (640 blocks) ====================
__global__ void __launch_bounds__(256) k_vtidal(const float* __restrict__ image) {
    extern __shared__ __align__(16) char dsm[];
    __shared__ float scv[80];
    const int tid = threadIdx.x;
    const int wid = tid >> 5, lane = tid & 31;
    const int b  = blockIdx.x >> 4;
    const int kz = (blockIdx.x >> 1) & 7;
    const int nh = blockIdx.x & 1;
    const int gid = lane >> 2, tig = lane & 3;
    const uint32_t sbase = s2u(dsm);
    const uint32_t* aHg = g_aH + (size_t)b * 76800;
    const uint32_t* aLg = g_aL + (size_t)b * 76800;
    const float* srcB = image + (size_t)(b * 8 + kz) * 65536 + (size_t)(nh * 128) * 256;

    if (tid < 75) scv[tid] = g_cinv_nt[b * 75 + tid];
    // zero A pad rows 75..79 in both stages
    for (int i = tid; i < 100; i += 256) {
        #pragma unroll
        for (int s = 0; s < 2; s++) {
            *(uint32_t*)(dsm + s * P3_ST +        (1500 + i) * 4) = 0;
            *(uint32_t*)(dsm + s * P3_ST + 6400 + (1500 + i) * 4) = 0;
        }
    }

    auto stage_a = [&](int c, int s) {
        const int rgw = (kz * 256 + c * 32) >> 1;
        #pragma unroll
        for (int i = 0; i < 3; i++) {
            int idx = tid + i * 256;
            if (idx < 600) {
                int half = (idx >= 300) ? 1 : 0;
                int j = idx - half * 300;
                int t = j >> 2, c4 = (j & 3) * 4;
                const uint32_t* src = (half ? aLg : aHg) + t * 1024 + rgw + c4;
                cp16(sbase + s * P3_ST + half * 6400 + (t * 20 + c4) * 4, src);
            }
        }
        cp_commit();
    };

    float4 vb[4];
    auto load_b = [&](int c) {
        const int p0 = c * 32;
        #pragma unroll
        for (int it = 0; it < 4; it++) {
            int idx = tid + it * 256;
            int d = idx >> 3, c4 = (idx & 7) * 4;
            vb[it] = *(const float4*)(srcB + (size_t)d * 256 + p0 + c4);
        }
    };
    auto store_b = [&](int s) {
        uint32_t* BH = (uint32_t*)(dsm + s * P3_ST + 12800);
        uint32_t* BL = (uint32_t*)(dsm + s * P3_ST + 23040);
        #pragma unroll
        for (int it = 0; it < 4; it++) {
            int idx = tid + it * 256;
            int d = idx >> 3, c4 = (idx & 7) * 4;
            uint32_t h0, l0, h1, l1;
            bsplit2(vb[it].x, vb[it].y, h0, l0);
            bsplit2(vb[it].z, vb[it].w, h1, l1);
            int w0 = d * 20 + (c4 >> 1);
            BH[w0] = h0; BH[w0 + 1] = h1;
            BL[w0] = l0; BL[w0 + 1] = l1;
        }
    };

    float acc[5][2][4];
    #pragma unroll
    for (int mt = 0; mt < 5; mt++)
        #pragma unroll
        for (int nt = 0; nt < 2; nt++)
            #pragma unroll
            for (int q = 0; q < 4; q++) acc[mt][nt][q] = 0.f;

    // prologue: chunk 0
    stage_a(0, 0);
    load_b(0);
    store_b(0);
    cp_wait0();
    __syncthreads();

    const int n0 = wid * 16;
    const uint32_t aoffb = (uint32_t)((lane & 15) * 80 + (lane >> 4) * 16);
    const uint32_t boff0 = (uint32_t)((n0 + ((lane >> 4) & 1) * 8 + (lane & 7)) * 80
                                      + ((lane >> 3) & 1) * 16);

    for (int c = 0; c < 8; c++) {
        const int s = c & 1;
        if (c < 7) { stage_a(c + 1, s ^ 1); load_b(c + 1); }
        // ---- mma on stage s (ldmatrix fragments) -------------------------
        {
            const uint32_t pAH = sbase + s * P3_ST;
            const uint32_t pAL = pAH + 6400;
            const uint32_t pBH = pAH + 12800;
            const uint32_t pBL = pAH + 23040;
            #pragma unroll
            for (int ks = 0; ks < 2; ks++) {
                uint32_t bh0, bh1, bh2, bh3, bl0, bl1, bl2, bl3;
                ldm_x4(bh0, bh1, bh2, bh3, pBH + boff0 + ks * 32);
                ldm_x4(bl0, bl1, bl2, bl3, pBL + boff0 + ks * 32);
                #pragma unroll
                for (int mt = 0; mt < 5; mt++) {
                    uint32_t ah0, ah1, ah2, ah3, al0, al1, al2, al3;
                    uint32_t ao = aoffb + (uint32_t)(mt * 16 * 80 + ks * 32);
                    ldm_x4(ah0, ah1, ah2, ah3, pAH + ao);
                    ldm_x4(al0, al1, al2, al3, pAL + ao);
                    mma_bf16(acc[mt][0], ah0, ah1, ah2, ah3, bh0, bh1);
                    mma_bf16(acc[mt][0], ah0, ah1, ah2, ah3, bl0, bl1);
                    mma_bf16(acc[mt][0], al0, al1, al2, al3, bh0, bh1);
                    mma_bf16(acc[mt][1], ah0, ah1, ah2, ah3, bh2, bh3);
                    mma_bf16(acc[mt][1], ah0, ah1, ah2, ah3, bl2, bl3);
                    mma_bf16(acc[mt][1], al0, al1, al2, al3, bh2, bh3);
                }
            }
        }
        if (c < 7) { store_b(s ^ 1); cp_wait0(); }
        __syncthreads();
    }
    // ---- epilogue: scale by cinv[t], write split-K partials -----------------
    float* outp = g_vtp + (size_t)kz * 40 * 75 * 256 + (size_t)b * 75 * 256 + nh * 128;
    #pragma unroll
    for (int mt = 0; mt < 5; mt++) {
        int t = mt * 16 + gid;
        #pragma unroll
        for (int nt = 0; nt < 2; nt++) {
            int d = n0 + nt * 8 + tig * 2;
            if (t < 75) {
                float ci = scv[t];
                float2 v0 = {acc[mt][nt][0] * ci, acc[mt][nt][1] * ci};
                *(float2*)(outp + (size_t)t * 256 + d) = v0;
            }
            if (t + 8 < 75) {
                float ci = scv[t + 8];
                float2 v1 = {acc[mt][nt][2] * ci, acc[mt][nt][3] * ci};
                *(float2*)(outp + (size_t)(t + 8) * 256 + d) = v1;
            }
        }
    }
}

// ============ PHASE 4: tail = logit2 (320) + reg (40) + score1 (375) ========
__global__ void __launch_bounds__(256) k_tail(const float* __restrict__ text) {
    __shared__ __align__(16) float pool[1500];
    const int bx = blockIdx.x;
    const int tid = threadIdx.x;
    const int lane = tid & 31, w = tid >> 5;

    if (bx < 320) {
        const int b = bx >> 3, m = bx & 7, blk = b / 5;
        float* shsd = pool;
        float* wred = pool + 16;
        const float vv = g_vns[((size_t)b * 8 + m) * 256 + tid];
        for (int sb = 0; sb < 5; sb++) {
            if (tid < 15) shsd[tid] = g_sd[((size_t)b * 8 + m) * 75 + sb * 15 + tid];
            __syncthreads();
            float segsum = 0.f;
            #pragma unroll
            for (int l = 0; l < 15; l++) segsum += shsd[l];
            float em = 0.f;
            #pragma unroll
            for (int l = 0; l < 15; l++)
                em = fmaf(shsd[l], text[((size_t)blk * 75 + sb * 15 + l) * 256 + tid], em);
            em /= segsum;
            float p = em * em, q = em * vv;
            #pragma unroll
            for (int o = 16; o > 0; o >>= 1) {
                p += __shfl_xor_sync(0xffffffffu, p, o);
                q += __shfl_xor_sync(0xffffffffu, q, o);
            }
            if (lane == 0) { wred[w] = p; wred[8 + w] = q; }
            __syncthreads();
            if (tid == 0) {
                float s1 = 0.f, s2 = 0.f;
                #pragma unroll
                for (int j = 0; j < 8; j++) { s1 += wred[j]; s2 += wred[8 + j]; }
                g_logit2[((size_t)b * 8 + m) * 5 + sb] =
                    s2 / (fmaxf(sqrtf(s1), 1e-12f) * 256.0f);
            }
            __syncthreads();
        }
    } else if (bx < 360) {
        const int b = bx - 320;
        float* ssd   = pool;
        float* sseg  = pool + 600;
        float* sbeta = pool + 640;
        float* red   = pool + 1240;
        for (int i = tid; i < 600; i += 256) ssd[i] = g_sd[(size_t)b * 600 + i];
        __syncthreads();
        if (tid < 40) {
            int m = tid / 5, sb2 = tid % 5;
            float s = 0.f;
            for (int l = 0; l < 15; l++) s += ssd[m * 75 + sb2 * 15 + l];
            sseg[tid] = s;
        }
        __syncthreads();
        for (int i = tid; i < 600; i += 256) {
            int m = i / 75, t = i % 75;
            sbeta[i] = ssd[i] / sseg[m * 5 + t / 15];
        }
        __syncthreads();
        float p = 0.f;
        if (tid < 64) {
            int m = tid >> 3, n = tid & 7;
            if (m != n) {
                float a = 0.f;
                for (int t = 0; t < 75; t++) a = fmaf(sbeta[m * 75 + t], sbeta[n * 75 + t], a);
                p = a * a;
            }
        }
        red[tid] = p; __syncthreads();
        for (int o = 128; o > 0; o >>= 1) { if (tid < o) red[tid] += red[tid + o]; __syncthreads(); }
        if (tid == 0) g_regval[b] = sqrtf(red[0]);
    } else {
        const int gt = (bx - 360) * 8 + w;
        if (gt < 3000) {
            const int b = gt / 75, t = gt % 75, blk = b / 5;
            const size_t SL = (size_t)40 * 75 * 256;
            const size_t voff = ((size_t)b * 75 + t) * 256;
            const float* e = text + ((size_t)blk * 75 + t) * 256;
            float dot = 0.f, nv = 0.f, ne = 0.f;
            #pragma unroll
            for (int j = 0; j < 8; j++) {
                int d = lane + 32 * j;
                float a = 0.f;
                #pragma unroll
                for (int s8 = 0; s8 < 8; s8++) a += g_vtp[s8 * SL + voff + d];
                float cc = e[d];
                dot = fmaf(a, cc, dot); nv = fmaf(a, a, nv); ne = fmaf(cc, cc, ne);
            }
            #pragma unroll
            for (int o = 16; o > 0; o >>= 1) {
                dot += __shfl_xor_sync(0xffffffffu, dot, o);
                nv  += __shfl_xor_sync(0xffffffffu, nv,  o);
                ne  += __shfl_xor_sync(0xffffffffu, ne,  o);
            }
            if (lane == 0)
                g_el[b * 75 + t] = __expf(dot / (fmaxf(sqrtf(nv), 1e-12f) * fmaxf(sqrtf(ne), 1e-12f)));
        }
    }
}

// ============ PHASE 5: final scalar =========================================
__global__ void k_final(float* __restrict__ out) {
    const int tid = threadIdx.x;
    __shared__ float lsm[200];
    __shared__ float bscore[8];
    if (tid < 200) {
        int blk = tid / 25, rem = tid % 25, i = rem / 5, sb = rem % 5;
        int gi = blk * 5 + i;
        float s2 = 0.f;
        #pragma unroll
        for (int m = 0; m < 8; m++) s2 += __expf(g_logit2[((size_t)gi * 8 + m) * 5 + sb]);
        float s1 = 0.f;
        #pragma unroll
        for (int l = 0; l < 15; l++) s1 += g_el[gi * 75 + sb * 15 + l];
        float l1 = __logf(__powf(s1, 0.2f) + EPSL);
        float l2 = __logf(__powf(s2, 0.2f) + EPSL);
        lsm[tid] = 10.0f * (l1 + l2);
    }
    __syncthreads();
    if (tid < 8) {
        const float* L = lsm + tid * 25;
        float rows[5] = {0, 0, 0, 0, 0}, cols[5] = {0, 0, 0, 0, 0};
        for (int i = 0; i < 5; i++)
            for (int sb = 0; sb < 5; sb++) {
                rows[i] += L[i * 5 + sb];
                cols[sb] += L[i * 5 + sb];
            }
        float acc = 0.f;
        for (int i = 0; i < 5; i++) {
            float dg = L[i * 5 + i];
            acc += -__logf(dg / rows[i] + EPSL) - __logf(dg / cols[i] + EPSL);
        }
        float reg = 0.f;
        for (int i = 0; i < 5; i++) reg += g_regval[tid * 5 + i];
        bscore[tid] = acc / 5.0f + reg / 5.0f;
    }
    __syncthreads();
    if (tid == 0) {
        float tot = 0.f;
        for (int k = 0; k < 8; k++) tot += bscore[k];
        out[0] = tot / 9.0f;
    }
}

// ---------------- launch -----------------------------------------------------
extern "C" void kernel_launch(void* const* d_in, const int* in_sizes, int n_in,
                              void* d_out, int out_size) {
    (void)in_sizes; (void)n_in; (void)out_size;
    const float* image = (const float*)d_in[0];
    const float* text  = (const float*)d_in[1];
    float* out = (float*)d_out;

    cudaFuncSetAttribute(k_phase1, cudaFuncAttributeMaxDynamicSharedMemorySize, P1_SZ);
    cudaFuncSetAttribute(k_vtidal, cudaFuncAttributeMaxDynamicSharedMemorySize, P3_SZ);

    k_prep<<<300, 256>>>(text);
    k_phase1<<<960, 256, P1_SZ>>>(image, text);
    k_colstats<<<dim3(75, 40), 256>>>();
    k_vtidal<<<640, 256, P3_SZ>>>(image);
    k_tail<<<735, 256>>>(text);
    k_final<<<1, 256>>>(out);
}

// round 10
// speedup vs baseline: 2.8724x; 1.0828x over previous
#include <cuda_runtime.h>
#include <cuda_bf16.h>
#include <math.h>
#include <stdint.h>

#define G1 4.0f
#define EPSL 1e-10f

// ---------------- scratch (device globals) ----------------------------------
__device__ float    g_sT[40u*75u*2048u];      // [b][t][r]: s scores
__device__ float    g_rowstats[40u*2048u*5u*2u];
__device__ float    g_cinv_nt[40*75];
__device__ float    g_sd[40*8*75];
__device__ uint32_t g_aH[40u*75u*1024u];      // alpha numerators, bf16-hi pairs
__device__ uint32_t g_aL[40u*75u*1024u];      // alpha numerators, bf16-lo pairs
__device__ uint32_t g_eh[8*75*128];           // text bf16-hi pairs
__device__ uint32_t g_el2[8*75*128];          // text bf16-lo pairs
__device__ float    g_vtp[8u*40u*75u*256u];   // split-K partials of v_tidal
__device__ float    g_vns[40*8*256];
__device__ float    g_el[40*75];
__device__ float    g_logit2[40*8*5];
__device__ float    g_regval[40];

// ---------------- helpers ----------------------------------------------------
__device__ __forceinline__ uint32_t s2u(const void* p) {
    uint32_t a;
    asm("{ .reg .u64 t; cvta.to.shared.u64 t, %1; cvt.u32.u64 %0, t; }" : "=r"(a) : "l"(p));
    return a;
}
__device__ __forceinline__ void cp16(uint32_t dst, const void* src) {
    asm volatile("cp.async.cg.shared.global [%0], [%1], 16;" :: "r"(dst), "l"(src));
}
__device__ __forceinline__ void cp_commit() { asm volatile("cp.async.commit_group;" ::: "memory"); }
__device__ __forceinline__ void cp_wait0()  { asm volatile("cp.async.wait_group 0;" ::: "memory"); }

__device__ __forceinline__ void ldm_x4(uint32_t& r0, uint32_t& r1, uint32_t& r2,
                                       uint32_t& r3, uint32_t addr) {
    asm volatile("ldmatrix.sync.aligned.m8n8.x4.shared.b16 {%0,%1,%2,%3}, [%4];"
                 : "=r"(r0), "=r"(r1), "=r"(r2), "=r"(r3) : "r"(addr));
}
__device__ __forceinline__ void ldm_x4_t(uint32_t& r0, uint32_t& r1, uint32_t& r2,
                                         uint32_t& r3, uint32_t addr) {
    asm volatile("ldmatrix.sync.aligned.m8n8.x4.trans.shared.b16 {%0,%1,%2,%3}, [%4];"
                 : "=r"(r0), "=r"(r1), "=r"(r2), "=r"(r3) : "r"(addr));
}
__device__ __forceinline__ void mma_bf16(float* c, uint32_t a0, uint32_t a1,
                                         uint32_t a2, uint32_t a3,
                                         uint32_t b0, uint32_t b1) {
    asm volatile(
        "mma.sync.aligned.m16n8k16.row.col.f32.bf16.bf16.f32 "
        "{%0,%1,%2,%3}, {%4,%5,%6,%7}, {%8,%9}, {%0,%1,%2,%3};"
        : "+f"(c[0]), "+f"(c[1]), "+f"(c[2]), "+f"(c[3])
        : "r"(a0), "r"(a1), "r"(a2), "r"(a3), "r"(b0), "r"(b1));
}
// fast split: x,y -> packed bf16 hi + packed bf16 lo residual
__device__ __forceinline__ void bsplit2(float x, float y, uint32_t& hi, uint32_t& lo) {
    uint32_t h;
    asm("cvt.rn.bf16x2.f32 %0, %1, %2;" : "=r"(h) : "f"(y), "f"(x));
    float hx = __uint_as_float(h << 16);
    float hy = __uint_as_float(h & 0xFFFF0000u);
    float lx = x - hx, ly = y - hy;
    asm("cvt.rn.bf16x2.f32 %0, %1, %2;" : "=r"(lo) : "f"(ly), "f"(lx));
    hi = h;
}

// phase1 per-stage 30208 B: AH[32 k][272 B] @0 | AL @8704 | BH[80][20w] @17408 | BL @23808
#define P1_ST  30208
#define P1_SZ  60416
// vtidal: per-stage 33280 B: AH[80][20] @0 | AL @6400 | BH[128][20] @12800 | BL @23040
#define P3_ST  33280
#define P3_SZ  66560

// ============ PHASE 0: convert text to bf16 hi/lo pairs =====================
__global__ void __launch_bounds__(256) k_prep(const float* __restrict__ text) {
    int i = blockIdx.x * 256 + threadIdx.x;   // 76800 pairs
    float2 v = *(const float2*)(text + 2 * i);
    uint32_t h, l;
    bsplit2(v.x, v.y, h, l);
    g_eh[i] = h; g_el2[i] = l;
}

// ============ PHASE 1: pipelined mma gemm_s (640 blks) + vns (320) ==========
__global__ void __launch_bounds__(256) k_phase1(const float* __restrict__ image,
                                                const float* __restrict__ text) {
    extern __shared__ __align__(16) char dsm[];
    const int bx = blockIdx.x;
    const int tid = threadIdx.x;
    const int wid = tid >> 5, lane = tid & 31;

    if (bx < 640) {
        const int b  = bx >> 4;
        const int rb = bx & 15;
        const int r0 = rb * 128;
        const int m  = rb >> 1, p0 = (rb & 1) * 128;
        const float* srcA = image + (size_t)(b * 8 + m) * 65536;
        const uint32_t* eH = g_eh  + (size_t)(b / 5) * 9600;
        const uint32_t* eL = g_el2 + (size_t)(b / 5) * 9600;
        const uint32_t sbase = s2u(dsm);
        const int gid = lane >> 2, tig = lane & 3;

        // zero B pad rows 75..79 in both stages
        for (int i = tid; i < 100; i += 256) {
            #pragma unroll
            for (int s = 0; s < 2; s++) {
                *(uint32_t*)(dsm + s * P1_ST + 17408 + (1500 + i) * 4) = 0;
                *(uint32_t*)(dsm + s * P1_ST + 23808 + (1500 + i) * 4) = 0;
            }
        }

        float4 iv[4];
        auto load_a = [&](int c) {
            const int kb = c * 32;
            #pragma unroll
            for (int it = 0; it < 4; it++) {
                int lin = tid + it * 256;
                int k = lin >> 5, f4 = (lin & 31) * 4;
                iv[it] = *(const float4*)(srcA + (size_t)(kb + k) * 256 + p0 + f4);
            }
        };
        // convert in regs, store bf16 hi/lo to [k][p] tile (272 B rows)
        auto store_a = [&](int s) {
            char* AH = dsm + s * P1_ST;
            char* AL = AH + 8704;
            #pragma unroll
            for (int it = 0; it < 4; it++) {
                int lin = tid + it * 256;
                int k = lin >> 5, p4 = (lin & 31) * 4;
                uint32_t h0, l0, h1, l1;
                bsplit2(iv[it].x, iv[it].y, h0, l0);
                bsplit2(iv[it].z, iv[it].w, h1, l1);
                int off = k * 272 + p4 * 2;
                *(uint2*)(AH + off) = make_uint2(h0, h1);
                *(uint2*)(AL + off) = make_uint2(l0, l1);
            }
        };
        auto stage_b = [&](int c, int s) {
            const int kw = c * 16;
            #pragma unroll
            for (int i = 0; i < 3; i++) {
                int idx = tid + i * 256;
                if (idx < 600) {
                    int half = (idx >= 300) ? 1 : 0;
                    int j = idx - half * 300;
                    int t = j >> 2, c4 = (j & 3) * 4;
                    const uint32_t* src = (half ? eL : eH) + t * 128 + kw + c4;
                    cp16(sbase + s * P1_ST + 17408 + half * 6400 + (t * 20 + c4) * 4, src);
                }
            }
            cp_commit();
        };

        float acc[10][4];
        #pragma unroll
        for (int nt = 0; nt < 10; nt++)
            #pragma unroll
            for (int q = 0; q < 4; q++) acc[nt][q] = 0.f;

        // ldmatrix.trans A base: lanes -> k-rows, matrices -> (m-half, k-half)
        const uint32_t aoffT = (uint32_t)(((lane & 7) + ((lane >> 4) & 1) * 8) * 272
                                          + ((lane >> 3) & 1) * 16 + wid * 32);
        const uint32_t boff0 = (uint32_t)((((lane >> 4) & 1) * 8 + (lane & 7)) * 80
                                          + ((lane >> 3) & 1) * 16);

        // prologue: chunk 0
        load_a(0);
        stage_b(0, 0);
        store_a(0);
        cp_wait0();
        __syncthreads();

        for (int c = 0; c < 8; c++) {
            const int s = c & 1;
            if (c < 7) { load_a(c + 1); stage_b(c + 1, s ^ 1); }
            // ---- mma on stage s ------------------------------------------
            {
                const uint32_t pAH = sbase + s * P1_ST;
                const uint32_t pAL = pAH + 8704;
                const uint32_t pBH = pAH + 17408;
                const uint32_t pBL = pAH + 23808;
                #pragma unroll
                for (int ks = 0; ks < 2; ks++) {
                    uint32_t ah0, ah1, ah2, ah3, al0, al1, al2, al3;
                    ldm_x4_t(ah0, ah1, ah2, ah3, pAH + aoffT + ks * 4352);
                    ldm_x4_t(al0, al1, al2, al3, pAL + aoffT + ks * 4352);
                    #pragma unroll
                    for (int j = 0; j < 5; j++) {
                        uint32_t bh0, bh1, bh2, bh3, bl0, bl1, bl2, bl3;
                        uint32_t bo = boff0 + (uint32_t)(j * 16 * 80 + ks * 32);
                        ldm_x4(bh0, bh1, bh2, bh3, pBH + bo);
                        ldm_x4(bl0, bl1, bl2, bl3, pBL + bo);
                        mma_bf16(acc[2 * j],     ah0, ah1, ah2, ah3, bh0, bh1);
                        mma_bf16(acc[2 * j + 1], ah0, ah1, ah2, ah3, bh2, bh3);
                        mma_bf16(acc[2 * j],     ah0, ah1, ah2, ah3, bl0, bl1);
                        mma_bf16(acc[2 * j + 1], ah0, ah1, ah2, ah3, bl2, bl3);
                        mma_bf16(acc[2 * j],     al0, al1, al2, al3, bh0, bh1);
                        mma_bf16(acc[2 * j + 1], al0, al1, al2, al3, bh2, bh3);
                    }
                }
            }
            if (c < 7) { store_a(s ^ 1); cp_wait0(); }
            __syncthreads();
        }
        // ---- epilogue: stage C to sc[t][132 r] --------------------------
        float* sc = (float*)dsm;
        const int rA = wid * 16 + gid;
        #pragma unroll
        for (int nt = 0; nt < 10; nt++) {
            int t0 = nt * 8 + tig * 2;
            sc[t0 * 132 + rA]           = acc[nt][0];
            sc[(t0 + 1) * 132 + rA]     = acc[nt][1];
            sc[t0 * 132 + rA + 8]       = acc[nt][2];
            sc[(t0 + 1) * 132 + rA + 8] = acc[nt][3];
        }
        __syncthreads();
        if (tid < 128) {
            const int r = tid;
            #pragma unroll
            for (int seg = 0; seg < 5; seg++) {
                float mx = -3.4e38f;
                #pragma unroll
                for (int l = 0; l < 15; l++)
                    mx = fmaxf(mx, sc[(seg * 15 + l) * 132 + r]);
                float se = 0.f;
                #pragma unroll
                for (int l = 0; l < 15; l++)
                    se += __expf(sc[(seg * 15 + l) * 132 + r] - mx);
                size_t ridx = ((size_t)b * 2048 + r0 + r) * 5 + seg;
                g_rowstats[ridx * 2]     = mx;
                g_rowstats[ridx * 2 + 1] = 1.0f / se;
            }
        }
        for (int i = tid; i < 9600; i += 256) {
            int t = i >> 7, r = i & 127;
            g_sT[((size_t)b * 75 + t) * 2048 + r0 + r] = sc[t * 132 + r];
        }
    } else {
        // -------- vns from image directly ------------------------------------
        const int bm = bx - 640;
        const float* src = image + (size_t)bm * 65536;
        float* invn = (float*)dsm;
        float s0 = 0.f, s1 = 0.f, s2 = 0.f, s3 = 0.f;
        for (int d = 0; d < 256; d += 4) {
            float x0 = src[(size_t)(d + 0) * 256 + tid];
            float x1 = src[(size_t)(d + 1) * 256 + tid];
            float x2 = src[(size_t)(d + 2) * 256 + tid];
            float x3 = src[(size_t)(d + 3) * 256 + tid];
            s0 = fmaf(x0, x0, s0); s1 = fmaf(x1, x1, s1);
            s2 = fmaf(x2, x2, s2); s3 = fmaf(x3, x3, s3);
        }
        invn[tid] = 1.0f / fmaxf(sqrtf((s0 + s1) + (s2 + s3)), 1e-12f);
        __syncthreads();
        for (int j = 0; j < 32; j++) {
            int d = wid * 32 + j;
            const float* row = src + (size_t)d * 256;
            float a = 0.f;
            #pragma unroll
            for (int q = 0; q < 8; q++) {
                int p = lane + 32 * q;
                a = fmaf(row[p], invn[p], a);
            }
            #pragma unroll
            for (int o = 16; o > 0; o >>= 1) a += __shfl_xor_sync(0xffffffffu, a, o);
            if (lane == 0) g_vns[(size_t)bm * 256 + d] = a;
        }
    }
}

// ============ PHASE 2: column stats + sd + packed bf16 alpha =================
__global__ void __launch_bounds__(256) k_colstats() {
    const int t = blockIdx.x, b = blockIdx.y, seg = t / 15;
    const int tid = threadIdx.x, lane = tid & 31, w = tid >> 5;
    const float* col = g_sT + ((size_t)b * 75 + t) * 2048;
    __shared__ float sred[24];

    float vals[8];
    *(float4*)vals       = *(const float4*)(col + tid * 8);
    *(float4*)(vals + 4) = *(const float4*)(col + tid * 8 + 4);

    float mx = vals[0];
    #pragma unroll
    for (int k = 1; k < 8; k++) mx = fmaxf(mx, vals[k]);
    #pragma unroll
    for (int o = 16; o > 0; o >>= 1) mx = fmaxf(mx, __shfl_xor_sync(0xffffffffu, mx, o));
    if (lane == 0) sred[w] = mx;
    __syncthreads();
    float cmax = sred[0];
    #pragma unroll
    for (int q = 1; q < 8; q++) cmax = fmaxf(cmax, sred[q]);

    float e1[8], al[8];
    float sraw = 0.f, snt = 0.f;
    const float* rsb = g_rowstats + (((size_t)b * 2048 + tid * 8) * 5 + seg) * 2;
    #pragma unroll
    for (int k = 0; k < 8; k++) {
        e1[k] = __expf(vals[k] - cmax);
        sraw += e1[k];
        float2 rs = *(const float2*)(rsb + k * 10);
        al[k] = __expf(G1 * __expf(vals[k] - rs.x) * rs.y);
        snt += al[k];
    }
    {
        uint32_t* aH = g_aH + (size_t)b * 76800 + t * 1024 + tid * 4;
        uint32_t* aL = g_aL + (size_t)b * 76800 + t * 1024 + tid * 4;
        #pragma unroll
        for (int j = 0; j < 4; j++) {
            uint32_t h, l;
            bsplit2(al[2 * j], al[2 * j + 1], h, l);
            aH[j] = h; aL[j] = l;
        }
    }
    float sr = sraw, sn = snt;
    #pragma unroll
    for (int o = 16; o > 0; o >>= 1) {
        sr += __shfl_xor_sync(0xffffffffu, sr, o);
        sn += __shfl_xor_sync(0xffffffffu, sn, o);
    }
    if (lane == 0) { sred[8 + w] = sr; sred[16 + w] = sn; }
    __syncthreads();
    float tot = 0.f;
    #pragma unroll
    for (int q = 0; q < 8; q++) tot += sred[8 + q];
    const float cinv = 1.0f / tot;
    if (tid == 0) {
        float s = 0.f;
        #pragma unroll
        for (int q = 0; q < 8; q++) s += sred[16 + q];
        g_cinv_nt[b * 75 + t] = 1.0f / s;
    }
    float e2 = 0.f;
    #pragma unroll
    for (int k = 0; k < 8; k++) e2 += __expf(e1[k] * cinv);
    #pragma unroll
    for (int o = 16; o > 0; o >>= 1) e2 += __shfl_xor_sync(0xffffffffu, e2, o);
    if (lane == 0) g_sd[((size_t)b * 8 + w) * 75 + t] = e2;
}

// ============ PHASE 3: pipelined mma v_tidal (640 blocks) ====================
__global__ void __launch_bounds__(256) k_vtidal(const float* __restrict__ image) {
    extern __shared__ __align__(16) char dsm[];
    __shared__ float scv[80];
    const int tid = threadIdx.x;
    const int wid = tid >> 5, lane = tid & 31;
    const int b  = blockIdx.x >> 4;
    const int kz = (blockIdx.x >> 1) & 7;
    const int nh = blockIdx.x & 1;
    const int gid = lane >> 2, tig = lane & 3;
    const uint32_t sbase = s2u(dsm);
    const uint32_t* aHg = g_aH + (size_t)b * 76800;
    const uint32_t* aLg = g_aL + (size_t)b * 76800;
    const float* srcB = image + (size_t)(b * 8 + kz) * 65536 + (size_t)(nh * 128) * 256;

    if (tid < 75) scv[tid] = g_cinv_nt[b * 75 + tid];
    // zero A pad rows 75..79 in both stages
    for (int i = tid; i < 100; i += 256) {
        #pragma unroll
        for (int s = 0; s < 2; s++) {
            *(uint32_t*)(dsm + s * P3_ST +        (1500 + i) * 4) = 0;
            *(uint32_t*)(dsm + s * P3_ST + 6400 + (1500 + i) * 4) = 0;
        }
    }

    auto stage_a = [&](int c, int s) {
        const int rgw = (kz * 256 + c * 32) >> 1;
        #pragma unroll
        for (int i = 0; i < 3; i++) {
            int idx = tid + i * 256;
            if (idx < 600) {
                int half = (idx >= 300) ? 1 : 0;
                int j = idx - half * 300;
                int t = j >> 2, c4 = (j & 3) * 4;
                const uint32_t* src = (half ? aLg : aHg) + t * 1024 + rgw + c4;
                cp16(sbase + s * P3_ST + half * 6400 + (t * 20 + c4) * 4, src);
            }
        }
        cp_commit();
    };

    float4 vb[4];
    auto load_b = [&](int c) {
        const int p0 = c * 32;
        #pragma unroll
        for (int it = 0; it < 4; it++) {
            int idx = tid + it * 256;
            int d = idx >> 3, c4 = (idx & 7) * 4;
            vb[it] = *(const float4*)(srcB + (size_t)d * 256 + p0 + c4);
        }
    };
    auto store_b = [&](int s) {
        uint32_t* BH = (uint32_t*)(dsm + s * P3_ST + 12800);
        uint32_t* BL = (uint32_t*)(dsm + s * P3_ST + 23040);
        #pragma unroll
        for (int it = 0; it < 4; it++) {
            int idx = tid + it * 256;
            int d = idx >> 3, c4 = (idx & 7) * 4;
            uint32_t h0, l0, h1, l1;
            bsplit2(vb[it].x, vb[it].y, h0, l0);
            bsplit2(vb[it].z, vb[it].w, h1, l1);
            int w0 = d * 20 + (c4 >> 1);
            BH[w0] = h0; BH[w0 + 1] = h1;
            BL[w0] = l0; BL[w0 + 1] = l1;
        }
    };

    float acc[5][2][4];
    #pragma unroll
    for (int mt = 0; mt < 5; mt++)
        #pragma unroll
        for (int nt = 0; nt < 2; nt++)
            #pragma unroll
            for (int q = 0; q < 4; q++) acc[mt][nt][q] = 0.f;

    // prologue: chunk 0
    stage_a(0, 0);
    load_b(0);
    store_b(0);
    cp_wait0();
    __syncthreads();

    const int n0 = wid * 16;
    const uint32_t aoffb = (uint32_t)((lane & 15) * 80 + (lane >> 4) * 16);
    const uint32_t boff0 = (uint32_t)((n0 + ((lane >> 4) & 1) * 8 + (lane & 7)) * 80
                                      + ((lane >> 3) & 1) * 16);

    for (int c = 0; c < 8; c++) {
        const int s = c & 1;
        if (c < 7) { stage_a(c + 1, s ^ 1); load_b(c + 1); }
        // ---- mma on stage s (interleaved accumulators) -------------------
        {
            const uint32_t pAH = sbase + s * P3_ST;
            const uint32_t pAL = pAH + 6400;
            const uint32_t pBH = pAH + 12800;
            const uint32_t pBL = pAH + 23040;
            #pragma unroll
            for (int ks = 0; ks < 2; ks++) {
                uint32_t bh0, bh1, bh2, bh3, bl0, bl1, bl2, bl3;
                ldm_x4(bh0, bh1, bh2, bh3, pBH + boff0 + ks * 32);
                ldm_x4(bl0, bl1, bl2, bl3, pBL + boff0 + ks * 32);
                #pragma unroll
                for (int mt = 0; mt < 5; mt++) {
                    uint32_t ah0, ah1, ah2, ah3, al0, al1, al2, al3;
                    uint32_t ao = aoffb + (uint32_t)(mt * 16 * 80 + ks * 32);
                    ldm_x4(ah0, ah1, ah2, ah3, pAH + ao);
                    ldm_x4(al0, al1, al2, al3, pAL + ao);
                    mma_bf16(acc[mt][0], ah0, ah1, ah2, ah3, bh0, bh1);
                    mma_bf16(acc[mt][1], ah0, ah1, ah2, ah3, bh2, bh3);
                    mma_bf16(acc[mt][0], ah0, ah1, ah2, ah3, bl0, bl1);
                    mma_bf16(acc[mt][1], ah0, ah1, ah2, ah3, bl2, bl3);
                    mma_bf16(acc[mt][0], al0, al1, al2, al3, bh0, bh1);
                    mma_bf16(acc[mt][1], al0, al1, al2, al3, bh2, bh3);
                }
            }
        }
        if (c < 7) { store_b(s ^ 1); cp_wait0(); }
        __syncthreads();
    }
    // ---- epilogue: scale by cinv[t], write split-K partials -----------------
    float* outp = g_vtp + (size_t)kz * 40 * 75 * 256 + (size_t)b * 75 * 256 + nh * 128;
    #pragma unroll
    for (int mt = 0; mt < 5; mt++) {
        int t = mt * 16 + gid;
        #pragma unroll
        for (int nt = 0; nt < 2; nt++) {
            int d = n0 + nt * 8 + tig * 2;
            if (t < 75) {
                float ci = scv[t];
                float2 v0 = {acc[mt][nt][0] * ci, acc[mt][nt][1] * ci};
                *(float2*)(outp + (size_t)t * 256 + d) = v0;
            }
            if (t + 8 < 75) {
                float ci = scv[t + 8];
                float2 v1 = {acc[mt][nt][2] * ci, acc[mt][nt][3] * ci};
                *(float2*)(outp + (size_t)(t + 8) * 256 + d) = v1;
            }
        }
    }
}

// ============ PHASE 4: tail = logit2 (320) + reg (40) + score1 (375) ========
__global__ void __launch_bounds__(256) k_tail(const float* __restrict__ text) {
    __shared__ __align__(16) float pool[1500];
    const int bx = blockIdx.x;
    const int tid = threadIdx.x;
    const int lane = tid & 31, w = tid >> 5;

    if (bx < 320) {
        const int b = bx >> 3, m = bx & 7, blk = b / 5;
        float* shsd = pool;
        float* wred = pool + 16;
        const float vv = g_vns[((size_t)b * 8 + m) * 256 + tid];
        for (int sb = 0; sb < 5; sb++) {
            if (tid < 15) shsd[tid] = g_sd[((size_t)b * 8 + m) * 75 + sb * 15 + tid];
            __syncthreads();
            float segsum = 0.f;
            #pragma unroll
            for (int l = 0; l < 15; l++) segsum += shsd[l];
            float em = 0.f;
            #pragma unroll
            for (int l = 0; l < 15; l++)
                em = fmaf(shsd[l], text[((size_t)blk * 75 + sb * 15 + l) * 256 + tid], em);
            em /= segsum;
            float p = em * em, q = em * vv;
            #pragma unroll
            for (int o = 16; o > 0; o >>= 1) {
                p += __shfl_xor_sync(0xffffffffu, p, o);
                q += __shfl_xor_sync(0xffffffffu, q, o);
            }
            if (lane == 0) { wred[w] = p; wred[8 + w] = q; }
            __syncthreads();
            if (tid == 0) {
                float s1 = 0.f, s2 = 0.f;
                #pragma unroll
                for (int j = 0; j < 8; j++) { s1 += wred[j]; s2 += wred[8 + j]; }
                g_logit2[((size_t)b * 8 + m) * 5 + sb] =
                    s2 / (fmaxf(sqrtf(s1), 1e-12f) * 256.0f);
            }
            __syncthreads();
        }
    } else if (bx < 360) {
        const int b = bx - 320;
        float* ssd   = pool;
        float* sseg  = pool + 600;
        float* sbeta = pool + 640;
        float* red   = pool + 1240;
        for (int i = tid; i < 600; i += 256) ssd[i] = g_sd[(size_t)b * 600 + i];
        __syncthreads();
        if (tid < 40) {
            int m = tid / 5, sb2 = tid % 5;
            float s = 0.f;
            for (int l = 0; l < 15; l++) s += ssd[m * 75 + sb2 * 15 + l];
            sseg[tid] = s;
        }
        __syncthreads();
        for (int i = tid; i < 600; i += 256) {
            int m = i / 75, t = i % 75;
            sbeta[i] = ssd[i] / sseg[m * 5 + t / 15];
        }
        __syncthreads();
        float p = 0.f;
        if (tid < 64) {
            int m = tid >> 3, n = tid & 7;
            if (m != n) {
                float a = 0.f;
                for (int t = 0; t < 75; t++) a = fmaf(sbeta[m * 75 + t], sbeta[n * 75 + t], a);
                p = a * a;
            }
        }
        red[tid] = p; __syncthreads();
        for (int o = 128; o > 0; o >>= 1) { if (tid < o) red[tid] += red[tid + o]; __syncthreads(); }
        if (tid == 0) g_regval[b] = sqrtf(red[0]);
    } else {
        const int gt = (bx - 360) * 8 + w;
        if (gt < 3000) {
            const int b = gt / 75, t = gt % 75, blk = b / 5;
            const size_t SL = (size_t)40 * 75 * 256;
            const size_t voff = ((size_t)b * 75 + t) * 256;
            const float* e = text + ((size_t)blk * 75 + t) * 256;
            float dot = 0.f, nv = 0.f, ne = 0.f;
            #pragma unroll
            for (int j = 0; j < 8; j++) {
                int d = lane + 32 * j;
                float a = 0.f;
                #pragma unroll
                for (int s8 = 0; s8 < 8; s8++) a += g_vtp[s8 * SL + voff + d];
                float cc = e[d];
                dot = fmaf(a, cc, dot); nv = fmaf(a, a, nv); ne = fmaf(cc, cc, ne);
            }
            #pragma unroll
            for (int o = 16; o > 0; o >>= 1) {
                dot += __shfl_xor_sync(0xffffffffu, dot, o);
                nv  += __shfl_xor_sync(0xffffffffu, nv,  o);
                ne  += __shfl_xor_sync(0xffffffffu, ne,  o);
            }
            if (lane == 0)
                g_el[b * 75 + t] = __expf(dot / (fmaxf(sqrtf(nv), 1e-12f) * fmaxf(sqrtf(ne), 1e-12f)));
        }
    }
}

// ============ PHASE 5: final scalar =========================================
__global__ void k_final(float* __restrict__ out) {
    const int tid = threadIdx.x;
    __shared__ float lsm[200];
    __shared__ float bscore[8];
    if (tid < 200) {
        int blk = tid / 25, rem = tid % 25, i = rem / 5, sb = rem % 5;
        int gi = blk * 5 + i;
        float s2 = 0.f;
        #pragma unroll
        for (int m = 0; m < 8; m++) s2 += __expf(g_logit2[((size_t)gi * 8 + m) * 5 + sb]);
        float s1 = 0.f;
        #pragma unroll
        for (int l = 0; l < 15; l++) s1 += g_el[gi * 75 + sb * 15 + l];
        float l1 = __logf(__powf(s1, 0.2f) + EPSL);
        float l2 = __logf(__powf(s2, 0.2f) + EPSL);
        lsm[tid] = 10.0f * (l1 + l2);
    }
    __syncthreads();
    if (tid < 8) {
        const float* L = lsm + tid * 25;
        float rows[5] = {0, 0, 0, 0, 0}, cols[5] = {0, 0, 0, 0, 0};
        for (int i = 0; i < 5; i++)
            for (int sb = 0; sb < 5; sb++) {
                rows[i] += L[i * 5 + sb];
                cols[sb] += L[i * 5 + sb];
            }
        float acc = 0.f;
        for (int i = 0; i < 5; i++) {
            float dg = L[i * 5 + i];
            acc += -__logf(dg / rows[i] + EPSL) - __logf(dg / cols[i] + EPSL);
        }
        float reg = 0.f;
        for (int i = 0; i < 5; i++) reg += g_regval[tid * 5 + i];
        bscore[tid] = acc / 5.0f + reg / 5.0f;
    }
    __syncthreads();
    if (tid == 0) {
        float tot = 0.f;
        for (int k = 0; k < 8; k++) tot += bscore[k];
        out[0] = tot / 9.0f;
    }
}

// ---------------- launch -----------------------------------------------------
extern "C" void kernel_launch(void* const* d_in, const int* in_sizes, int n_in,
                              void* d_out, int out_size) {
    (void)in_sizes; (void)n_in; (void)out_size;
    const float* image = (const float*)d_in[0];
    const float* text  = (const float*)d_in[1];
    float* out = (float*)d_out;

    cudaFuncSetAttribute(k_phase1, cudaFuncAttributeMaxDynamicSharedMemorySize, P1_SZ);
    cudaFuncSetAttribute(k_vtidal, cudaFuncAttributeMaxDynamicSharedMemorySize, P3_SZ);

    k_prep<<<300, 256>>>(text);
    k_phase1<<<960, 256, P1_SZ>>>(image, text);
    k_colstats<<<dim3(75, 40), 256>>>();
    k_vtidal<<<640, 256, P3_SZ>>>(image);
    k_tail<<<735, 256>>>(text);
    k_final<<<1, 256>>>(out);
}

// round 11
// speedup vs baseline: 3.2411x; 1.1284x over previous
#include <cuda_runtime.h>
#include <cuda_bf16.h>
#include <math.h>
#include <stdint.h>

#define G1 4.0f
#define EPSL 1e-10f

// ---------------- scratch (device globals) ----------------------------------
__device__ float    g_sT[40u*75u*2048u];      // [b][t][r]: s scores
__device__ float    g_rsmax[40u*5u*2048u];    // [b][seg][r] row max
__device__ float    g_rsinv[40u*5u*2048u];    // [b][seg][r] 1/sumexp
__device__ float    g_cinv_nt[40*75];
__device__ float    g_sd[40*8*75];
__device__ uint32_t g_aH[40u*75u*1024u];      // alpha numerators, bf16-hi pairs
__device__ uint32_t g_aL[40u*75u*1024u];      // alpha numerators, bf16-lo pairs
__device__ uint32_t g_eh[8*75*128];           // text bf16-hi pairs
__device__ uint32_t g_el2[8*75*128];          // text bf16-lo pairs
__device__ float    g_vtp[8u*40u*75u*256u];   // split-K partials of v_tidal
__device__ float    g_vns[40*8*256];
__device__ float    g_el[40*75];
__device__ float    g_logit2[40*8*5];
__device__ float    g_regval[40];

// ---------------- helpers ----------------------------------------------------
__device__ __forceinline__ uint32_t s2u(const void* p) {
    uint32_t a;
    asm("{ .reg .u64 t; cvta.to.shared.u64 t, %1; cvt.u32.u64 %0, t; }" : "=r"(a) : "l"(p));
    return a;
}
__device__ __forceinline__ void cp16(uint32_t dst, const void* src) {
    asm volatile("cp.async.cg.shared.global [%0], [%1], 16;" :: "r"(dst), "l"(src));
}
__device__ __forceinline__ void cp_commit() { asm volatile("cp.async.commit_group;" ::: "memory"); }
__device__ __forceinline__ void cp_wait0()  { asm volatile("cp.async.wait_group 0;" ::: "memory"); }

__device__ __forceinline__ void ldm_x4(uint32_t& r0, uint32_t& r1, uint32_t& r2,
                                       uint32_t& r3, uint32_t addr) {
    asm volatile("ldmatrix.sync.aligned.m8n8.x4.shared.b16 {%0,%1,%2,%3}, [%4];"
                 : "=r"(r0), "=r"(r1), "=r"(r2), "=r"(r3) : "r"(addr));
}
__device__ __forceinline__ void ldm_x4_t(uint32_t& r0, uint32_t& r1, uint32_t& r2,
                                         uint32_t& r3, uint32_t addr) {
    asm volatile("ldmatrix.sync.aligned.m8n8.x4.trans.shared.b16 {%0,%1,%2,%3}, [%4];"
                 : "=r"(r0), "=r"(r1), "=r"(r2), "=r"(r3) : "r"(addr));
}
__device__ __forceinline__ void mma_bf16(float* c, uint32_t a0, uint32_t a1,
                                         uint32_t a2, uint32_t a3,
                                         uint32_t b0, uint32_t b1) {
    asm volatile(
        "mma.sync.aligned.m16n8k16.row.col.f32.bf16.bf16.f32 "
        "{%0,%1,%2,%3}, {%4,%5,%6,%7}, {%8,%9}, {%0,%1,%2,%3};"
        : "+f"(c[0]), "+f"(c[1]), "+f"(c[2]), "+f"(c[3])
        : "r"(a0), "r"(a1), "r"(a2), "r"(a3), "r"(b0), "r"(b1));
}
// fast split: x,y -> packed bf16 hi + packed bf16 lo residual
__device__ __forceinline__ void bsplit2(float x, float y, uint32_t& hi, uint32_t& lo) {
    uint32_t h;
    asm("cvt.rn.bf16x2.f32 %0, %1, %2;" : "=r"(h) : "f"(y), "f"(x));
    float hx = __uint_as_float(h << 16);
    float hy = __uint_as_float(h & 0xFFFF0000u);
    float lx = x - hx, ly = y - hy;
    asm("cvt.rn.bf16x2.f32 %0, %1, %2;" : "=r"(lo) : "f"(ly), "f"(lx));
    hi = h;
}

// phase1 per-stage 30208 B: AH[32 k][272 B] @0 | AL @8704 | BH[80][20w] @17408 | BL @23808
#define P1_ST  30208
#define P1_SZ  60416
// vtidal: per-stage 33280 B: AH[80][20] @0 | AL @6400 | BH[128][20] @12800 | BL @23040
#define P3_ST  33280
#define P3_SZ  66560

// ============ PHASE 0: convert text to bf16 hi/lo pairs =====================
__global__ void __launch_bounds__(256) k_prep(const float* __restrict__ text) {
    int i = blockIdx.x * 256 + threadIdx.x;   // 76800 pairs
    float2 v = *(const float2*)(text + 2 * i);
    uint32_t h, l;
    bsplit2(v.x, v.y, h, l);
    g_eh[i] = h; g_el2[i] = l;
}

// ============ PHASE 1: pipelined mma gemm_s (640 blks) ======================
__global__ void __launch_bounds__(256) k_phase1(const float* __restrict__ image,
                                                const float* __restrict__ text) {
    extern __shared__ __align__(16) char dsm[];
    const int bx = blockIdx.x;
    const int tid = threadIdx.x;
    const int wid = tid >> 5, lane = tid & 31;

    const int b  = bx >> 4;
    const int rb = bx & 15;
    const int r0 = rb * 128;
    const int m  = rb >> 1, p0 = (rb & 1) * 128;
    const float* srcA = image + (size_t)(b * 8 + m) * 65536;
    const uint32_t* eH = g_eh  + (size_t)(b / 5) * 9600;
    const uint32_t* eL = g_el2 + (size_t)(b / 5) * 9600;
    const uint32_t sbase = s2u(dsm);
    const int gid = lane >> 2, tig = lane & 3;

    // zero B pad rows 75..79 in both stages
    for (int i = tid; i < 100; i += 256) {
        #pragma unroll
        for (int s = 0; s < 2; s++) {
            *(uint32_t*)(dsm + s * P1_ST + 17408 + (1500 + i) * 4) = 0;
            *(uint32_t*)(dsm + s * P1_ST + 23808 + (1500 + i) * 4) = 0;
        }
    }

    float4 iv[4];
    auto load_a = [&](int c) {
        const int kb = c * 32;
        #pragma unroll
        for (int it = 0; it < 4; it++) {
            int lin = tid + it * 256;
            int k = lin >> 5, f4 = (lin & 31) * 4;
            iv[it] = *(const float4*)(srcA + (size_t)(kb + k) * 256 + p0 + f4);
        }
    };
    // convert in regs, store bf16 hi/lo to [k][p] tile (272 B rows)
    auto store_a = [&](int s) {
        char* AH = dsm + s * P1_ST;
        char* AL = AH + 8704;
        #pragma unroll
        for (int it = 0; it < 4; it++) {
            int lin = tid + it * 256;
            int k = lin >> 5, p4 = (lin & 31) * 4;
            uint32_t h0, l0, h1, l1;
            bsplit2(iv[it].x, iv[it].y, h0, l0);
            bsplit2(iv[it].z, iv[it].w, h1, l1);
            int off = k * 272 + p4 * 2;
            *(uint2*)(AH + off) = make_uint2(h0, h1);
            *(uint2*)(AL + off) = make_uint2(l0, l1);
        }
    };
    auto stage_b = [&](int c, int s) {
        const int kw = c * 16;
        #pragma unroll
        for (int i = 0; i < 3; i++) {
            int idx = tid + i * 256;
            if (idx < 600) {
                int half = (idx >= 300) ? 1 : 0;
                int j = idx - half * 300;
                int t = j >> 2, c4 = (j & 3) * 4;
                const uint32_t* src = (half ? eL : eH) + t * 128 + kw + c4;
                cp16(sbase + s * P1_ST + 17408 + half * 6400 + (t * 20 + c4) * 4, src);
            }
        }
        cp_commit();
    };

    float acc[10][4];
    #pragma unroll
    for (int nt = 0; nt < 10; nt++)
        #pragma unroll
        for (int q = 0; q < 4; q++) acc[nt][q] = 0.f;

    // ldmatrix.trans A base: lanes -> k-rows, matrices -> (m-half, k-half)
    const uint32_t aoffT = (uint32_t)(((lane & 7) + ((lane >> 4) & 1) * 8) * 272
                                      + ((lane >> 3) & 1) * 16 + wid * 32);
    const uint32_t boff0 = (uint32_t)((((lane >> 4) & 1) * 8 + (lane & 7)) * 80
                                      + ((lane >> 3) & 1) * 16);

    // prologue: chunk 0
    load_a(0);
    stage_b(0, 0);
    store_a(0);
    cp_wait0();
    __syncthreads();

    for (int c = 0; c < 8; c++) {
        const int s = c & 1;
        if (c < 7) { load_a(c + 1); stage_b(c + 1, s ^ 1); }
        // ---- mma on stage s ------------------------------------------
        {
            const uint32_t pAH = sbase + s * P1_ST;
            const uint32_t pAL = pAH + 8704;
            const uint32_t pBH = pAH + 17408;
            const uint32_t pBL = pAH + 23808;
            #pragma unroll
            for (int ks = 0; ks < 2; ks++) {
                uint32_t ah0, ah1, ah2, ah3, al0, al1, al2, al3;
                ldm_x4_t(ah0, ah1, ah2, ah3, pAH + aoffT + ks * 4352);
                ldm_x4_t(al0, al1, al2, al3, pAL + aoffT + ks * 4352);
                #pragma unroll
                for (int j = 0; j < 5; j++) {
                    uint32_t bh0, bh1, bh2, bh3, bl0, bl1, bl2, bl3;
                    uint32_t bo = boff0 + (uint32_t)(j * 16 * 80 + ks * 32);
                    ldm_x4(bh0, bh1, bh2, bh3, pBH + bo);
                    ldm_x4(bl0, bl1, bl2, bl3, pBL + bo);
                    mma_bf16(acc[2 * j],     ah0, ah1, ah2, ah3, bh0, bh1);
                    mma_bf16(acc[2 * j + 1], ah0, ah1, ah2, ah3, bh2, bh3);
                    mma_bf16(acc[2 * j],     ah0, ah1, ah2, ah3, bl0, bl1);
                    mma_bf16(acc[2 * j + 1], ah0, ah1, ah2, ah3, bl2, bl3);
                    mma_bf16(acc[2 * j],     al0, al1, al2, al3, bh0, bh1);
                    mma_bf16(acc[2 * j + 1], al0, al1, al2, al3, bh2, bh3);
                }
            }
        }
        if (c < 7) { store_a(s ^ 1); cp_wait0(); }
        __syncthreads();
    }
    // ---- epilogue: stage C to sc[t][132 r] --------------------------
    float* sc = (float*)dsm;
    const int rA = wid * 16 + gid;
    #pragma unroll
    for (int nt = 0; nt < 10; nt++) {
        int t0 = nt * 8 + tig * 2;
        sc[t0 * 132 + rA]           = acc[nt][0];
        sc[(t0 + 1) * 132 + rA]     = acc[nt][1];
        sc[t0 * 132 + rA + 8]       = acc[nt][2];
        sc[(t0 + 1) * 132 + rA + 8] = acc[nt][3];
    }
    __syncthreads();
    if (tid < 128) {
        const int r = tid;
        #pragma unroll
        for (int seg = 0; seg < 5; seg++) {
            float mx = -3.4e38f;
            #pragma unroll
            for (int l = 0; l < 15; l++)
                mx = fmaxf(mx, sc[(seg * 15 + l) * 132 + r]);
            float se = 0.f;
            #pragma unroll
            for (int l = 0; l < 15; l++)
                se += __expf(sc[(seg * 15 + l) * 132 + r] - mx);
            size_t off = ((size_t)b * 5 + seg) * 2048 + r0 + r;
            g_rsmax[off] = mx;
            g_rsinv[off] = 1.0f / se;
        }
    }
    for (int i = tid; i < 9600; i += 256) {
        int t = i >> 7, r = i & 127;
        g_sT[((size_t)b * 75 + t) * 2048 + r0 + r] = sc[t * 132 + r];
    }
}

// ============ PHASE 2: column stats + sd + packed bf16 alpha =================
__global__ void __launch_bounds__(256) k_colstats() {
    const int t = blockIdx.x, b = blockIdx.y, seg = t / 15;
    const int tid = threadIdx.x, lane = tid & 31, w = tid >> 5;
    const float* col = g_sT + ((size_t)b * 75 + t) * 2048;
    __shared__ float sred[24];

    float vals[8];
    *(float4*)vals       = *(const float4*)(col + tid * 8);
    *(float4*)(vals + 4) = *(const float4*)(col + tid * 8 + 4);

    float mx = vals[0];
    #pragma unroll
    for (int k = 1; k < 8; k++) mx = fmaxf(mx, vals[k]);
    #pragma unroll
    for (int o = 16; o > 0; o >>= 1) mx = fmaxf(mx, __shfl_xor_sync(0xffffffffu, mx, o));
    if (lane == 0) sred[w] = mx;
    __syncthreads();
    float cmax = sred[0];
    #pragma unroll
    for (int q = 1; q < 8; q++) cmax = fmaxf(cmax, sred[q]);

    // SoA rowstats: vectorized loads
    float mxv[8], inv[8];
    {
        const size_t off = ((size_t)b * 5 + seg) * 2048 + tid * 8;
        *(float4*)mxv       = *(const float4*)(g_rsmax + off);
        *(float4*)(mxv + 4) = *(const float4*)(g_rsmax + off + 4);
        *(float4*)inv       = *(const float4*)(g_rsinv + off);
        *(float4*)(inv + 4) = *(const float4*)(g_rsinv + off + 4);
    }

    float e1[8], al[8];
    float sraw = 0.f, snt = 0.f;
    #pragma unroll
    for (int k = 0; k < 8; k++) {
        e1[k] = __expf(vals[k] - cmax);
        sraw += e1[k];
        al[k] = __expf(G1 * __expf(vals[k] - mxv[k]) * inv[k]);
        snt += al[k];
    }
    {
        uint32_t* aH = g_aH + (size_t)b * 76800 + t * 1024 + tid * 4;
        uint32_t* aL = g_aL + (size_t)b * 76800 + t * 1024 + tid * 4;
        #pragma unroll
        for (int j = 0; j < 4; j++) {
            uint32_t h, l;
            bsplit2(al[2 * j], al[2 * j + 1], h, l);
            aH[j] = h; aL[j] = l;
        }
    }
    float sr = sraw, sn = snt;
    #pragma unroll
    for (int o = 16; o > 0; o >>= 1) {
        sr += __shfl_xor_sync(0xffffffffu, sr, o);
        sn += __shfl_xor_sync(0xffffffffu, sn, o);
    }
    if (lane == 0) { sred[8 + w] = sr; sred[16 + w] = sn; }
    __syncthreads();
    float tot = 0.f;
    #pragma unroll
    for (int q = 0; q < 8; q++) tot += sred[8 + q];
    const float cinv = 1.0f / tot;
    if (tid == 0) {
        float s = 0.f;
        #pragma unroll
        for (int q = 0; q < 8; q++) s += sred[16 + q];
        g_cinv_nt[b * 75 + t] = 1.0f / s;
    }
    float e2 = 0.f;
    #pragma unroll
    for (int k = 0; k < 8; k++) e2 += __expf(e1[k] * cinv);
    #pragma unroll
    for (int o = 16; o > 0; o >>= 1) e2 += __shfl_xor_sync(0xffffffffu, e2, o);
    if (lane == 0) g_sd[((size_t)b * 8 + w) * 75 + t] = e2;
}

// ============ PHASE 3: mma v_tidal (640) + vns (320) =========================
__global__ void __launch_bounds__(256) k_vtidal(const float* __restrict__ image) {
    extern __shared__ __align__(16) char dsm[];
    __shared__ float scv[80];
    const int bx = blockIdx.x;
    const int tid = threadIdx.x;
    const int wid = tid >> 5, lane = tid & 31;

    if (bx >= 640) {
        // -------- vns from image directly (overlaps tensor-bound vtidal) -----
        const int bm = bx - 640;
        const float* src = image + (size_t)bm * 65536;
        float* invn = (float*)dsm;
        float s0 = 0.f, s1 = 0.f, s2 = 0.f, s3 = 0.f;
        for (int d = 0; d < 256; d += 4) {
            float x0 = src[(size_t)(d + 0) * 256 + tid];
            float x1 = src[(size_t)(d + 1) * 256 + tid];
            float x2 = src[(size_t)(d + 2) * 256 + tid];
            float x3 = src[(size_t)(d + 3) * 256 + tid];
            s0 = fmaf(x0, x0, s0); s1 = fmaf(x1, x1, s1);
            s2 = fmaf(x2, x2, s2); s3 = fmaf(x3, x3, s3);
        }
        invn[tid] = 1.0f / fmaxf(sqrtf((s0 + s1) + (s2 + s3)), 1e-12f);
        __syncthreads();
        for (int j = 0; j < 32; j++) {
            int d = wid * 32 + j;
            const float* row = src + (size_t)d * 256;
            float a = 0.f;
            #pragma unroll
            for (int q = 0; q < 8; q++) {
                int p = lane + 32 * q;
                a = fmaf(row[p], invn[p], a);
            }
            #pragma unroll
            for (int o = 16; o > 0; o >>= 1) a += __shfl_xor_sync(0xffffffffu, a, o);
            if (lane == 0) g_vns[(size_t)bm * 256 + d] = a;
        }
        return;
    }

    const int b  = bx >> 4;
    const int kz = (bx >> 1) & 7;
    const int nh = bx & 1;
    const int gid = lane >> 2, tig = lane & 3;
    const uint32_t sbase = s2u(dsm);
    const uint32_t* aHg = g_aH + (size_t)b * 76800;
    const uint32_t* aLg = g_aL + (size_t)b * 76800;
    const float* srcB = image + (size_t)(b * 8 + kz) * 65536 + (size_t)(nh * 128) * 256;

    if (tid < 75) scv[tid] = g_cinv_nt[b * 75 + tid];
    // zero A pad rows 75..79 in both stages
    for (int i = tid; i < 100; i += 256) {
        #pragma unroll
        for (int s = 0; s < 2; s++) {
            *(uint32_t*)(dsm + s * P3_ST +        (1500 + i) * 4) = 0;
            *(uint32_t*)(dsm + s * P3_ST + 6400 + (1500 + i) * 4) = 0;
        }
    }

    auto stage_a = [&](int c, int s) {
        const int rgw = (kz * 256 + c * 32) >> 1;
        #pragma unroll
        for (int i = 0; i < 3; i++) {
            int idx = tid + i * 256;
            if (idx < 600) {
                int half = (idx >= 300) ? 1 : 0;
                int j = idx - half * 300;
                int t = j >> 2, c4 = (j & 3) * 4;
                const uint32_t* src = (half ? aLg : aHg) + t * 1024 + rgw + c4;
                cp16(sbase + s * P3_ST + half * 6400 + (t * 20 + c4) * 4, src);
            }
        }
        cp_commit();
    };

    float4 vb[4];
    auto load_b = [&](int c) {
        const int p0 = c * 32;
        #pragma unroll
        for (int it = 0; it < 4; it++) {
            int idx = tid + it * 256;
            int d = idx >> 3, c4 = (idx & 7) * 4;
            vb[it] = *(const float4*)(srcB + (size_t)d * 256 + p0 + c4);
        }
    };
    auto store_b = [&](int s) {
        uint32_t* BH = (uint32_t*)(dsm + s * P3_ST + 12800);
        uint32_t* BL = (uint32_t*)(dsm + s * P3_ST + 23040);
        #pragma unroll
        for (int it = 0; it < 4; it++) {
            int idx = tid + it * 256;
            int d = idx >> 3, c4 = (idx & 7) * 4;
            uint32_t h0, l0, h1, l1;
            bsplit2(vb[it].x, vb[it].y, h0, l0);
            bsplit2(vb[it].z, vb[it].w, h1, l1);
            int w0 = d * 20 + (c4 >> 1);
            BH[w0] = h0; BH[w0 + 1] = h1;
            BL[w0] = l0; BL[w0 + 1] = l1;
        }
    };

    float acc[5][2][4];
    #pragma unroll
    for (int mt = 0; mt < 5; mt++)
        #pragma unroll
        for (int nt = 0; nt < 2; nt++)
            #pragma unroll
            for (int q = 0; q < 4; q++) acc[mt][nt][q] = 0.f;

    // prologue: chunk 0
    stage_a(0, 0);
    load_b(0);
    store_b(0);
    cp_wait0();
    __syncthreads();

    const int n0 = wid * 16;
    const uint32_t aoffb = (uint32_t)((lane & 15) * 80 + (lane >> 4) * 16);
    const uint32_t boff0 = (uint32_t)((n0 + ((lane >> 4) & 1) * 8 + (lane & 7)) * 80
                                      + ((lane >> 3) & 1) * 16);

    for (int c = 0; c < 8; c++) {
        const int s = c & 1;
        if (c < 7) { stage_a(c + 1, s ^ 1); load_b(c + 1); }
        // ---- mma on stage s (interleaved accumulators) -------------------
        {
            const uint32_t pAH = sbase + s * P3_ST;
            const uint32_t pAL = pAH + 6400;
            const uint32_t pBH = pAH + 12800;
            const uint32_t pBL = pAH + 23040;
            #pragma unroll
            for (int ks = 0; ks < 2; ks++) {
                uint32_t bh0, bh1, bh2, bh3, bl0, bl1, bl2, bl3;
                ldm_x4(bh0, bh1, bh2, bh3, pBH + boff0 + ks * 32);
                ldm_x4(bl0, bl1, bl2, bl3, pBL + boff0 + ks * 32);
                #pragma unroll
                for (int mt = 0; mt < 5; mt++) {
                    uint32_t ah0, ah1, ah2, ah3, al0, al1, al2, al3;
                    uint32_t ao = aoffb + (uint32_t)(mt * 16 * 80 + ks * 32);
                    ldm_x4(ah0, ah1, ah2, ah3, pAH + ao);
                    ldm_x4(al0, al1, al2, al3, pAL + ao);
                    mma_bf16(acc[mt][0], ah0, ah1, ah2, ah3, bh0, bh1);
                    mma_bf16(acc[mt][1], ah0, ah1, ah2, ah3, bh2, bh3);
                    mma_bf16(acc[mt][0], ah0, ah1, ah2, ah3, bl0, bl1);
                    mma_bf16(acc[mt][1], ah0, ah1, ah2, ah3, bl2, bl3);
                    mma_bf16(acc[mt][0], al0, al1, al2, al3, bh0, bh1);
                    mma_bf16(acc[mt][1], al0, al1, al2, al3, bh2, bh3);
                }
            }
        }
        if (c < 7) { store_b(s ^ 1); cp_wait0(); }
        __syncthreads();
    }
    // ---- epilogue: scale by cinv[t], write split-K partials -----------------
    float* outp = g_vtp + (size_t)kz * 40 * 75 * 256 + (size_t)b * 75 * 256 + nh * 128;
    #pragma unroll
    for (int mt = 0; mt < 5; mt++) {
        int t = mt * 16 + gid;
        #pragma unroll
        for (int nt = 0; nt < 2; nt++) {
            int d = n0 + nt * 8 + tig * 2;
            if (t < 75) {
                float ci = scv[t];
                float2 v0 = {acc[mt][nt][0] * ci, acc[mt][nt][1] * ci};
                *(float2*)(outp + (size_t)t * 256 + d) = v0;
            }
            if (t + 8 < 75) {
                float ci = scv[t + 8];
                float2 v1 = {acc[mt][nt][2] * ci, acc[mt][nt][3] * ci};
                *(float2*)(outp + (size_t)(t + 8) * 256 + d) = v1;
            }
        }
    }
}

// ============ PHASE 4: tail = logit2 (320) + reg (40) + score1 (375) ========
__global__ void __launch_bounds__(256) k_tail(const float* __restrict__ text) {
    __shared__ __align__(16) float pool[1500];
    const int bx = blockIdx.x;
    const int tid = threadIdx.x;
    const int lane = tid & 31, w = tid >> 5;

    if (bx < 320) {
        const int b = bx >> 3, m = bx & 7, blk = b / 5;
        float* shsd = pool;
        float* wred = pool + 16;
        const float vv = g_vns[((size_t)b * 8 + m) * 256 + tid];
        for (int sb = 0; sb < 5; sb++) {
            if (tid < 15) shsd[tid] = g_sd[((size_t)b * 8 + m) * 75 + sb * 15 + tid];
            __syncthreads();
            float segsum = 0.f;
            #pragma unroll
            for (int l = 0; l < 15; l++) segsum += shsd[l];
            float em = 0.f;
            #pragma unroll
            for (int l = 0; l < 15; l++)
                em = fmaf(shsd[l], text[((size_t)blk * 75 + sb * 15 + l) * 256 + tid], em);
            em /= segsum;
            float p = em * em, q = em * vv;
            #pragma unroll
            for (int o = 16; o > 0; o >>= 1) {
                p += __shfl_xor_sync(0xffffffffu, p, o);
                q += __shfl_xor_sync(0xffffffffu, q, o);
            }
            if (lane == 0) { wred[w] = p; wred[8 + w] = q; }
            __syncthreads();
            if (tid == 0) {
                float s1 = 0.f, s2 = 0.f;
                #pragma unroll
                for (int j = 0; j < 8; j++) { s1 += wred[j]; s2 += wred[8 + j]; }
                g_logit2[((size_t)b * 8 + m) * 5 + sb] =
                    s2 / (fmaxf(sqrtf(s1), 1e-12f) * 256.0f);
            }
            __syncthreads();
        }
    } else if (bx < 360) {
        const int b = bx - 320;
        float* ssd   = pool;
        float* sseg  = pool + 600;
        float* sbeta = pool + 640;
        float* red   = pool + 1240;
        for (int i = tid; i < 600; i += 256) ssd[i] = g_sd[(size_t)b * 600 + i];
        __syncthreads();
        if (tid < 40) {
            int m = tid / 5, sb2 = tid % 5;
            float s = 0.f;
            for (int l = 0; l < 15; l++) s += ssd[m * 75 + sb2 * 15 + l];
            sseg[tid] = s;
        }
        __syncthreads();
        for (int i = tid; i < 600; i += 256) {
            int m = i / 75, t = i % 75;
            sbeta[i] = ssd[i] / sseg[m * 5 + t / 15];
        }
        __syncthreads();
        float p = 0.f;
        if (tid < 64) {
            int m = tid >> 3, n = tid & 7;
            if (m != n) {
                float a = 0.f;
                for (int t = 0; t < 75; t++) a = fmaf(sbeta[m * 75 + t], sbeta[n * 75 + t], a);
                p = a * a;
            }
        }
        red[tid] = p; __syncthreads();
        for (int o = 128; o > 0; o >>= 1) { if (tid < o) red[tid] += red[tid + o]; __syncthreads(); }
        if (tid == 0) g_regval[b] = sqrtf(red[0]);
    } else {
        const int gt = (bx - 360) * 8 + w;
        if (gt < 3000) {
            const int b = gt / 75, t = gt % 75, blk = b / 5;
            const size_t SL = (size_t)40 * 75 * 256;
            const size_t voff = ((size_t)b * 75 + t) * 256;
            const float* e = text + ((size_t)blk * 75 + t) * 256;
            float dot = 0.f, nv = 0.f, ne = 0.f;
            #pragma unroll
            for (int j = 0; j < 8; j++) {
                int d = lane + 32 * j;
                float a = 0.f;
                #pragma unroll
                for (int s8 = 0; s8 < 8; s8++) a += g_vtp[s8 * SL + voff + d];
                float cc = e[d];
                dot = fmaf(a, cc, dot); nv = fmaf(a, a, nv); ne = fmaf(cc, cc, ne);
            }
            #pragma unroll
            for (int o = 16; o > 0; o >>= 1) {
                dot += __shfl_xor_sync(0xffffffffu, dot, o);
                nv  += __shfl_xor_sync(0xffffffffu, nv,  o);
                ne  += __shfl_xor_sync(0xffffffffu, ne,  o);
            }
            if (lane == 0)
                g_el[b * 75 + t] = __expf(dot / (fmaxf(sqrtf(nv), 1e-12f) * fmaxf(sqrtf(ne), 1e-12f)));
        }
    }
}

// ============ PHASE 5: final scalar =========================================
__global__ void k_final(float* __restrict__ out) {
    const int tid = threadIdx.x;
    __shared__ float lsm[200];
    __shared__ float bscore[8];
    if (tid < 200) {
        int blk = tid / 25, rem = tid % 25, i = rem / 5, sb = rem % 5;
        int gi = blk * 5 + i;
        float s2 = 0.f;
        #pragma unroll
        for (int m = 0; m < 8; m++) s2 += __expf(g_logit2[((size_t)gi * 8 + m) * 5 + sb]);
        float s1 = 0.f;
        #pragma unroll
        for (int l = 0; l < 15; l++) s1 += g_el[gi * 75 + sb * 15 + l];
        float l1 = __logf(__powf(s1, 0.2f) + EPSL);
        float l2 = __logf(__powf(s2, 0.2f) + EPSL);
        lsm[tid] = 10.0f * (l1 + l2);
    }
    __syncthreads();
    if (tid < 8) {
        const float* L = lsm + tid * 25;
        float rows[5] = {0, 0, 0, 0, 0}, cols[5] = {0, 0, 0, 0, 0};
        for (int i = 0; i < 5; i++)
            for (int sb = 0; sb < 5; sb++) {
                rows[i] += L[i * 5 + sb];
                cols[sb] += L[i * 5 + sb];
            }
        float acc = 0.f;
        for (int i = 0; i < 5; i++) {
            float dg = L[i * 5 + i];
            acc += -__logf(dg / rows[i] + EPSL) - __logf(dg / cols[i] + EPSL);
        }
        float reg = 0.f;
        for (int i = 0; i < 5; i++) reg += g_regval[tid * 5 + i];
        bscore[tid] = acc / 5.0f + reg / 5.0f;
    }
    __syncthreads();
    if (tid == 0) {
        float tot = 0.f;
        for (int k = 0; k < 8; k++) tot += bscore[k];
        out[0] = tot / 9.0f;
    }
}

// ---------------- launch -----------------------------------------------------
extern "C" void kernel_launch(void* const* d_in, const int* in_sizes, int n_in,
                              void* d_out, int out_size) {
    (void)in_sizes; (void)n_in; (void)out_size;
    const float* image = (const float*)d_in[0];
    const float* text  = (const float*)d_in[1];
    float* out = (float*)d_out;

    cudaFuncSetAttribute(k_phase1, cudaFuncAttributeMaxDynamicSharedMemorySize, P1_SZ);
    cudaFuncSetAttribute(k_vtidal, cudaFuncAttributeMaxDynamicSharedMemorySize, P3_SZ);

    k_prep<<<300, 256>>>(text);
    k_phase1<<<640, 256, P1_SZ>>>(image, text);
    k_colstats<<<dim3(75, 40), 256>>>();
    k_vtidal<<<960, 256, P3_SZ>>>(image);
    k_tail<<<735, 256>>>(text);
    k_final<<<1, 256>>>(out);
}